// round 1
// baseline (speedup 1.0000x reference)
#include <cuda_runtime.h>
#include <cstdint>
#include <cstddef>

#define BB 4
#define CC 32
#define DD 64
#define HH 128
#define WW 256
#define HW_ (HH*WW)          // 32768
#define BDHW_ (BB*DD*HW_)    // 8388608
#define BCHW_ (BB*CC*HW_)    // 4194304

// ---------------- scratch (static device globals; no allocation) ----------------
__device__ float g_conv[BDHW_];
__device__ float g_xA[BDHW_];
__device__ float g_xB[BDHW_];
__device__ float g_vt[BDHW_];        // v in [b][h][w][d] layout
__device__ float g_oht[BDHW_];       // oH in [b][h][w][d] layout
__device__ float g_qt[BCHW_];        // q in [b][h][w][c]
__device__ float g_kt[BCHW_];        // k in [b][h][w][c]
__device__ float g_aH[BB*HH*WW*HH];  // 16777216
__device__ float g_aW[BB*HH*WW*WW];  // 33554432
__device__ float2 g_part[64*8];
__device__ float2 g_stats[64];

// ---------------- conv 3x3 SAME, 64->64 ----------------
// grid (H/8, B*(D/8)) block (32,8); each thread: 8 dout x 8 w-reps (full W row tile)
__global__ void conv3x3_kernel(const float* __restrict__ x, const float* __restrict__ wt,
                               float* __restrict__ y) {
    const int h0 = blockIdx.x * 8;
    const int bz = blockIdx.y;
    const int b  = bz >> 3;
    const int d0 = (bz & 7) * 8;
    const int tx = threadIdx.x, ty = threadIdx.y;
    const int tid = ty * 32 + tx;

    __shared__ float s_in[10][WW + 2];
    __shared__ float s_w[8][9];

    float acc[8][8];
#pragma unroll
    for (int i = 0; i < 8; ++i)
#pragma unroll
        for (int j = 0; j < 8; ++j) acc[i][j] = 0.f;

    for (int c = 0; c < 64; ++c) {
        const float* xp = x + ((size_t)(b * 64 + c)) * HW_;
        for (int i = tid; i < 10 * (WW + 2); i += 256) {
            int ih = i / (WW + 2), iw = i % (WW + 2);
            int gh = h0 + ih - 1, gw = iw - 1;
            float v = 0.f;
            if (gh >= 0 && gh < HH && gw >= 0 && gw < WW) v = xp[gh * WW + gw];
            s_in[ih][iw] = v;
        }
        if (tid < 72) {
            int dd = tid / 9, t = tid % 9;
            s_w[dd][t] = wt[((size_t)(d0 + dd) * 64 + c) * 9 + t];
        }
        __syncthreads();
#pragma unroll
        for (int t = 0; t < 9; ++t) {
            const int dh = t / 3, dw = t % 3;
            float in8[8], w8[8];
#pragma unroll
            for (int k = 0; k < 8; ++k) in8[k] = s_in[ty + dh][tx + k * 32 + dw];
#pragma unroll
            for (int dd = 0; dd < 8; ++dd) w8[dd] = s_w[dd][t];
#pragma unroll
            for (int dd = 0; dd < 8; ++dd)
#pragma unroll
                for (int k = 0; k < 8; ++k) acc[dd][k] += w8[dd] * in8[k];
        }
        __syncthreads();
    }
    const int h = h0 + ty;
#pragma unroll
    for (int dd = 0; dd < 8; ++dd) {
        float* yp = y + ((size_t)(b * 64 + d0 + dd)) * HW_ + h * WW + tx;
#pragma unroll
        for (int k = 0; k < 8; ++k) yp[k * 32] = acc[dd][k];
    }
}

// ---------------- batchnorm: partial reduce / finalize / apply ----------------
__global__ void bn_reduce_kernel(const float* __restrict__ x, float2* __restrict__ part) {
    const int c = blockIdx.x, p = blockIdx.y;
    float s = 0.f, s2 = 0.f;
    const int base = p * 16384;
    for (int j = threadIdx.x; j < 16384; j += 256) {
        const int f = base + j;
        const int b = f >> 15;
        const int i = f & 32767;
        const float v = x[((size_t)(b * 64 + c)) * HW_ + i];
        s += v; s2 += v * v;
    }
    __shared__ float rs[8], rs2[8];
#pragma unroll
    for (int o = 16; o; o >>= 1) {
        s  += __shfl_xor_sync(0xffffffffu, s, o);
        s2 += __shfl_xor_sync(0xffffffffu, s2, o);
    }
    if ((threadIdx.x & 31) == 0) { rs[threadIdx.x >> 5] = s; rs2[threadIdx.x >> 5] = s2; }
    __syncthreads();
    if (threadIdx.x == 0) {
        float a = 0.f, b2 = 0.f;
        for (int k = 0; k < 8; ++k) { a += rs[k]; b2 += rs2[k]; }
        part[c * 8 + p] = make_float2(a, b2);
    }
}

__global__ void bn_finalize_kernel(const float2* __restrict__ part, float2* __restrict__ stats) {
    const int c = threadIdx.x;
    float s = 0.f, s2 = 0.f;
    for (int p = 0; p < 8; ++p) { s += part[c * 8 + p].x; s2 += part[c * 8 + p].y; }
    const float inv_n = 1.f / 131072.f;
    const float mean = s * inv_n;
    const float var  = s2 * inv_n - mean * mean;
    stats[c] = make_float2(mean, rsqrtf(var + 1e-5f));
}

__global__ void bn_apply_kernel(const float* __restrict__ x, const float2* __restrict__ stats,
                                const float* __restrict__ gam, const float* __restrict__ bet,
                                float* __restrict__ y) {
    const int idx = blockIdx.x * 256 + threadIdx.x;   // float4 index; grid covers exactly
    const int e = idx * 4;
    const int c = (e / HW_) & 63;
    const float2 st = stats[c];
    const float g = gam[c], be = bet[c];
    float4 v = reinterpret_cast<const float4*>(x)[idx];
    v.x = (v.x - st.x) * st.y * g + be;
    v.y = (v.y - st.x) * st.y * g + be;
    v.z = (v.z - st.x) * st.y * g + be;
    v.w = (v.w - st.x) * st.y * g + be;
    reinterpret_cast<float4*>(y)[idx] = v;
}

// ---------------- 1x1 convs, writing channel-last ----------------
// q/k: 32->32, output [b][h][w][c]
__global__ void conv1x1_c32_kernel(const float* __restrict__ x, const float* __restrict__ wgt,
                                   const float* __restrict__ bias, float* __restrict__ yt) {
    __shared__ float sw[32][33];
    __shared__ float sb[32];
    const int tid = threadIdx.x;
    for (int i = tid; i < 1024; i += 256) sw[i >> 5][i & 31] = wgt[i];
    if (tid < 32) sb[tid] = bias[tid];
    __syncthreads();
    const int pos = blockIdx.x * 256 + tid;   // b*HW + hw
    const int b = pos >> 15, i = pos & 32767;
    float xin[32];
#pragma unroll
    for (int ci = 0; ci < 32; ++ci) xin[ci] = x[((size_t)(b * 32 + ci)) * HW_ + i];
    float* out = yt + (size_t)pos * 32;
#pragma unroll
    for (int co = 0; co < 32; co += 4) {
        float4 a = make_float4(sb[co], sb[co + 1], sb[co + 2], sb[co + 3]);
#pragma unroll
        for (int ci = 0; ci < 32; ++ci) {
            const float xv = xin[ci];
            a.x += sw[co][ci] * xv; a.y += sw[co + 1][ci] * xv;
            a.z += sw[co + 2][ci] * xv; a.w += sw[co + 3][ci] * xv;
        }
        *reinterpret_cast<float4*>(out + co) = a;
    }
}

// v: 64->64, output [b][h][w][d]
__global__ void conv1x1_d64_kernel(const float* __restrict__ x, const float* __restrict__ wgt,
                                   const float* __restrict__ bias, float* __restrict__ vt) {
    __shared__ float sw[64][65];
    __shared__ float sb[64];
    const int tid = threadIdx.x;
    for (int i = tid; i < 4096; i += 256) sw[i >> 6][i & 63] = wgt[i];
    if (tid < 64) sb[tid] = bias[tid];
    __syncthreads();
    const int pos = blockIdx.x * 256 + tid;
    const int b = pos >> 15, i = pos & 32767;
    float xin[64];
#pragma unroll
    for (int ci = 0; ci < 64; ++ci) xin[ci] = x[((size_t)(b * 64 + ci)) * HW_ + i];
    float* out = vt + (size_t)pos * 64;
#pragma unroll
    for (int co = 0; co < 64; co += 4) {
        float4 a = make_float4(sb[co], sb[co + 1], sb[co + 2], sb[co + 3]);
#pragma unroll
        for (int ci = 0; ci < 64; ++ci) {
            const float xv = xin[ci];
            a.x += sw[co][ci] * xv; a.y += sw[co + 1][ci] * xv;
            a.z += sw[co + 2][ci] * xv; a.w += sw[co + 3][ci] * xv;
        }
        *reinterpret_cast<float4*>(out + co) = a;
    }
}

// ---------------- eH: per (b,w): E[h,g] = sum_c q[h,c]*k[g,c], diag=-inf ----------------
// grid (W, B), 256 threads (16 hgrp x 16 ggrp, each 8x8)
__global__ void eH_kernel(const float* __restrict__ qt, const float* __restrict__ kt,
                          float* __restrict__ aH) {
    const int w = blockIdx.x, b = blockIdx.y;
    const int tid = threadIdx.x;
    __shared__ float Qs[32][132];
    __shared__ float Ks[32][132];
    for (int i = tid; i < 4096; i += 256) {
        const int h = i >> 5, c = i & 31;
        const size_t gidx = (((size_t)b * HH + h) * WW + w) * 32 + c;
        Qs[c][h] = qt[gidx];
        Ks[c][h] = kt[gidx];
    }
    __syncthreads();
    const int hg = tid >> 4, gg = tid & 15;
    float acc[8][8];
#pragma unroll
    for (int i = 0; i < 8; ++i)
#pragma unroll
        for (int j = 0; j < 8; ++j) acc[i][j] = 0.f;
    for (int c = 0; c < 32; ++c) {
        float4 qa = *reinterpret_cast<float4*>(&Qs[c][hg * 8]);
        float4 qb = *reinterpret_cast<float4*>(&Qs[c][hg * 8 + 4]);
        float4 ka = *reinterpret_cast<float4*>(&Ks[c][gg * 8]);
        float4 kb = *reinterpret_cast<float4*>(&Ks[c][gg * 8 + 4]);
        float qv[8] = {qa.x, qa.y, qa.z, qa.w, qb.x, qb.y, qb.z, qb.w};
        float kv[8] = {ka.x, ka.y, ka.z, ka.w, kb.x, kb.y, kb.z, kb.w};
#pragma unroll
        for (int i = 0; i < 8; ++i)
#pragma unroll
            for (int j = 0; j < 8; ++j) acc[i][j] += qv[i] * kv[j];
    }
    const float ninf = __int_as_float(0xff800000);
#pragma unroll
    for (int i = 0; i < 8; ++i) {
        const int h = hg * 8 + i;
        float* row = aH + (((size_t)b * HH + h) * WW + w) * 128 + gg * 8;
#pragma unroll
        for (int j = 0; j < 8; ++j) {
            const int g = gg * 8 + j;
            row[j] = (h == g) ? ninf : acc[i][j];
        }
    }
}

// ---------------- eW: per (b,h): E[w,g] = sum_c q[w,c]*k[g,c], g-chunked ----------------
// grid (4, H, B), 256 threads (32 wgrp x 8 ggrp, each 8x8); g chunk of 64
__global__ void eW_kernel(const float* __restrict__ qt, const float* __restrict__ kt,
                          float* __restrict__ aW) {
    const int gc = blockIdx.x * 64;
    const int h = blockIdx.y, b = blockIdx.z;
    const int tid = threadIdx.x;
    __shared__ float Qs[32][260];
    __shared__ float Ks[32][68];
    const float* qbase = qt + (((size_t)b * HH + h) * WW) * 32;
    for (int i = tid; i < 8192; i += 256) { Qs[i & 31][i >> 5] = qbase[i]; }
    const float* kbase = kt + (((size_t)b * HH + h) * WW + gc) * 32;
    for (int i = tid; i < 2048; i += 256) { Ks[i & 31][i >> 5] = kbase[i]; }
    __syncthreads();
    const int wg = tid >> 3, gg = tid & 7;
    float acc[8][8];
#pragma unroll
    for (int i = 0; i < 8; ++i)
#pragma unroll
        for (int j = 0; j < 8; ++j) acc[i][j] = 0.f;
    for (int c = 0; c < 32; ++c) {
        float4 qa = *reinterpret_cast<float4*>(&Qs[c][wg * 8]);
        float4 qb = *reinterpret_cast<float4*>(&Qs[c][wg * 8 + 4]);
        float4 ka = *reinterpret_cast<float4*>(&Ks[c][gg * 8]);
        float4 kb = *reinterpret_cast<float4*>(&Ks[c][gg * 8 + 4]);
        float qv[8] = {qa.x, qa.y, qa.z, qa.w, qb.x, qb.y, qb.z, qb.w};
        float kv[8] = {ka.x, ka.y, ka.z, ka.w, kb.x, kb.y, kb.z, kb.w};
#pragma unroll
        for (int i = 0; i < 8; ++i)
#pragma unroll
            for (int j = 0; j < 8; ++j) acc[i][j] += qv[i] * kv[j];
    }
#pragma unroll
    for (int i = 0; i < 8; ++i) {
        const int w = wg * 8 + i;
        float* row = aW + (((size_t)b * HH + h) * WW + w) * 256 + gc + gg * 8;
        *reinterpret_cast<float4*>(row)     = make_float4(acc[i][0], acc[i][1], acc[i][2], acc[i][3]);
        *reinterpret_cast<float4*>(row + 4) = make_float4(acc[i][4], acc[i][5], acc[i][6], acc[i][7]);
    }
}

// ---------------- softmax over concat(eH[128], eW[256]) per (b,h,w) row, in place ----------------
__global__ void softmax_kernel(float* __restrict__ aH, float* __restrict__ aW) {
    const int row = blockIdx.x * 8 + (threadIdx.x >> 5);
    const int lane = threadIdx.x & 31;
    float4* ph = reinterpret_cast<float4*>(aH) + (size_t)row * 32;
    float4* pw = reinterpret_cast<float4*>(aW) + (size_t)row * 64;
    float4 vh  = ph[lane];
    float4 vw0 = pw[lane];
    float4 vw1 = pw[lane + 32];
    float m = fmaxf(fmaxf(fmaxf(vh.x, vh.y), fmaxf(vh.z, vh.w)),
              fmaxf(fmaxf(fmaxf(vw0.x, vw0.y), fmaxf(vw0.z, vw0.w)),
                    fmaxf(fmaxf(vw1.x, vw1.y), fmaxf(vw1.z, vw1.w))));
#pragma unroll
    for (int o = 16; o; o >>= 1) m = fmaxf(m, __shfl_xor_sync(0xffffffffu, m, o));
    vh.x = __expf(vh.x - m); vh.y = __expf(vh.y - m); vh.z = __expf(vh.z - m); vh.w = __expf(vh.w - m);
    vw0.x = __expf(vw0.x - m); vw0.y = __expf(vw0.y - m); vw0.z = __expf(vw0.z - m); vw0.w = __expf(vw0.w - m);
    vw1.x = __expf(vw1.x - m); vw1.y = __expf(vw1.y - m); vw1.z = __expf(vw1.z - m); vw1.w = __expf(vw1.w - m);
    float s = vh.x + vh.y + vh.z + vh.w + vw0.x + vw0.y + vw0.z + vw0.w + vw1.x + vw1.y + vw1.z + vw1.w;
#pragma unroll
    for (int o = 16; o; o >>= 1) s += __shfl_xor_sync(0xffffffffu, s, o);
    const float inv = 1.f / s;
    vh.x *= inv; vh.y *= inv; vh.z *= inv; vh.w *= inv;
    vw0.x *= inv; vw0.y *= inv; vw0.z *= inv; vw0.w *= inv;
    vw1.x *= inv; vw1.y *= inv; vw1.z *= inv; vw1.w *= inv;
    ph[lane] = vh; pw[lane] = vw0; pw[lane + 32] = vw1;
}

// ---------------- oH: per (b,w): O[d,h] = sum_g v[g,d]*aH[h,g]; out [b][h][w][d] ----------------
// grid (2, W, B), 256 threads (16 dgrp x 16 hgrp, each 4x4)
__global__ void oH_kernel(const float* __restrict__ vt, const float* __restrict__ aH,
                          float* __restrict__ oht) {
    const int hh = blockIdx.x * 64;
    const int w = blockIdx.y, b = blockIdx.z;
    const int tid = threadIdx.x;
    const int dg = tid & 15, hg = tid >> 4;
    __shared__ float Vs[64][64];
    __shared__ float As[64][68];
    float acc[4][4];
#pragma unroll
    for (int i = 0; i < 4; ++i)
#pragma unroll
        for (int j = 0; j < 4; ++j) acc[i][j] = 0.f;
    for (int gc = 0; gc < 128; gc += 64) {
        for (int i = tid; i < 4096; i += 256) {
            const int g = i >> 6, d = i & 63;
            Vs[g][d] = vt[(((size_t)b * HH + gc + g) * WW + w) * 64 + d];
        }
        for (int i = tid; i < 4096; i += 256) {
            const int h = i >> 6, g = i & 63;
            As[g][h] = aH[(((size_t)b * HH + hh + h) * WW + w) * 128 + gc + g];
        }
        __syncthreads();
#pragma unroll 8
        for (int g = 0; g < 64; ++g) {
            float4 vv = *reinterpret_cast<float4*>(&Vs[g][dg * 4]);
            float4 aa = *reinterpret_cast<float4*>(&As[g][hg * 4]);
            float vd[4] = {vv.x, vv.y, vv.z, vv.w};
            float ah[4] = {aa.x, aa.y, aa.z, aa.w};
#pragma unroll
            for (int di = 0; di < 4; ++di)
#pragma unroll
                for (int hj = 0; hj < 4; ++hj) acc[di][hj] += vd[di] * ah[hj];
        }
        __syncthreads();
    }
#pragma unroll
    for (int j = 0; j < 4; ++j) {
        const int h = hh + hg * 4 + j;
        *reinterpret_cast<float4*>(&oht[(((size_t)b * HH + h) * WW + w) * 64 + dg * 4]) =
            make_float4(acc[0][j], acc[1][j], acc[2][j], acc[3][j]);
    }
}

// ---------------- oW + combine: out = gamma*(oH+oW) + x ----------------
// grid (4, H, B), 256 threads (16 dgrp x 16 wgrp, each 4x4)
__global__ void oW_combine_kernel(const float* __restrict__ vt, const float* __restrict__ aW,
                                  const float* __restrict__ oht, const float* __restrict__ x,
                                  const float* __restrict__ gamma, float* __restrict__ xout) {
    const int wt = blockIdx.x * 64;
    const int h = blockIdx.y, b = blockIdx.z;
    const int tid = threadIdx.x;
    const int dg = tid & 15, wg = tid >> 4;
    __shared__ float Vs[64][64];
    __shared__ float As[64][68];
    float acc[4][4];
#pragma unroll
    for (int i = 0; i < 4; ++i)
#pragma unroll
        for (int j = 0; j < 4; ++j) acc[i][j] = 0.f;
    for (int gc = 0; gc < 256; gc += 64) {
        const float* vbase = vt + (((size_t)b * HH + h) * WW + gc) * 64;
        for (int i = tid; i < 4096; i += 256) Vs[i >> 6][i & 63] = vbase[i];
        for (int i = tid; i < 4096; i += 256) {
            const int ww = i >> 6, g = i & 63;
            As[g][ww] = aW[(((size_t)b * HH + h) * WW + wt + ww) * 256 + gc + g];
        }
        __syncthreads();
#pragma unroll 8
        for (int g = 0; g < 64; ++g) {
            float4 vv = *reinterpret_cast<float4*>(&Vs[g][dg * 4]);
            float4 aa = *reinterpret_cast<float4*>(&As[g][wg * 4]);
            float vd[4] = {vv.x, vv.y, vv.z, vv.w};
            float aw4[4] = {aa.x, aa.y, aa.z, aa.w};
#pragma unroll
            for (int di = 0; di < 4; ++di)
#pragma unroll
                for (int wj = 0; wj < 4; ++wj) acc[di][wj] += vd[di] * aw4[wj];
        }
        __syncthreads();
    }
    const float gam = *gamma;
#pragma unroll
    for (int di = 0; di < 4; ++di) {
        const int d = dg * 4 + di;
        const size_t xoff = ((size_t)(b * 64 + d)) * HW_ + (size_t)h * WW + wt + wg * 4;
        float4 xr = *reinterpret_cast<const float4*>(x + xoff);
        float o[4];
#pragma unroll
        for (int wj = 0; wj < 4; ++wj)
            o[wj] = oht[(((size_t)b * HH + h) * WW + wt + wg * 4 + wj) * 64 + d];
        float4 r;
        r.x = gam * (acc[di][0] + o[0]) + xr.x;
        r.y = gam * (acc[di][1] + o[1]) + xr.y;
        r.z = gam * (acc[di][2] + o[2]) + xr.z;
        r.w = gam * (acc[di][3] + o[3]) + xr.w;
        *reinterpret_cast<float4*>(xout + xoff) = r;
    }
}

// ---------------- host ----------------
extern "C" void kernel_launch(void* const* d_in, const int* in_sizes, int n_in,
                              void* d_out, int out_size) {
    const float* cost  = (const float*)d_in[0];
    const float* lf0   = (const float*)d_in[1];
    const float* lf1   = (const float*)d_in[2];
    const float* Wa    = (const float*)d_in[3];
    const float* bn_ag = (const float*)d_in[4];
    const float* bn_ab = (const float*)d_in[5];
    const float* Wq    = (const float*)d_in[6];
    const float* bq    = (const float*)d_in[7];
    const float* Wk    = (const float*)d_in[8];
    const float* bk    = (const float*)d_in[9];
    const float* Wv    = (const float*)d_in[10];
    const float* bv    = (const float*)d_in[11];
    const float* gamma = (const float*)d_in[12];
    const float* Wb    = (const float*)d_in[13];
    const float* bn_bg = (const float*)d_in[14];
    const float* bn_bb = (const float*)d_in[15];
    float* out = (float*)d_out;

    float *conv, *xA, *xB, *vt, *oht, *qt, *kt, *aH, *aW;
    float2 *part, *stats;
    cudaGetSymbolAddress((void**)&conv, g_conv);
    cudaGetSymbolAddress((void**)&xA, g_xA);
    cudaGetSymbolAddress((void**)&xB, g_xB);
    cudaGetSymbolAddress((void**)&vt, g_vt);
    cudaGetSymbolAddress((void**)&oht, g_oht);
    cudaGetSymbolAddress((void**)&qt, g_qt);
    cudaGetSymbolAddress((void**)&kt, g_kt);
    cudaGetSymbolAddress((void**)&aH, g_aH);
    cudaGetSymbolAddress((void**)&aW, g_aW);
    cudaGetSymbolAddress((void**)&part, g_part);
    cudaGetSymbolAddress((void**)&stats, g_stats);

    // Stage A: conv3x3(cost, Wa) + BN -> xA
    conv3x3_kernel<<<dim3(16, 32), dim3(32, 8)>>>(cost, Wa, conv);
    bn_reduce_kernel<<<dim3(64, 8), 256>>>(conv, part);
    bn_finalize_kernel<<<1, 64>>>(part, stats);
    bn_apply_kernel<<<8192, 256>>>(conv, stats, bn_ag, bn_ab, xA);

    // Stage B: attention maps (invariant across recurrence -> compute once)
    conv1x1_c32_kernel<<<512, 256>>>(lf0, Wq, bq, qt);
    conv1x1_c32_kernel<<<512, 256>>>(lf1, Wk, bk, kt);
    eH_kernel<<<dim3(256, 4), 256>>>(qt, kt, aH);
    eW_kernel<<<dim3(4, 128, 4), 256>>>(qt, kt, aW);
    softmax_kernel<<<16384, 256>>>(aH, aW);

    // Stage C: 2 recurrence iterations
    float* cur = xA;
    float* nxt = xB;
    for (int it = 0; it < 2; ++it) {
        conv1x1_d64_kernel<<<512, 256>>>(cur, Wv, bv, vt);
        oH_kernel<<<dim3(2, 256, 4), 256>>>(vt, aH, oht);
        oW_combine_kernel<<<dim3(4, 128, 4), 256>>>(vt, aW, oht, cur, gamma, nxt);
        float* t = cur; cur = nxt; nxt = t;
    }

    // Stage D: conv3x3(cur, Wb) + BN -> out
    conv3x3_kernel<<<dim3(16, 32), dim3(32, 8)>>>(cur, Wb, conv);
    bn_reduce_kernel<<<dim3(64, 8), 256>>>(conv, part);
    bn_finalize_kernel<<<1, 64>>>(part, stats);
    bn_apply_kernel<<<8192, 256>>>(conv, stats, bn_bg, bn_bb, out);
}

// round 3
// speedup vs baseline: 1.3784x; 1.3784x over previous
#include <cuda_runtime.h>
#include <cstdint>
#include <cstddef>

#define BB 4
#define CC 32
#define DD 64
#define HH 128
#define WW 256
#define HW_ (HH*WW)          // 32768
#define BDHW_ (BB*DD*HW_)    // 8388608
#define BCHW_ (BB*CC*HW_)    // 4194304

// ---------------- scratch (static device globals; no allocation) ----------------
__device__ float g_conv[BDHW_];
__device__ float g_xA[BDHW_];
__device__ float g_xB[BDHW_];
__device__ float g_vt[BDHW_];        // v in [b][h][w][d] layout
__device__ float g_oht[BDHW_];       // oH in [b][h][w][d] layout
__device__ float g_qt[BCHW_];        // q in [b][h][w][c]
__device__ float g_kt[BCHW_];        // k in [b][h][w][c]
__device__ float g_aH[BB*HH*WW*HH];  // 16777216
__device__ float g_aW[BB*HH*WW*WW];  // 33554432
__device__ float g_wt[9*64*64];      // transposed tf32 conv weights [t][c][d]
__device__ float2 g_part[64*8];
__device__ float2 g_stats[64];

// ---------------- weight transform: W[d][c][3][3] -> wt[t][c][d], tf32-rounded ----------------
__global__ void wtrans_kernel(const float* __restrict__ W, float* __restrict__ wt) {
    const int i = blockIdx.x * 256 + threadIdx.x;
    if (i >= 9 * 64 * 64) return;
    const int t = i >> 12;
    const int rem = i & 4095;
    const int c = rem >> 6;
    const int d = rem & 63;
    float v = W[(((d << 6) + c) * 9) + t];
    uint32_t uv;
    asm("cvt.rna.tf32.f32 %0, %1;" : "=r"(uv) : "f"(v));
    wt[i] = __uint_as_float(uv);
}

// ---------------- conv3x3 via tf32 mma.sync (tap-decomposed implicit GEMM) ----------------
// grid (W/64, H, B), 128 threads (4 warps). Block output tile: 64 d x 64 w positions.
#define XS_RSTRIDE 68
#define XS_CSTRIDE (3*68)       // 204
#define XS_FLOATS (64*3*68)     // 13056
#define WS_STRIDE 72
#define WS_FLOATS (64*72)       // 4608
#define CONV_SMEM ((XS_FLOATS + WS_FLOATS) * 4)   // 70656 bytes

__device__ __forceinline__ void mma_tf32(float* c, uint32_t a0, uint32_t a1, uint32_t a2, uint32_t a3,
                                         uint32_t b0, uint32_t b1) {
    asm volatile("mma.sync.aligned.m16n8k8.row.col.f32.tf32.tf32.f32 "
                 "{%0,%1,%2,%3}, {%4,%5,%6,%7}, {%8,%9}, {%0,%1,%2,%3};"
                 : "+f"(c[0]), "+f"(c[1]), "+f"(c[2]), "+f"(c[3])
                 : "r"(a0), "r"(a1), "r"(a2), "r"(a3), "r"(b0), "r"(b1));
}

__global__ void conv3x3_mma_kernel(const float* __restrict__ x, const float* __restrict__ wt,
                                   float* __restrict__ y) {
    extern __shared__ float smem[];
    float* xs = smem;                 // [c][r][68]
    float* ws = smem + XS_FLOATS;     // [c][72]

    const int w0 = blockIdx.x * 64;
    const int h  = blockIdx.y;
    const int b  = blockIdx.z;
    const int tid = threadIdx.x;
    const int lane = tid & 31;
    const int warp = tid >> 5;
    const int d0 = warp * 16;
    const int q4 = lane & 3;      // quad col
    const int g8 = lane >> 2;     // group id

    // load input tile: c in [0,64), rows h-1..h+1, cols w0-1..w0+64, tf32-rounded
    for (int i = tid; i < 64 * 3 * 66; i += 128) {
        const int c = i / 198;
        const int rem = i - c * 198;
        const int r = rem / 66;
        const int col = rem - r * 66;
        const int gh = h + r - 1;
        const int gw = w0 + col - 1;
        float v = 0.f;
        if (gh >= 0 && gh < HH && gw >= 0 && gw < WW)
            v = x[((size_t)(b * 64 + c)) * HW_ + gh * WW + gw];
        uint32_t uv;
        asm("cvt.rna.tf32.f32 %0, %1;" : "=r"(uv) : "f"(v));
        xs[c * XS_CSTRIDE + r * XS_RSTRIDE + col] = __uint_as_float(uv);
    }

    float acc[8][4];
#pragma unroll
    for (int j = 0; j < 8; ++j)
#pragma unroll
        for (int k = 0; k < 4; ++k) acc[j][k] = 0.f;

    for (int t = 0; t < 9; ++t) {
        __syncthreads();
        // load this tap's weights ws[c][d] (coalesced from wt[t][c][d])
        const float* wp = wt + t * 4096;
        for (int i = tid; i < 4096; i += 128)
            ws[(i >> 6) * WS_STRIDE + (i & 63)] = wp[i];
        __syncthreads();

        const int dh = t / 3;
        const int dw = t - dh * 3;
#pragma unroll
        for (int ck = 0; ck < 8; ++ck) {
            const int c0 = ck * 8;
            const float* wr0 = ws + (c0 + q4) * WS_STRIDE + d0 + g8;
            const float* wr1 = wr0 + 4 * WS_STRIDE;
            const uint32_t a0 = __float_as_uint(wr0[0]);
            const uint32_t a1 = __float_as_uint(wr0[8]);
            const uint32_t a2 = __float_as_uint(wr1[0]);
            const uint32_t a3 = __float_as_uint(wr1[8]);
            const float* xb0 = xs + (c0 + q4) * XS_CSTRIDE + dh * XS_RSTRIDE + dw + g8;
            const float* xb1 = xb0 + 4 * XS_CSTRIDE;
#pragma unroll
            for (int j = 0; j < 8; ++j) {
                const uint32_t b0 = __float_as_uint(xb0[j * 8]);
                const uint32_t b1 = __float_as_uint(xb1[j * 8]);
                mma_tf32(acc[j], a0, a1, a2, a3, b0, b1);
            }
        }
    }

    // epilogue: C tile j: rows d0+g8 / d0+g8+8, cols w0 + j*8 + 2*q4 (+1)
#pragma unroll
    for (int j = 0; j < 8; ++j) {
        const int w = w0 + j * 8 + 2 * q4;
        const size_t base = ((size_t)(b * 64 + d0 + g8)) * HW_ + (size_t)h * WW + w;
        *reinterpret_cast<float2*>(y + base) = make_float2(acc[j][0], acc[j][1]);
        *reinterpret_cast<float2*>(y + base + (size_t)8 * HW_) = make_float2(acc[j][2], acc[j][3]);
    }
}

// ---------------- batchnorm: partial reduce / finalize / apply ----------------
__global__ void bn_reduce_kernel(const float* __restrict__ x, float2* __restrict__ part) {
    const int c = blockIdx.x, p = blockIdx.y;
    float s = 0.f, s2 = 0.f;
    const int base = p * 16384;
    for (int j = threadIdx.x; j < 16384; j += 256) {
        const int f = base + j;
        const int b = f >> 15;
        const int i = f & 32767;
        const float v = x[((size_t)(b * 64 + c)) * HW_ + i];
        s += v; s2 += v * v;
    }
    __shared__ float rs[8], rs2[8];
#pragma unroll
    for (int o = 16; o; o >>= 1) {
        s  += __shfl_xor_sync(0xffffffffu, s, o);
        s2 += __shfl_xor_sync(0xffffffffu, s2, o);
    }
    if ((threadIdx.x & 31) == 0) { rs[threadIdx.x >> 5] = s; rs2[threadIdx.x >> 5] = s2; }
    __syncthreads();
    if (threadIdx.x == 0) {
        float a = 0.f, b2 = 0.f;
        for (int k = 0; k < 8; ++k) { a += rs[k]; b2 += rs2[k]; }
        part[c * 8 + p] = make_float2(a, b2);
    }
}

__global__ void bn_finalize_kernel(const float2* __restrict__ part, float2* __restrict__ stats) {
    const int c = threadIdx.x;
    float s = 0.f, s2 = 0.f;
    for (int p = 0; p < 8; ++p) { s += part[c * 8 + p].x; s2 += part[c * 8 + p].y; }
    const float inv_n = 1.f / 131072.f;
    const float mean = s * inv_n;
    const float var  = s2 * inv_n - mean * mean;
    stats[c] = make_float2(mean, rsqrtf(var + 1e-5f));
}

__global__ void bn_apply_kernel(const float* __restrict__ x, const float2* __restrict__ stats,
                                const float* __restrict__ gam, const float* __restrict__ bet,
                                float* __restrict__ y) {
    const int idx = blockIdx.x * 256 + threadIdx.x;
    const int e = idx * 4;
    const int c = (e / HW_) & 63;
    const float2 st = stats[c];
    const float g = gam[c], be = bet[c];
    float4 v = reinterpret_cast<const float4*>(x)[idx];
    v.x = (v.x - st.x) * st.y * g + be;
    v.y = (v.y - st.x) * st.y * g + be;
    v.z = (v.z - st.x) * st.y * g + be;
    v.w = (v.w - st.x) * st.y * g + be;
    reinterpret_cast<float4*>(y)[idx] = v;
}

// ---------------- 1x1 convs, writing channel-last ----------------
__global__ void conv1x1_c32_kernel(const float* __restrict__ x, const float* __restrict__ wgt,
                                   const float* __restrict__ bias, float* __restrict__ yt) {
    __shared__ float sw[32][33];
    __shared__ float sb[32];
    const int tid = threadIdx.x;
    for (int i = tid; i < 1024; i += 256) sw[i >> 5][i & 31] = wgt[i];
    if (tid < 32) sb[tid] = bias[tid];
    __syncthreads();
    const int pos = blockIdx.x * 256 + tid;
    const int b = pos >> 15, i = pos & 32767;
    float xin[32];
#pragma unroll
    for (int ci = 0; ci < 32; ++ci) xin[ci] = x[((size_t)(b * 32 + ci)) * HW_ + i];
    float* out = yt + (size_t)pos * 32;
#pragma unroll
    for (int co = 0; co < 32; co += 4) {
        float4 a = make_float4(sb[co], sb[co + 1], sb[co + 2], sb[co + 3]);
#pragma unroll
        for (int ci = 0; ci < 32; ++ci) {
            const float xv = xin[ci];
            a.x += sw[co][ci] * xv; a.y += sw[co + 1][ci] * xv;
            a.z += sw[co + 2][ci] * xv; a.w += sw[co + 3][ci] * xv;
        }
        *reinterpret_cast<float4*>(out + co) = a;
    }
}

__global__ void conv1x1_d64_kernel(const float* __restrict__ x, const float* __restrict__ wgt,
                                   const float* __restrict__ bias, float* __restrict__ vt) {
    __shared__ float sw[64][65];
    __shared__ float sb[64];
    const int tid = threadIdx.x;
    for (int i = tid; i < 4096; i += 256) sw[i >> 6][i & 63] = wgt[i];
    if (tid < 64) sb[tid] = bias[tid];
    __syncthreads();
    const int pos = blockIdx.x * 256 + tid;
    const int b = pos >> 15, i = pos & 32767;
    float xin[64];
#pragma unroll
    for (int ci = 0; ci < 64; ++ci) xin[ci] = x[((size_t)(b * 64 + ci)) * HW_ + i];
    float* out = vt + (size_t)pos * 64;
#pragma unroll
    for (int co = 0; co < 64; co += 4) {
        float4 a = make_float4(sb[co], sb[co + 1], sb[co + 2], sb[co + 3]);
#pragma unroll
        for (int ci = 0; ci < 64; ++ci) {
            const float xv = xin[ci];
            a.x += sw[co][ci] * xv; a.y += sw[co + 1][ci] * xv;
            a.z += sw[co + 2][ci] * xv; a.w += sw[co + 3][ci] * xv;
        }
        *reinterpret_cast<float4*>(out + co) = a;
    }
}

// ---------------- eH ----------------
__global__ void eH_kernel(const float* __restrict__ qt, const float* __restrict__ kt,
                          float* __restrict__ aH) {
    const int w = blockIdx.x, b = blockIdx.y;
    const int tid = threadIdx.x;
    __shared__ float Qs[32][132];
    __shared__ float Ks[32][132];
    for (int i = tid; i < 4096; i += 256) {
        const int h = i >> 5, c = i & 31;
        const size_t gidx = (((size_t)b * HH + h) * WW + w) * 32 + c;
        Qs[c][h] = qt[gidx];
        Ks[c][h] = kt[gidx];
    }
    __syncthreads();
    const int hg = tid >> 4, gg = tid & 15;
    float acc[8][8];
#pragma unroll
    for (int i = 0; i < 8; ++i)
#pragma unroll
        for (int j = 0; j < 8; ++j) acc[i][j] = 0.f;
    for (int c = 0; c < 32; ++c) {
        float4 qa = *reinterpret_cast<float4*>(&Qs[c][hg * 8]);
        float4 qb = *reinterpret_cast<float4*>(&Qs[c][hg * 8 + 4]);
        float4 ka = *reinterpret_cast<float4*>(&Ks[c][gg * 8]);
        float4 kb = *reinterpret_cast<float4*>(&Ks[c][gg * 8 + 4]);
        float qv[8] = {qa.x, qa.y, qa.z, qa.w, qb.x, qb.y, qb.z, qb.w};
        float kv[8] = {ka.x, ka.y, ka.z, ka.w, kb.x, kb.y, kb.z, kb.w};
#pragma unroll
        for (int i = 0; i < 8; ++i)
#pragma unroll
            for (int j = 0; j < 8; ++j) acc[i][j] += qv[i] * kv[j];
    }
    const float ninf = __int_as_float(0xff800000);
#pragma unroll
    for (int i = 0; i < 8; ++i) {
        const int h = hg * 8 + i;
        float* row = aH + (((size_t)b * HH + h) * WW + w) * 128 + gg * 8;
#pragma unroll
        for (int j = 0; j < 8; ++j) {
            const int g = gg * 8 + j;
            row[j] = (h == g) ? ninf : acc[i][j];
        }
    }
}

// ---------------- eW ----------------
__global__ void eW_kernel(const float* __restrict__ qt, const float* __restrict__ kt,
                          float* __restrict__ aW) {
    const int gc = blockIdx.x * 64;
    const int h = blockIdx.y, b = blockIdx.z;
    const int tid = threadIdx.x;
    __shared__ float Qs[32][260];
    __shared__ float Ks[32][68];
    const float* qbase = qt + (((size_t)b * HH + h) * WW) * 32;
    for (int i = tid; i < 8192; i += 256) { Qs[i & 31][i >> 5] = qbase[i]; }
    const float* kbase = kt + (((size_t)b * HH + h) * WW + gc) * 32;
    for (int i = tid; i < 2048; i += 256) { Ks[i & 31][i >> 5] = kbase[i]; }
    __syncthreads();
    const int wg = tid >> 3, gg = tid & 7;
    float acc[8][8];
#pragma unroll
    for (int i = 0; i < 8; ++i)
#pragma unroll
        for (int j = 0; j < 8; ++j) acc[i][j] = 0.f;
    for (int c = 0; c < 32; ++c) {
        float4 qa = *reinterpret_cast<float4*>(&Qs[c][wg * 8]);
        float4 qb = *reinterpret_cast<float4*>(&Qs[c][wg * 8 + 4]);
        float4 ka = *reinterpret_cast<float4*>(&Ks[c][gg * 8]);
        float4 kb = *reinterpret_cast<float4*>(&Ks[c][gg * 8 + 4]);
        float qv[8] = {qa.x, qa.y, qa.z, qa.w, qb.x, qb.y, qb.z, qb.w};
        float kv[8] = {ka.x, ka.y, ka.z, ka.w, kb.x, kb.y, kb.z, kb.w};
#pragma unroll
        for (int i = 0; i < 8; ++i)
#pragma unroll
            for (int j = 0; j < 8; ++j) acc[i][j] += qv[i] * kv[j];
    }
#pragma unroll
    for (int i = 0; i < 8; ++i) {
        const int w = wg * 8 + i;
        float* row = aW + (((size_t)b * HH + h) * WW + w) * 256 + gc + gg * 8;
        *reinterpret_cast<float4*>(row)     = make_float4(acc[i][0], acc[i][1], acc[i][2], acc[i][3]);
        *reinterpret_cast<float4*>(row + 4) = make_float4(acc[i][4], acc[i][5], acc[i][6], acc[i][7]);
    }
}

// ---------------- fast exp (FMA/ALU pipes only, no MUFU) ----------------
__device__ __forceinline__ float fexp(float x) {
    x = fmaxf(x, -80.f);
    const float y = x * 1.44269504f;
    const int e = __float2int_rn(y);
    const float f = y - (float)e;
    float p = 0.00133335581f;
    p = fmaf(p, f, 0.00961812910f);
    p = fmaf(p, f, 0.0555041086f);
    p = fmaf(p, f, 0.240226507f);
    p = fmaf(p, f, 0.693147182f);
    p = fmaf(p, f, 1.0f);
    return p * __int_as_float((e + 127) << 23);
}

// ---------------- softmax over concat(eH[128], eW[256]) per row, in place ----------------
__global__ void softmax_kernel(float* __restrict__ aH, float* __restrict__ aW) {
    const int row = blockIdx.x * 8 + (threadIdx.x >> 5);
    const int lane = threadIdx.x & 31;
    float4* ph = reinterpret_cast<float4*>(aH) + (size_t)row * 32;
    float4* pw = reinterpret_cast<float4*>(aW) + (size_t)row * 64;
    float4 vh  = ph[lane];
    float4 vw0 = pw[lane];
    float4 vw1 = pw[lane + 32];
    float m = fmaxf(fmaxf(fmaxf(vh.x, vh.y), fmaxf(vh.z, vh.w)),
              fmaxf(fmaxf(fmaxf(vw0.x, vw0.y), fmaxf(vw0.z, vw0.w)),
                    fmaxf(fmaxf(fmaxf(vw1.x, vw1.y), fmaxf(vw1.z, vw1.w)), -1e30f)));
#pragma unroll
    for (int o = 16; o; o >>= 1) m = fmaxf(m, __shfl_xor_sync(0xffffffffu, m, o));
    vh.x = fexp(vh.x - m); vh.y = fexp(vh.y - m); vh.z = fexp(vh.z - m); vh.w = fexp(vh.w - m);
    vw0.x = fexp(vw0.x - m); vw0.y = fexp(vw0.y - m); vw0.z = fexp(vw0.z - m); vw0.w = fexp(vw0.w - m);
    vw1.x = fexp(vw1.x - m); vw1.y = fexp(vw1.y - m); vw1.z = fexp(vw1.z - m); vw1.w = fexp(vw1.w - m);
    float s = vh.x + vh.y + vh.z + vh.w + vw0.x + vw0.y + vw0.z + vw0.w + vw1.x + vw1.y + vw1.z + vw1.w;
#pragma unroll
    for (int o = 16; o; o >>= 1) s += __shfl_xor_sync(0xffffffffu, s, o);
    const float inv = 1.f / s;
    vh.x *= inv; vh.y *= inv; vh.z *= inv; vh.w *= inv;
    vw0.x *= inv; vw0.y *= inv; vw0.z *= inv; vw0.w *= inv;
    vw1.x *= inv; vw1.y *= inv; vw1.z *= inv; vw1.w *= inv;
    ph[lane] = vh; pw[lane] = vw0; pw[lane + 32] = vw1;
}

// ---------------- oH ----------------
__global__ void oH_kernel(const float* __restrict__ vt, const float* __restrict__ aH,
                          float* __restrict__ oht) {
    const int hh = blockIdx.x * 64;
    const int w = blockIdx.y, b = blockIdx.z;
    const int tid = threadIdx.x;
    const int dg = tid & 15, hg = tid >> 4;
    __shared__ float Vs[64][64];
    __shared__ float As[64][68];
    float acc[4][4];
#pragma unroll
    for (int i = 0; i < 4; ++i)
#pragma unroll
        for (int j = 0; j < 4; ++j) acc[i][j] = 0.f;
    for (int gc = 0; gc < 128; gc += 64) {
        for (int i = tid; i < 4096; i += 256) {
            const int g = i >> 6, d = i & 63;
            Vs[g][d] = vt[(((size_t)b * HH + gc + g) * WW + w) * 64 + d];
        }
        for (int i = tid; i < 4096; i += 256) {
            const int h = i >> 6, g = i & 63;
            As[g][h] = aH[(((size_t)b * HH + hh + h) * WW + w) * 128 + gc + g];
        }
        __syncthreads();
#pragma unroll 8
        for (int g = 0; g < 64; ++g) {
            float4 vv = *reinterpret_cast<float4*>(&Vs[g][dg * 4]);
            float4 aa = *reinterpret_cast<float4*>(&As[g][hg * 4]);
            float vd[4] = {vv.x, vv.y, vv.z, vv.w};
            float ah[4] = {aa.x, aa.y, aa.z, aa.w};
#pragma unroll
            for (int di = 0; di < 4; ++di)
#pragma unroll
                for (int hj = 0; hj < 4; ++hj) acc[di][hj] += vd[di] * ah[hj];
        }
        __syncthreads();
    }
#pragma unroll
    for (int j = 0; j < 4; ++j) {
        const int h = hh + hg * 4 + j;
        *reinterpret_cast<float4*>(&oht[(((size_t)b * HH + h) * WW + w) * 64 + dg * 4]) =
            make_float4(acc[0][j], acc[1][j], acc[2][j], acc[3][j]);
    }
}

// ---------------- oW + combine ----------------
__global__ void oW_combine_kernel(const float* __restrict__ vt, const float* __restrict__ aW,
                                  const float* __restrict__ oht, const float* __restrict__ x,
                                  const float* __restrict__ gamma, float* __restrict__ xout) {
    const int wt = blockIdx.x * 64;
    const int h = blockIdx.y, b = blockIdx.z;
    const int tid = threadIdx.x;
    const int dg = tid & 15, wg = tid >> 4;
    __shared__ float Vs[64][64];
    __shared__ float As[64][68];
    float acc[4][4];
#pragma unroll
    for (int i = 0; i < 4; ++i)
#pragma unroll
        for (int j = 0; j < 4; ++j) acc[i][j] = 0.f;
    for (int gc = 0; gc < 256; gc += 64) {
        const float* vbase = vt + (((size_t)b * HH + h) * WW + gc) * 64;
        for (int i = tid; i < 4096; i += 256) Vs[i >> 6][i & 63] = vbase[i];
        for (int i = tid; i < 4096; i += 256) {
            const int ww = i >> 6, g = i & 63;
            As[g][ww] = aW[(((size_t)b * HH + h) * WW + wt + ww) * 256 + gc + g];
        }
        __syncthreads();
#pragma unroll 8
        for (int g = 0; g < 64; ++g) {
            float4 vv = *reinterpret_cast<float4*>(&Vs[g][dg * 4]);
            float4 aa = *reinterpret_cast<float4*>(&As[g][wg * 4]);
            float vd[4] = {vv.x, vv.y, vv.z, vv.w};
            float aw4[4] = {aa.x, aa.y, aa.z, aa.w};
#pragma unroll
            for (int di = 0; di < 4; ++di)
#pragma unroll
                for (int wj = 0; wj < 4; ++wj) acc[di][wj] += vd[di] * aw4[wj];
        }
        __syncthreads();
    }
    const float gam = *gamma;
#pragma unroll
    for (int di = 0; di < 4; ++di) {
        const int d = dg * 4 + di;
        const size_t xoff = ((size_t)(b * 64 + d)) * HW_ + (size_t)h * WW + wt + wg * 4;
        float4 xr = *reinterpret_cast<const float4*>(x + xoff);
        float o[4];
#pragma unroll
        for (int wj = 0; wj < 4; ++wj)
            o[wj] = oht[(((size_t)b * HH + h) * WW + wt + wg * 4 + wj) * 64 + d];
        float4 r;
        r.x = gam * (acc[di][0] + o[0]) + xr.x;
        r.y = gam * (acc[di][1] + o[1]) + xr.y;
        r.z = gam * (acc[di][2] + o[2]) + xr.z;
        r.w = gam * (acc[di][3] + o[3]) + xr.w;
        *reinterpret_cast<float4*>(xout + xoff) = r;
    }
}

// ---------------- host ----------------
extern "C" void kernel_launch(void* const* d_in, const int* in_sizes, int n_in,
                              void* d_out, int out_size) {
    const float* cost  = (const float*)d_in[0];
    const float* lf0   = (const float*)d_in[1];
    const float* lf1   = (const float*)d_in[2];
    const float* Wa    = (const float*)d_in[3];
    const float* bn_ag = (const float*)d_in[4];
    const float* bn_ab = (const float*)d_in[5];
    const float* Wq    = (const float*)d_in[6];
    const float* bq    = (const float*)d_in[7];
    const float* Wk    = (const float*)d_in[8];
    const float* bk    = (const float*)d_in[9];
    const float* Wv    = (const float*)d_in[10];
    const float* bv    = (const float*)d_in[11];
    const float* gamma = (const float*)d_in[12];
    const float* Wb    = (const float*)d_in[13];
    const float* bn_bg = (const float*)d_in[14];
    const float* bn_bb = (const float*)d_in[15];
    float* out = (float*)d_out;

    float *conv, *xA, *xB, *vt, *oht, *qt, *kt, *aH, *aW, *wtb;
    float2 *part, *stats;
    cudaGetSymbolAddress((void**)&conv, g_conv);
    cudaGetSymbolAddress((void**)&xA, g_xA);
    cudaGetSymbolAddress((void**)&xB, g_xB);
    cudaGetSymbolAddress((void**)&vt, g_vt);
    cudaGetSymbolAddress((void**)&oht, g_oht);
    cudaGetSymbolAddress((void**)&qt, g_qt);
    cudaGetSymbolAddress((void**)&kt, g_kt);
    cudaGetSymbolAddress((void**)&aH, g_aH);
    cudaGetSymbolAddress((void**)&aW, g_aW);
    cudaGetSymbolAddress((void**)&wtb, g_wt);
    cudaGetSymbolAddress((void**)&part, g_part);
    cudaGetSymbolAddress((void**)&stats, g_stats);

    // Idempotent, called unconditionally (no static guards — harness rule).
    cudaFuncSetAttribute(conv3x3_mma_kernel,
                         cudaFuncAttributeMaxDynamicSharedMemorySize, CONV_SMEM);

    // Stage A: conv3x3(cost, Wa) + BN -> xA
    wtrans_kernel<<<144, 256>>>(Wa, wtb);
    conv3x3_mma_kernel<<<dim3(4, 128, 4), 128, CONV_SMEM>>>(cost, wtb, conv);
    bn_reduce_kernel<<<dim3(64, 8), 256>>>(conv, part);
    bn_finalize_kernel<<<1, 64>>>(part, stats);
    bn_apply_kernel<<<8192, 256>>>(conv, stats, bn_ag, bn_ab, xA);

    // Stage B: attention maps (invariant across recurrence -> compute once)
    conv1x1_c32_kernel<<<512, 256>>>(lf0, Wq, bq, qt);
    conv1x1_c32_kernel<<<512, 256>>>(lf1, Wk, bk, kt);
    eH_kernel<<<dim3(256, 4), 256>>>(qt, kt, aH);
    eW_kernel<<<dim3(4, 128, 4), 256>>>(qt, kt, aW);
    softmax_kernel<<<16384, 256>>>(aH, aW);

    // Stage C: 2 recurrence iterations
    float* cur = xA;
    float* nxt = xB;
    for (int it = 0; it < 2; ++it) {
        conv1x1_d64_kernel<<<512, 256>>>(cur, Wv, bv, vt);
        oH_kernel<<<dim3(2, 256, 4), 256>>>(vt, aH, oht);
        oW_combine_kernel<<<dim3(4, 128, 4), 256>>>(vt, aW, oht, cur, gamma, nxt);
        float* t = cur; cur = nxt; nxt = t;
    }

    // Stage D: conv3x3(cur, Wb) + BN -> out
    wtrans_kernel<<<144, 256>>>(Wb, wtb);
    conv3x3_mma_kernel<<<dim3(4, 128, 4), 128, CONV_SMEM>>>(cur, wtb, conv);
    bn_reduce_kernel<<<dim3(64, 8), 256>>>(conv, part);
    bn_finalize_kernel<<<1, 64>>>(part, stats);
    bn_apply_kernel<<<8192, 256>>>(conv, stats, bn_bg, bn_bb, out);
}

// round 5
// speedup vs baseline: 1.6259x; 1.1796x over previous
#include <cuda_runtime.h>
#include <cuda_fp16.h>
#include <cstdint>
#include <cstddef>

#define BB 4
#define CC 32
#define DD 64
#define HH 128
#define WW 256
#define HW_ (HH*WW)          // 32768
#define BDHW_ (BB*DD*HW_)    // 8388608
#define BCHW_ (BB*CC*HW_)    // 4194304

// ---------------- scratch (static device globals; no allocation) ----------------
__device__ float g_conv[BDHW_];
__device__ float g_xA[BDHW_];
__device__ float g_xB[BDHW_];
__device__ float g_vt[BDHW_];        // v in [b][h][w][d] layout
__device__ float g_oht[BDHW_];       // oH in [b][h][w][d] layout
__device__ float g_qt[BCHW_];        // q in [b][h][w][c]
__device__ float g_kt[BCHW_];        // k in [b][h][w][c]
__device__ float g_aH[BB*HH*WW*HH];  // fp32 scores (H part)
__device__ float g_aW[BB*HH*WW*WW];  // fp32 scores (W part)
__device__ __half g_aHh[BB*HH*WW*HH];  // fp16 normalized weights
__device__ __half g_aWh[BB*HH*WW*WW];
__device__ float g_wt[9*64*64];      // transposed tf32 conv weights [t][c][d]
__device__ float2 g_part[64*8];
__device__ float2 g_stats[64];

// ---------------- weight transform: W[d][c][3][3] -> wt[t][c][d], tf32-rounded ----------------
__global__ void wtrans_kernel(const float* __restrict__ W, float* __restrict__ wt) {
    const int i = blockIdx.x * 256 + threadIdx.x;
    if (i >= 9 * 64 * 64) return;
    const int t = i >> 12;
    const int rem = i & 4095;
    const int c = rem >> 6;
    const int d = rem & 63;
    float v = W[(((d << 6) + c) * 9) + t];
    uint32_t uv;
    asm("cvt.rna.tf32.f32 %0, %1;" : "=r"(uv) : "f"(v));
    wt[i] = __uint_as_float(uv);
}

// ---------------- conv3x3 via tf32 mma.sync, 2 h-rows per block ----------------
// grid (W/64, H/2, B), 256 threads (8 warps). Tile: 64 d x 64 w x 2 h.
#define XS_RSTRIDE 68
#define XS_CSTRIDE 280          // 4*68 + 8 pad; 280 % 32 = 24 -> conflict-free B frags
#define XS_FLOATS (64*280)      // 17920
#define WS_STRIDE 72
#define WS_FLOATS (64*72)       // 4608
#define CONV_SMEM ((XS_FLOATS + WS_FLOATS) * 4)   // 90112 bytes

__device__ __forceinline__ void mma_tf32(float* c, uint32_t a0, uint32_t a1, uint32_t a2, uint32_t a3,
                                         uint32_t b0, uint32_t b1) {
    asm volatile("mma.sync.aligned.m16n8k8.row.col.f32.tf32.tf32.f32 "
                 "{%0,%1,%2,%3}, {%4,%5,%6,%7}, {%8,%9}, {%0,%1,%2,%3};"
                 : "+f"(c[0]), "+f"(c[1]), "+f"(c[2]), "+f"(c[3])
                 : "r"(a0), "r"(a1), "r"(a2), "r"(a3), "r"(b0), "r"(b1));
}

__global__ void conv3x3_mma_kernel(const float* __restrict__ x, const float* __restrict__ wt,
                                   float* __restrict__ y) {
    extern __shared__ float smem[];
    float* xs = smem;                 // [c][280] : 4 rows of 68 (+pad)
    float* ws = smem + XS_FLOATS;     // [c][72]

    const int w0 = blockIdx.x * 64;
    const int h0 = blockIdx.y * 2;
    const int b  = blockIdx.z;
    const int tid = threadIdx.x;
    const int lane = tid & 31;
    const int warp = tid >> 5;
    const int hsel = warp >> 2;       // 0/1 -> output row h0+hsel
    const int d0 = (warp & 3) * 16;
    const int q4 = lane & 3;
    const int g8 = lane >> 2;

    // input tile: c in [0,64), rows h0-1..h0+2, cols w0-1..w0+64, tf32-rounded
    for (int i = tid; i < 64 * 4 * 66; i += 256) {
        const int c = i / 264;
        const int rem = i - c * 264;
        const int r = rem / 66;
        const int col = rem - r * 66;
        const int gh = h0 + r - 1;
        const int gw = w0 + col - 1;
        float v = 0.f;
        if (gh >= 0 && gh < HH && gw >= 0 && gw < WW)
            v = x[((size_t)(b * 64 + c)) * HW_ + gh * WW + gw];
        uint32_t uv;
        asm("cvt.rna.tf32.f32 %0, %1;" : "=r"(uv) : "f"(v));
        xs[c * XS_CSTRIDE + r * XS_RSTRIDE + col] = __uint_as_float(uv);
    }

    float acc[8][4];
#pragma unroll
    for (int j = 0; j < 8; ++j)
#pragma unroll
        for (int k = 0; k < 4; ++k) acc[j][k] = 0.f;

    for (int t = 0; t < 9; ++t) {
        __syncthreads();
        const float* wp = wt + t * 4096;
        for (int i = tid; i < 4096; i += 256)
            ws[(i >> 6) * WS_STRIDE + (i & 63)] = wp[i];
        __syncthreads();

        const int dh = t / 3;
        const int dw = t - dh * 3;
#pragma unroll
        for (int ck = 0; ck < 8; ++ck) {
            const int c0 = ck * 8;
            const float* wr0 = ws + (c0 + q4) * WS_STRIDE + d0 + g8;
            const float* wr1 = wr0 + 4 * WS_STRIDE;
            const uint32_t a0 = __float_as_uint(wr0[0]);
            const uint32_t a1 = __float_as_uint(wr0[8]);
            const uint32_t a2 = __float_as_uint(wr1[0]);
            const uint32_t a3 = __float_as_uint(wr1[8]);
            const float* xb0 = xs + (c0 + q4) * XS_CSTRIDE + (hsel + dh) * XS_RSTRIDE + dw + g8;
            const float* xb1 = xb0 + 4 * XS_CSTRIDE;
#pragma unroll
            for (int j = 0; j < 8; ++j) {
                const uint32_t b0 = __float_as_uint(xb0[j * 8]);
                const uint32_t b1 = __float_as_uint(xb1[j * 8]);
                mma_tf32(acc[j], a0, a1, a2, a3, b0, b1);
            }
        }
    }

    const int h = h0 + hsel;
#pragma unroll
    for (int j = 0; j < 8; ++j) {
        const int w = w0 + j * 8 + 2 * q4;
        const size_t base = ((size_t)(b * 64 + d0 + g8)) * HW_ + (size_t)h * WW + w;
        *reinterpret_cast<float2*>(y + base) = make_float2(acc[j][0], acc[j][1]);
        *reinterpret_cast<float2*>(y + base + (size_t)8 * HW_) = make_float2(acc[j][2], acc[j][3]);
    }
}

// ---------------- batchnorm: partial reduce / finalize / apply ----------------
__global__ void bn_reduce_kernel(const float* __restrict__ x, float2* __restrict__ part) {
    const int c = blockIdx.x, p = blockIdx.y;
    float s = 0.f, s2 = 0.f;
    const int base = p * 16384;
    for (int j = threadIdx.x; j < 16384; j += 256) {
        const int f = base + j;
        const int b = f >> 15;
        const int i = f & 32767;
        const float v = x[((size_t)(b * 64 + c)) * HW_ + i];
        s += v; s2 += v * v;
    }
    __shared__ float rs[8], rs2[8];
#pragma unroll
    for (int o = 16; o; o >>= 1) {
        s  += __shfl_xor_sync(0xffffffffu, s, o);
        s2 += __shfl_xor_sync(0xffffffffu, s2, o);
    }
    if ((threadIdx.x & 31) == 0) { rs[threadIdx.x >> 5] = s; rs2[threadIdx.x >> 5] = s2; }
    __syncthreads();
    if (threadIdx.x == 0) {
        float a = 0.f, b2 = 0.f;
        for (int k = 0; k < 8; ++k) { a += rs[k]; b2 += rs2[k]; }
        part[c * 8 + p] = make_float2(a, b2);
    }
}

__global__ void bn_finalize_kernel(const float2* __restrict__ part, float2* __restrict__ stats) {
    const int c = threadIdx.x;
    float s = 0.f, s2 = 0.f;
    for (int p = 0; p < 8; ++p) { s += part[c * 8 + p].x; s2 += part[c * 8 + p].y; }
    const float inv_n = 1.f / 131072.f;
    const float mean = s * inv_n;
    const float var  = s2 * inv_n - mean * mean;
    stats[c] = make_float2(mean, rsqrtf(var + 1e-5f));
}

__global__ void bn_apply_kernel(const float* __restrict__ x, const float2* __restrict__ stats,
                                const float* __restrict__ gam, const float* __restrict__ bet,
                                float* __restrict__ y) {
    const int idx = blockIdx.x * 256 + threadIdx.x;
    const int e = idx * 4;
    const int c = (e / HW_) & 63;
    const float2 st = stats[c];
    const float g = gam[c], be = bet[c];
    float4 v = reinterpret_cast<const float4*>(x)[idx];
    v.x = (v.x - st.x) * st.y * g + be;
    v.y = (v.y - st.x) * st.y * g + be;
    v.z = (v.z - st.x) * st.y * g + be;
    v.w = (v.w - st.x) * st.y * g + be;
    reinterpret_cast<float4*>(y)[idx] = v;
}

// ---------------- 1x1 convs, writing channel-last ----------------
__global__ void conv1x1_c32_kernel(const float* __restrict__ x, const float* __restrict__ wgt,
                                   const float* __restrict__ bias, float* __restrict__ yt) {
    __shared__ float sw[32][33];
    __shared__ float sb[32];
    const int tid = threadIdx.x;
    for (int i = tid; i < 1024; i += 256) sw[i >> 5][i & 31] = wgt[i];
    if (tid < 32) sb[tid] = bias[tid];
    __syncthreads();
    const int pos = blockIdx.x * 256 + tid;
    const int b = pos >> 15, i = pos & 32767;
    float xin[32];
#pragma unroll
    for (int ci = 0; ci < 32; ++ci) xin[ci] = x[((size_t)(b * 32 + ci)) * HW_ + i];
    float* out = yt + (size_t)pos * 32;
#pragma unroll
    for (int co = 0; co < 32; co += 4) {
        float4 a = make_float4(sb[co], sb[co + 1], sb[co + 2], sb[co + 3]);
#pragma unroll
        for (int ci = 0; ci < 32; ++ci) {
            const float xv = xin[ci];
            a.x += sw[co][ci] * xv; a.y += sw[co + 1][ci] * xv;
            a.z += sw[co + 2][ci] * xv; a.w += sw[co + 3][ci] * xv;
        }
        *reinterpret_cast<float4*>(out + co) = a;
    }
}

__global__ void conv1x1_d64_kernel(const float* __restrict__ x, const float* __restrict__ wgt,
                                   const float* __restrict__ bias, float* __restrict__ vt) {
    __shared__ float sw[64][65];
    __shared__ float sb[64];
    const int tid = threadIdx.x;
    for (int i = tid; i < 4096; i += 256) sw[i >> 6][i & 63] = wgt[i];
    if (tid < 64) sb[tid] = bias[tid];
    __syncthreads();
    const int pos = blockIdx.x * 256 + tid;
    const int b = pos >> 15, i = pos & 32767;
    float xin[64];
#pragma unroll
    for (int ci = 0; ci < 64; ++ci) xin[ci] = x[((size_t)(b * 64 + ci)) * HW_ + i];
    float* out = vt + (size_t)pos * 64;
#pragma unroll
    for (int co = 0; co < 64; co += 4) {
        float4 a = make_float4(sb[co], sb[co + 1], sb[co + 2], sb[co + 3]);
#pragma unroll
        for (int ci = 0; ci < 64; ++ci) {
            const float xv = xin[ci];
            a.x += sw[co][ci] * xv; a.y += sw[co + 1][ci] * xv;
            a.z += sw[co + 2][ci] * xv; a.w += sw[co + 3][ci] * xv;
        }
        *reinterpret_cast<float4*>(out + co) = a;
    }
}

// ---------------- eH: per (b,w): E[h,g] = sum_c q[h,c]*k[g,c], diag=-inf ----------------
__global__ void eH_kernel(const float* __restrict__ qt, const float* __restrict__ kt,
                          float* __restrict__ aH) {
    const int w = blockIdx.x, b = blockIdx.y;
    const int tid = threadIdx.x;
    __shared__ float Qs[32][132];
    __shared__ float Ks[32][132];
    for (int i = tid; i < 4096; i += 256) {
        const int h = i >> 5, c = i & 31;
        const size_t gidx = (((size_t)b * HH + h) * WW + w) * 32 + c;
        Qs[c][h] = qt[gidx];
        Ks[c][h] = kt[gidx];
    }
    __syncthreads();
    const int hg = tid >> 4, gg = tid & 15;
    float acc[8][8];
#pragma unroll
    for (int i = 0; i < 8; ++i)
#pragma unroll
        for (int j = 0; j < 8; ++j) acc[i][j] = 0.f;
    for (int c = 0; c < 32; ++c) {
        float4 qa = *reinterpret_cast<float4*>(&Qs[c][hg * 8]);
        float4 qb = *reinterpret_cast<float4*>(&Qs[c][hg * 8 + 4]);
        float4 ka = *reinterpret_cast<float4*>(&Ks[c][gg * 8]);
        float4 kb = *reinterpret_cast<float4*>(&Ks[c][gg * 8 + 4]);
        float qv[8] = {qa.x, qa.y, qa.z, qa.w, qb.x, qb.y, qb.z, qb.w};
        float kv[8] = {ka.x, ka.y, ka.z, ka.w, kb.x, kb.y, kb.z, kb.w};
#pragma unroll
        for (int i = 0; i < 8; ++i)
#pragma unroll
            for (int j = 0; j < 8; ++j) acc[i][j] += qv[i] * kv[j];
    }
    const float ninf = __int_as_float(0xff800000);
#pragma unroll
    for (int i = 0; i < 8; ++i) {
        const int h = hg * 8 + i;
        float* row = aH + (((size_t)b * HH + h) * WW + w) * 128 + gg * 8;
#pragma unroll
        for (int j = 0; j < 8; ++j) {
            const int g = gg * 8 + j;
            row[j] = (h == g) ? ninf : acc[i][j];
        }
    }
}

// ---------------- eW ----------------
__global__ void eW_kernel(const float* __restrict__ qt, const float* __restrict__ kt,
                          float* __restrict__ aW) {
    const int gc = blockIdx.x * 64;
    const int h = blockIdx.y, b = blockIdx.z;
    const int tid = threadIdx.x;
    __shared__ float Qs[32][260];
    __shared__ float Ks[32][68];
    const float* qbase = qt + (((size_t)b * HH + h) * WW) * 32;
    for (int i = tid; i < 8192; i += 256) { Qs[i & 31][i >> 5] = qbase[i]; }
    const float* kbase = kt + (((size_t)b * HH + h) * WW + gc) * 32;
    for (int i = tid; i < 2048; i += 256) { Ks[i & 31][i >> 5] = kbase[i]; }
    __syncthreads();
    const int wg = tid >> 3, gg = tid & 7;
    float acc[8][8];
#pragma unroll
    for (int i = 0; i < 8; ++i)
#pragma unroll
        for (int j = 0; j < 8; ++j) acc[i][j] = 0.f;
    for (int c = 0; c < 32; ++c) {
        float4 qa = *reinterpret_cast<float4*>(&Qs[c][wg * 8]);
        float4 qb = *reinterpret_cast<float4*>(&Qs[c][wg * 8 + 4]);
        float4 ka = *reinterpret_cast<float4*>(&Ks[c][gg * 8]);
        float4 kb = *reinterpret_cast<float4*>(&Ks[c][gg * 8 + 4]);
        float qv[8] = {qa.x, qa.y, qa.z, qa.w, qb.x, qb.y, qb.z, qb.w};
        float kv[8] = {ka.x, ka.y, ka.z, ka.w, kb.x, kb.y, kb.z, kb.w};
#pragma unroll
        for (int i = 0; i < 8; ++i)
#pragma unroll
            for (int j = 0; j < 8; ++j) acc[i][j] += qv[i] * kv[j];
    }
#pragma unroll
    for (int i = 0; i < 8; ++i) {
        const int w = wg * 8 + i;
        float* row = aW + (((size_t)b * HH + h) * WW + w) * 256 + gc + gg * 8;
        *reinterpret_cast<float4*>(row)     = make_float4(acc[i][0], acc[i][1], acc[i][2], acc[i][3]);
        *reinterpret_cast<float4*>(row + 4) = make_float4(acc[i][4], acc[i][5], acc[i][6], acc[i][7]);
    }
}

// ---------------- fast exp (FMA/ALU pipes only, no MUFU) ----------------
__device__ __forceinline__ float fexp(float x) {
    x = fmaxf(x, -80.f);
    const float y = x * 1.44269504f;
    const int e = __float2int_rn(y);
    const float f = y - (float)e;
    float p = 0.00133335581f;
    p = fmaf(p, f, 0.00961812910f);
    p = fmaf(p, f, 0.0555041086f);
    p = fmaf(p, f, 0.240226507f);
    p = fmaf(p, f, 0.693147182f);
    p = fmaf(p, f, 1.0f);
    return p * __int_as_float((e + 127) << 23);
}

// ---------------- softmax: read fp32 scores, write fp16 weights ----------------
union H4pack { __half2 h2[2]; uint2 u; };

__global__ void softmax_kernel(const float* __restrict__ aH, const float* __restrict__ aW,
                               __half* __restrict__ aHh, __half* __restrict__ aWh) {
    const int row = blockIdx.x * 8 + (threadIdx.x >> 5);
    const int lane = threadIdx.x & 31;
    const float4* ph = reinterpret_cast<const float4*>(aH) + (size_t)row * 32;
    const float4* pw = reinterpret_cast<const float4*>(aW) + (size_t)row * 64;
    float4 vh  = ph[lane];
    float4 vw0 = pw[lane];
    float4 vw1 = pw[lane + 32];
    float m = fmaxf(fmaxf(fmaxf(vh.x, vh.y), fmaxf(vh.z, vh.w)),
              fmaxf(fmaxf(fmaxf(vw0.x, vw0.y), fmaxf(vw0.z, vw0.w)),
                    fmaxf(fmaxf(fmaxf(vw1.x, vw1.y), fmaxf(vw1.z, vw1.w)), -1e30f)));
#pragma unroll
    for (int o = 16; o; o >>= 1) m = fmaxf(m, __shfl_xor_sync(0xffffffffu, m, o));
    vh.x = fexp(vh.x - m); vh.y = fexp(vh.y - m); vh.z = fexp(vh.z - m); vh.w = fexp(vh.w - m);
    vw0.x = fexp(vw0.x - m); vw0.y = fexp(vw0.y - m); vw0.z = fexp(vw0.z - m); vw0.w = fexp(vw0.w - m);
    vw1.x = fexp(vw1.x - m); vw1.y = fexp(vw1.y - m); vw1.z = fexp(vw1.z - m); vw1.w = fexp(vw1.w - m);
    float s = vh.x + vh.y + vh.z + vh.w + vw0.x + vw0.y + vw0.z + vw0.w + vw1.x + vw1.y + vw1.z + vw1.w;
#pragma unroll
    for (int o = 16; o; o >>= 1) s += __shfl_xor_sync(0xffffffffu, s, o);
    const float inv = 1.f / s;
    H4pack p0, p1, p2;
    p0.h2[0] = __floats2half2_rn(vh.x * inv, vh.y * inv);
    p0.h2[1] = __floats2half2_rn(vh.z * inv, vh.w * inv);
    p1.h2[0] = __floats2half2_rn(vw0.x * inv, vw0.y * inv);
    p1.h2[1] = __floats2half2_rn(vw0.z * inv, vw0.w * inv);
    p2.h2[0] = __floats2half2_rn(vw1.x * inv, vw1.y * inv);
    p2.h2[1] = __floats2half2_rn(vw1.z * inv, vw1.w * inv);
    reinterpret_cast<uint2*>(aHh)[(size_t)row * 32 + lane] = p0.u;
    uint2* pwh = reinterpret_cast<uint2*>(aWh) + (size_t)row * 64;
    pwh[lane] = p1.u;
    pwh[lane + 32] = p2.u;
}

// ---------------- oH: per (b,w): O[d,h] = sum_g v[g,d]*aHh[h,g]; out [b][h][w][d] ----------------
__global__ void oH_kernel(const float* __restrict__ vt, const __half* __restrict__ aHh,
                          float* __restrict__ oht) {
    const int hh = blockIdx.x * 64;
    const int w = blockIdx.y, b = blockIdx.z;
    const int tid = threadIdx.x;
    const int dg = tid & 15, hg = tid >> 4;
    __shared__ float Vs[64][64];
    __shared__ float As[64][68];
    float acc[4][4];
#pragma unroll
    for (int i = 0; i < 4; ++i)
#pragma unroll
        for (int j = 0; j < 4; ++j) acc[i][j] = 0.f;
    for (int gc = 0; gc < 128; gc += 64) {
        for (int i = tid; i < 4096; i += 256) {
            const int g = i >> 6, d = i & 63;
            Vs[g][d] = vt[(((size_t)b * HH + gc + g) * WW + w) * 64 + d];
        }
        for (int i = tid; i < 2048; i += 256) {
            const int h = i >> 5, g2 = i & 31;
            const __half2 v2 = *reinterpret_cast<const __half2*>(
                aHh + (((size_t)b * HH + hh + h) * WW + w) * 128 + gc + g2 * 2);
            const float2 f = __half22float2(v2);
            As[g2 * 2][h] = f.x;
            As[g2 * 2 + 1][h] = f.y;
        }
        __syncthreads();
#pragma unroll 8
        for (int g = 0; g < 64; ++g) {
            float4 vv = *reinterpret_cast<float4*>(&Vs[g][dg * 4]);
            float4 aa = *reinterpret_cast<float4*>(&As[g][hg * 4]);
            float vd[4] = {vv.x, vv.y, vv.z, vv.w};
            float ah[4] = {aa.x, aa.y, aa.z, aa.w};
#pragma unroll
            for (int di = 0; di < 4; ++di)
#pragma unroll
                for (int hj = 0; hj < 4; ++hj) acc[di][hj] += vd[di] * ah[hj];
        }
        __syncthreads();
    }
#pragma unroll
    for (int j = 0; j < 4; ++j) {
        const int h = hh + hg * 4 + j;
        *reinterpret_cast<float4*>(&oht[(((size_t)b * HH + h) * WW + w) * 64 + dg * 4]) =
            make_float4(acc[0][j], acc[1][j], acc[2][j], acc[3][j]);
    }
}

// ---------------- oW + combine: out = gamma*(oH+oW) + x ----------------
__global__ void oW_combine_kernel(const float* __restrict__ vt, const __half* __restrict__ aWh,
                                  const float* __restrict__ oht, const float* __restrict__ x,
                                  const float* __restrict__ gamma, float* __restrict__ xout) {
    const int wt = blockIdx.x * 64;
    const int h = blockIdx.y, b = blockIdx.z;
    const int tid = threadIdx.x;
    const int dg = tid & 15, wg = tid >> 4;
    __shared__ float Vs[64][64];
    __shared__ float As[64][68];
    float acc[4][4];
#pragma unroll
    for (int i = 0; i < 4; ++i)
#pragma unroll
        for (int j = 0; j < 4; ++j) acc[i][j] = 0.f;
    for (int gc = 0; gc < 256; gc += 64) {
        const float* vbase = vt + (((size_t)b * HH + h) * WW + gc) * 64;
        for (int i = tid; i < 4096; i += 256) Vs[i >> 6][i & 63] = vbase[i];
        for (int i = tid; i < 2048; i += 256) {
            const int ww = i >> 5, g2 = i & 31;
            const __half2 v2 = *reinterpret_cast<const __half2*>(
                aWh + (((size_t)b * HH + h) * WW + wt + ww) * 256 + gc + g2 * 2);
            const float2 f = __half22float2(v2);
            As[g2 * 2][ww] = f.x;
            As[g2 * 2 + 1][ww] = f.y;
        }
        __syncthreads();
#pragma unroll 8
        for (int g = 0; g < 64; ++g) {
            float4 vv = *reinterpret_cast<float4*>(&Vs[g][dg * 4]);
            float4 aa = *reinterpret_cast<float4*>(&As[g][wg * 4]);
            float vd[4] = {vv.x, vv.y, vv.z, vv.w};
            float aw4[4] = {aa.x, aa.y, aa.z, aa.w};
#pragma unroll
            for (int di = 0; di < 4; ++di)
#pragma unroll
                for (int wj = 0; wj < 4; ++wj) acc[di][wj] += vd[di] * aw4[wj];
        }
        __syncthreads();
    }
    const float gam = *gamma;
#pragma unroll
    for (int di = 0; di < 4; ++di) {
        const int d = dg * 4 + di;
        const size_t xoff = ((size_t)(b * 64 + d)) * HW_ + (size_t)h * WW + wt + wg * 4;
        float4 xr = *reinterpret_cast<const float4*>(x + xoff);
        float o[4];
#pragma unroll
        for (int wj = 0; wj < 4; ++wj)
            o[wj] = oht[(((size_t)b * HH + h) * WW + wt + wg * 4 + wj) * 64 + d];
        float4 r;
        r.x = gam * (acc[di][0] + o[0]) + xr.x;
        r.y = gam * (acc[di][1] + o[1]) + xr.y;
        r.z = gam * (acc[di][2] + o[2]) + xr.z;
        r.w = gam * (acc[di][3] + o[3]) + xr.w;
        *reinterpret_cast<float4*>(xout + xoff) = r;
    }
}

// ---------------- host ----------------
extern "C" void kernel_launch(void* const* d_in, const int* in_sizes, int n_in,
                              void* d_out, int out_size) {
    const float* cost  = (const float*)d_in[0];
    const float* lf0   = (const float*)d_in[1];
    const float* lf1   = (const float*)d_in[2];
    const float* Wa    = (const float*)d_in[3];
    const float* bn_ag = (const float*)d_in[4];
    const float* bn_ab = (const float*)d_in[5];
    const float* Wq    = (const float*)d_in[6];
    const float* bq    = (const float*)d_in[7];
    const float* Wk    = (const float*)d_in[8];
    const float* bk    = (const float*)d_in[9];
    const float* Wv    = (const float*)d_in[10];
    const float* bv    = (const float*)d_in[11];
    const float* gamma = (const float*)d_in[12];
    const float* Wb    = (const float*)d_in[13];
    const float* bn_bg = (const float*)d_in[14];
    const float* bn_bb = (const float*)d_in[15];
    float* out = (float*)d_out;

    float *conv, *xA, *xB, *vt, *oht, *qt, *kt, *aH, *aW, *wtb;
    __half *aHh, *aWh;
    float2 *part, *stats;
    cudaGetSymbolAddress((void**)&conv, g_conv);
    cudaGetSymbolAddress((void**)&xA, g_xA);
    cudaGetSymbolAddress((void**)&xB, g_xB);
    cudaGetSymbolAddress((void**)&vt, g_vt);
    cudaGetSymbolAddress((void**)&oht, g_oht);
    cudaGetSymbolAddress((void**)&qt, g_qt);
    cudaGetSymbolAddress((void**)&kt, g_kt);
    cudaGetSymbolAddress((void**)&aH, g_aH);
    cudaGetSymbolAddress((void**)&aW, g_aW);
    cudaGetSymbolAddress((void**)&aHh, g_aHh);
    cudaGetSymbolAddress((void**)&aWh, g_aWh);
    cudaGetSymbolAddress((void**)&wtb, g_wt);
    cudaGetSymbolAddress((void**)&part, g_part);
    cudaGetSymbolAddress((void**)&stats, g_stats);

    // Idempotent, called unconditionally (no static guards — harness rule).
    cudaFuncSetAttribute(conv3x3_mma_kernel,
                         cudaFuncAttributeMaxDynamicSharedMemorySize, CONV_SMEM);

    // Stage B first (independent of stage A): attention maps, computed once
    conv1x1_c32_kernel<<<512, 256>>>(lf0, Wq, bq, qt);
    conv1x1_c32_kernel<<<512, 256>>>(lf1, Wk, bk, kt);
    eH_kernel<<<dim3(256, 4), 256>>>(qt, kt, aH);
    eW_kernel<<<dim3(4, 128, 4), 256>>>(qt, kt, aW);
    softmax_kernel<<<16384, 256>>>(aH, aW, aHh, aWh);

    // Stage A: conv3x3(cost, Wa) + BN -> xA
    wtrans_kernel<<<144, 256>>>(Wa, wtb);
    conv3x3_mma_kernel<<<dim3(4, 64, 4), 256, CONV_SMEM>>>(cost, wtb, conv);
    bn_reduce_kernel<<<dim3(64, 8), 256>>>(conv, part);
    bn_finalize_kernel<<<1, 64>>>(part, stats);
    bn_apply_kernel<<<8192, 256>>>(conv, stats, bn_ag, bn_ab, xA);

    // Stage C: 2 recurrence iterations
    float* cur = xA;
    float* nxt = xB;
    for (int it = 0; it < 2; ++it) {
        conv1x1_d64_kernel<<<512, 256>>>(cur, Wv, bv, vt);
        oH_kernel<<<dim3(2, 256, 4), 256>>>(vt, aHh, oht);
        oW_combine_kernel<<<dim3(4, 128, 4), 256>>>(vt, aWh, oht, cur, gamma, nxt);
        float* t = cur; cur = nxt; nxt = t;
    }

    // Stage D: conv3x3(cur, Wb) + BN -> out
    wtrans_kernel<<<144, 256>>>(Wb, wtb);
    conv3x3_mma_kernel<<<dim3(4, 64, 4), 256, CONV_SMEM>>>(cur, wtb, conv);
    bn_reduce_kernel<<<dim3(64, 8), 256>>>(conv, part);
    bn_finalize_kernel<<<1, 64>>>(part, stats);
    bn_apply_kernel<<<8192, 256>>>(conv, stats, bn_bg, bn_bb, out);
}

// round 6
// speedup vs baseline: 1.7413x; 1.0710x over previous
#include <cuda_runtime.h>
#include <cuda_fp16.h>
#include <cstdint>
#include <cstddef>

#define BB 4
#define CC 32
#define DD 64
#define HH 128
#define WW 256
#define HW_ (HH*WW)          // 32768
#define BDHW_ (BB*DD*HW_)    // 8388608
#define BCHW_ (BB*CC*HW_)    // 4194304

// ---------------- scratch (static device globals; no allocation) ----------------
__device__ float g_conv[BDHW_];
__device__ float g_xA[BDHW_];
__device__ float g_xB[BDHW_];
__device__ float g_vt[BDHW_];        // v in [b][h][w][d] layout
__device__ float g_oht[BDHW_];       // oH in [b][h][w][d] layout
__device__ float g_qt[BCHW_];        // q in [b][h][w][c]
__device__ float g_kt[BCHW_];        // k in [b][h][w][c]
__device__ __half g_aHs[BB*HH*WW*HH];  // fp16 scores (H part)
__device__ __half g_aWs[BB*HH*WW*WW];  // fp16 scores (W part)
__device__ __half g_aHh[BB*HH*WW*HH];  // fp16 normalized weights
__device__ __half g_aWh[BB*HH*WW*WW];
__device__ float g_wt[9*64*64];      // transposed tf32 conv weights [t][c][d]
__device__ float2 g_part[64*8];
__device__ float2 g_stats[64];

// ---------------- weight transform: W[d][c][3][3] -> wt[t][c][d], tf32-rounded ----------------
__global__ void wtrans_kernel(const float* __restrict__ W, float* __restrict__ wt) {
    const int i = blockIdx.x * 256 + threadIdx.x;
    if (i >= 9 * 64 * 64) return;
    const int t = i >> 12;
    const int rem = i & 4095;
    const int c = rem >> 6;
    const int d = rem & 63;
    float v = W[(((d << 6) + c) * 9) + t];
    uint32_t uv;
    asm("cvt.rna.tf32.f32 %0, %1;" : "=r"(uv) : "f"(v));
    wt[i] = __uint_as_float(uv);
}

// ---------------- conv3x3 via tf32 mma.sync, 2 h-rows per block ----------------
// grid (W/64, H/2, B), 256 threads (8 warps). Tile: 64 d x 64 w x 2 h.
#define XS_RSTRIDE 68
#define XS_CSTRIDE 280          // 4*68 + 8 pad; 280 % 32 = 24 -> conflict-free B frags
#define XS_FLOATS (64*280)      // 17920
#define WS_STRIDE 72
#define WS_FLOATS (64*72)       // 4608
#define CONV_SMEM ((XS_FLOATS + WS_FLOATS) * 4)   // 90112 bytes

__device__ __forceinline__ void mma_tf32(float* c, uint32_t a0, uint32_t a1, uint32_t a2, uint32_t a3,
                                         uint32_t b0, uint32_t b1) {
    asm volatile("mma.sync.aligned.m16n8k8.row.col.f32.tf32.tf32.f32 "
                 "{%0,%1,%2,%3}, {%4,%5,%6,%7}, {%8,%9}, {%0,%1,%2,%3};"
                 : "+f"(c[0]), "+f"(c[1]), "+f"(c[2]), "+f"(c[3])
                 : "r"(a0), "r"(a1), "r"(a2), "r"(a3), "r"(b0), "r"(b1));
}

__global__ void conv3x3_mma_kernel(const float* __restrict__ x, const float* __restrict__ wt,
                                   float* __restrict__ y) {
    extern __shared__ float smem[];
    float* xs = smem;                 // [c][280] : 4 rows of 68 (+pad)
    float* ws = smem + XS_FLOATS;     // [c][72]

    const int w0 = blockIdx.x * 64;
    const int h0 = blockIdx.y * 2;
    const int b  = blockIdx.z;
    const int tid = threadIdx.x;
    const int lane = tid & 31;
    const int warp = tid >> 5;
    const int hsel = warp >> 2;       // 0/1 -> output row h0+hsel
    const int d0 = (warp & 3) * 16;
    const int q4 = lane & 3;
    const int g8 = lane >> 2;

    // input tile: c in [0,64), rows h0-1..h0+2, cols w0-1..w0+64, tf32-rounded
    for (int i = tid; i < 64 * 4 * 66; i += 256) {
        const int c = i / 264;
        const int rem = i - c * 264;
        const int r = rem / 66;
        const int col = rem - r * 66;
        const int gh = h0 + r - 1;
        const int gw = w0 + col - 1;
        float v = 0.f;
        if (gh >= 0 && gh < HH && gw >= 0 && gw < WW)
            v = x[((size_t)(b * 64 + c)) * HW_ + gh * WW + gw];
        uint32_t uv;
        asm("cvt.rna.tf32.f32 %0, %1;" : "=r"(uv) : "f"(v));
        xs[c * XS_CSTRIDE + r * XS_RSTRIDE + col] = __uint_as_float(uv);
    }

    float acc[8][4];
#pragma unroll
    for (int j = 0; j < 8; ++j)
#pragma unroll
        for (int k = 0; k < 4; ++k) acc[j][k] = 0.f;

    for (int t = 0; t < 9; ++t) {
        __syncthreads();
        const float* wp = wt + t * 4096;
        for (int i = tid; i < 4096; i += 256)
            ws[(i >> 6) * WS_STRIDE + (i & 63)] = wp[i];
        __syncthreads();

        const int dh = t / 3;
        const int dw = t - dh * 3;
#pragma unroll
        for (int ck = 0; ck < 8; ++ck) {
            const int c0 = ck * 8;
            const float* wr0 = ws + (c0 + q4) * WS_STRIDE + d0 + g8;
            const float* wr1 = wr0 + 4 * WS_STRIDE;
            const uint32_t a0 = __float_as_uint(wr0[0]);
            const uint32_t a1 = __float_as_uint(wr0[8]);
            const uint32_t a2 = __float_as_uint(wr1[0]);
            const uint32_t a3 = __float_as_uint(wr1[8]);
            const float* xb0 = xs + (c0 + q4) * XS_CSTRIDE + (hsel + dh) * XS_RSTRIDE + dw + g8;
            const float* xb1 = xb0 + 4 * XS_CSTRIDE;
#pragma unroll
            for (int j = 0; j < 8; ++j) {
                const uint32_t b0 = __float_as_uint(xb0[j * 8]);
                const uint32_t b1 = __float_as_uint(xb1[j * 8]);
                mma_tf32(acc[j], a0, a1, a2, a3, b0, b1);
            }
        }
    }

    const int h = h0 + hsel;
#pragma unroll
    for (int j = 0; j < 8; ++j) {
        const int w = w0 + j * 8 + 2 * q4;
        const size_t base = ((size_t)(b * 64 + d0 + g8)) * HW_ + (size_t)h * WW + w;
        *reinterpret_cast<float2*>(y + base) = make_float2(acc[j][0], acc[j][1]);
        *reinterpret_cast<float2*>(y + base + (size_t)8 * HW_) = make_float2(acc[j][2], acc[j][3]);
    }
}

// ---------------- batchnorm: partial reduce / finalize / apply ----------------
__global__ void bn_reduce_kernel(const float* __restrict__ x, float2* __restrict__ part) {
    const int c = blockIdx.x, p = blockIdx.y;
    float s = 0.f, s2 = 0.f;
    const int base = p * 16384;
    for (int j = threadIdx.x; j < 16384; j += 256) {
        const int f = base + j;
        const int b = f >> 15;
        const int i = f & 32767;
        const float v = x[((size_t)(b * 64 + c)) * HW_ + i];
        s += v; s2 += v * v;
    }
    __shared__ float rs[8], rs2[8];
#pragma unroll
    for (int o = 16; o; o >>= 1) {
        s  += __shfl_xor_sync(0xffffffffu, s, o);
        s2 += __shfl_xor_sync(0xffffffffu, s2, o);
    }
    if ((threadIdx.x & 31) == 0) { rs[threadIdx.x >> 5] = s; rs2[threadIdx.x >> 5] = s2; }
    __syncthreads();
    if (threadIdx.x == 0) {
        float a = 0.f, b2 = 0.f;
        for (int k = 0; k < 8; ++k) { a += rs[k]; b2 += rs2[k]; }
        part[c * 8 + p] = make_float2(a, b2);
    }
}

__global__ void bn_finalize_kernel(const float2* __restrict__ part, float2* __restrict__ stats) {
    const int c = threadIdx.x;
    float s = 0.f, s2 = 0.f;
    for (int p = 0; p < 8; ++p) { s += part[c * 8 + p].x; s2 += part[c * 8 + p].y; }
    const float inv_n = 1.f / 131072.f;
    const float mean = s * inv_n;
    const float var  = s2 * inv_n - mean * mean;
    stats[c] = make_float2(mean, rsqrtf(var + 1e-5f));
}

__global__ void bn_apply_kernel(const float* __restrict__ x, const float2* __restrict__ stats,
                                const float* __restrict__ gam, const float* __restrict__ bet,
                                float* __restrict__ y) {
    const int idx = blockIdx.x * 256 + threadIdx.x;
    const int e = idx * 4;
    const int c = (e / HW_) & 63;
    const float2 st = stats[c];
    const float g = gam[c], be = bet[c];
    float4 v = reinterpret_cast<const float4*>(x)[idx];
    v.x = (v.x - st.x) * st.y * g + be;
    v.y = (v.y - st.x) * st.y * g + be;
    v.z = (v.z - st.x) * st.y * g + be;
    v.w = (v.w - st.x) * st.y * g + be;
    reinterpret_cast<float4*>(y)[idx] = v;
}

// ---------------- 1x1 convs, writing channel-last ----------------
__global__ void conv1x1_c32_kernel(const float* __restrict__ x, const float* __restrict__ wgt,
                                   const float* __restrict__ bias, float* __restrict__ yt) {
    __shared__ float sw[32][33];
    __shared__ float sb[32];
    const int tid = threadIdx.x;
    for (int i = tid; i < 1024; i += 256) sw[i >> 5][i & 31] = wgt[i];
    if (tid < 32) sb[tid] = bias[tid];
    __syncthreads();
    const int pos = blockIdx.x * 256 + tid;
    const int b = pos >> 15, i = pos & 32767;
    float xin[32];
#pragma unroll
    for (int ci = 0; ci < 32; ++ci) xin[ci] = x[((size_t)(b * 32 + ci)) * HW_ + i];
    float* out = yt + (size_t)pos * 32;
#pragma unroll
    for (int co = 0; co < 32; co += 4) {
        float4 a = make_float4(sb[co], sb[co + 1], sb[co + 2], sb[co + 3]);
#pragma unroll
        for (int ci = 0; ci < 32; ++ci) {
            const float xv = xin[ci];
            a.x += sw[co][ci] * xv; a.y += sw[co + 1][ci] * xv;
            a.z += sw[co + 2][ci] * xv; a.w += sw[co + 3][ci] * xv;
        }
        *reinterpret_cast<float4*>(out + co) = a;
    }
}

__global__ void conv1x1_d64_kernel(const float* __restrict__ x, const float* __restrict__ wgt,
                                   const float* __restrict__ bias, float* __restrict__ vt) {
    __shared__ float sw[64][65];
    __shared__ float sb[64];
    const int tid = threadIdx.x;
    for (int i = tid; i < 4096; i += 256) sw[i >> 6][i & 63] = wgt[i];
    if (tid < 64) sb[tid] = bias[tid];
    __syncthreads();
    const int pos = blockIdx.x * 256 + tid;
    const int b = pos >> 15, i = pos & 32767;
    float xin[64];
#pragma unroll
    for (int ci = 0; ci < 64; ++ci) xin[ci] = x[((size_t)(b * 64 + ci)) * HW_ + i];
    float* out = vt + (size_t)pos * 64;
#pragma unroll
    for (int co = 0; co < 64; co += 4) {
        float4 a = make_float4(sb[co], sb[co + 1], sb[co + 2], sb[co + 3]);
#pragma unroll
        for (int ci = 0; ci < 64; ++ci) {
            const float xv = xin[ci];
            a.x += sw[co][ci] * xv; a.y += sw[co + 1][ci] * xv;
            a.z += sw[co + 2][ci] * xv; a.w += sw[co + 3][ci] * xv;
        }
        *reinterpret_cast<float4*>(out + co) = a;
    }
}

// ---------------- half-pack helpers ----------------
union H8pack { __half2 h2[4]; uint4 u; };

// ---------------- eH: scores -> fp16, diag=-inf ----------------
__global__ void eH_kernel(const float* __restrict__ qt, const float* __restrict__ kt,
                          __half* __restrict__ aHs) {
    const int w = blockIdx.x, b = blockIdx.y;
    const int tid = threadIdx.x;
    __shared__ float Qs[32][132];
    __shared__ float Ks[32][132];
    for (int i = tid; i < 4096; i += 256) {
        const int h = i >> 5, c = i & 31;
        const size_t gidx = (((size_t)b * HH + h) * WW + w) * 32 + c;
        Qs[c][h] = qt[gidx];
        Ks[c][h] = kt[gidx];
    }
    __syncthreads();
    const int hg = tid >> 4, gg = tid & 15;
    float acc[8][8];
#pragma unroll
    for (int i = 0; i < 8; ++i)
#pragma unroll
        for (int j = 0; j < 8; ++j) acc[i][j] = 0.f;
    for (int c = 0; c < 32; ++c) {
        float4 qa = *reinterpret_cast<float4*>(&Qs[c][hg * 8]);
        float4 qb = *reinterpret_cast<float4*>(&Qs[c][hg * 8 + 4]);
        float4 ka = *reinterpret_cast<float4*>(&Ks[c][gg * 8]);
        float4 kb = *reinterpret_cast<float4*>(&Ks[c][gg * 8 + 4]);
        float qv[8] = {qa.x, qa.y, qa.z, qa.w, qb.x, qb.y, qb.z, qb.w};
        float kv[8] = {ka.x, ka.y, ka.z, ka.w, kb.x, kb.y, kb.z, kb.w};
#pragma unroll
        for (int i = 0; i < 8; ++i)
#pragma unroll
            for (int j = 0; j < 8; ++j) acc[i][j] += qv[i] * kv[j];
    }
    const float ninf = __int_as_float(0xff800000);
#pragma unroll
    for (int i = 0; i < 8; ++i) {
        const int h = hg * 8 + i;
#pragma unroll
        for (int j = 0; j < 8; ++j) {
            const int g = gg * 8 + j;
            if (h == g) acc[i][j] = ninf;
        }
        H8pack p;
#pragma unroll
        for (int j = 0; j < 4; ++j)
            p.h2[j] = __floats2half2_rn(acc[i][2 * j], acc[i][2 * j + 1]);
        *reinterpret_cast<uint4*>(aHs + (((size_t)b * HH + h) * WW + w) * 128 + gg * 8) = p.u;
    }
}

// ---------------- eW: scores -> fp16 ----------------
__global__ void eW_kernel(const float* __restrict__ qt, const float* __restrict__ kt,
                          __half* __restrict__ aWs) {
    const int gc = blockIdx.x * 64;
    const int h = blockIdx.y, b = blockIdx.z;
    const int tid = threadIdx.x;
    __shared__ float Qs[32][260];
    __shared__ float Ks[32][68];
    const float* qbase = qt + (((size_t)b * HH + h) * WW) * 32;
    for (int i = tid; i < 8192; i += 256) { Qs[i & 31][i >> 5] = qbase[i]; }
    const float* kbase = kt + (((size_t)b * HH + h) * WW + gc) * 32;
    for (int i = tid; i < 2048; i += 256) { Ks[i & 31][i >> 5] = kbase[i]; }
    __syncthreads();
    const int wg = tid >> 3, gg = tid & 7;
    float acc[8][8];
#pragma unroll
    for (int i = 0; i < 8; ++i)
#pragma unroll
        for (int j = 0; j < 8; ++j) acc[i][j] = 0.f;
    for (int c = 0; c < 32; ++c) {
        float4 qa = *reinterpret_cast<float4*>(&Qs[c][wg * 8]);
        float4 qb = *reinterpret_cast<float4*>(&Qs[c][wg * 8 + 4]);
        float4 ka = *reinterpret_cast<float4*>(&Ks[c][gg * 8]);
        float4 kb = *reinterpret_cast<float4*>(&Ks[c][gg * 8 + 4]);
        float qv[8] = {qa.x, qa.y, qa.z, qa.w, qb.x, qb.y, qb.z, qb.w};
        float kv[8] = {ka.x, ka.y, ka.z, ka.w, kb.x, kb.y, kb.z, kb.w};
#pragma unroll
        for (int i = 0; i < 8; ++i)
#pragma unroll
            for (int j = 0; j < 8; ++j) acc[i][j] += qv[i] * kv[j];
    }
#pragma unroll
    for (int i = 0; i < 8; ++i) {
        const int w = wg * 8 + i;
        H8pack p;
#pragma unroll
        for (int j = 0; j < 4; ++j)
            p.h2[j] = __floats2half2_rn(acc[i][2 * j], acc[i][2 * j + 1]);
        *reinterpret_cast<uint4*>(aWs + (((size_t)b * HH + h) * WW + w) * 256 + gc + gg * 8) = p.u;
    }
}

// ---------------- fast exp (FMA/ALU pipes only, no MUFU) ----------------
__device__ __forceinline__ float fexp(float x) {
    x = fmaxf(x, -80.f);
    const float y = x * 1.44269504f;
    const int e = __float2int_rn(y);
    const float f = y - (float)e;
    float p = 0.00133335581f;
    p = fmaf(p, f, 0.00961812910f);
    p = fmaf(p, f, 0.0555041086f);
    p = fmaf(p, f, 0.240226507f);
    p = fmaf(p, f, 0.693147182f);
    p = fmaf(p, f, 1.0f);
    return p * __int_as_float((e + 127) << 23);
}

// ---------------- softmax: fp16 scores in, fp16 weights out ----------------
union H4pack { __half2 h2[2]; uint2 u; };

__global__ void softmax_kernel(const __half* __restrict__ aHs, const __half* __restrict__ aWs,
                               __half* __restrict__ aHh, __half* __restrict__ aWh) {
    const int row = blockIdx.x * 8 + (threadIdx.x >> 5);
    const int lane = threadIdx.x & 31;
    const uint2* ph = reinterpret_cast<const uint2*>(aHs) + (size_t)row * 32;
    const uint2* pw = reinterpret_cast<const uint2*>(aWs) + (size_t)row * 64;
    H4pack ih, iw0, iw1;
    ih.u = ph[lane];
    iw0.u = pw[lane];
    iw1.u = pw[lane + 32];
    float2 h01 = __half22float2(ih.h2[0]);
    float2 h23 = __half22float2(ih.h2[1]);
    float2 w01 = __half22float2(iw0.h2[0]);
    float2 w23 = __half22float2(iw0.h2[1]);
    float2 w45 = __half22float2(iw1.h2[0]);
    float2 w67 = __half22float2(iw1.h2[1]);
    float4 vh  = make_float4(h01.x, h01.y, h23.x, h23.y);
    float4 vw0 = make_float4(w01.x, w01.y, w23.x, w23.y);
    float4 vw1 = make_float4(w45.x, w45.y, w67.x, w67.y);
    float m = fmaxf(fmaxf(fmaxf(vh.x, vh.y), fmaxf(vh.z, vh.w)),
              fmaxf(fmaxf(fmaxf(vw0.x, vw0.y), fmaxf(vw0.z, vw0.w)),
                    fmaxf(fmaxf(fmaxf(vw1.x, vw1.y), fmaxf(vw1.z, vw1.w)), -1e30f)));
#pragma unroll
    for (int o = 16; o; o >>= 1) m = fmaxf(m, __shfl_xor_sync(0xffffffffu, m, o));
    vh.x = fexp(vh.x - m); vh.y = fexp(vh.y - m); vh.z = fexp(vh.z - m); vh.w = fexp(vh.w - m);
    vw0.x = fexp(vw0.x - m); vw0.y = fexp(vw0.y - m); vw0.z = fexp(vw0.z - m); vw0.w = fexp(vw0.w - m);
    vw1.x = fexp(vw1.x - m); vw1.y = fexp(vw1.y - m); vw1.z = fexp(vw1.z - m); vw1.w = fexp(vw1.w - m);
    float s = vh.x + vh.y + vh.z + vh.w + vw0.x + vw0.y + vw0.z + vw0.w + vw1.x + vw1.y + vw1.z + vw1.w;
#pragma unroll
    for (int o = 16; o; o >>= 1) s += __shfl_xor_sync(0xffffffffu, s, o);
    const float inv = 1.f / s;
    H4pack p0, p1, p2;
    p0.h2[0] = __floats2half2_rn(vh.x * inv, vh.y * inv);
    p0.h2[1] = __floats2half2_rn(vh.z * inv, vh.w * inv);
    p1.h2[0] = __floats2half2_rn(vw0.x * inv, vw0.y * inv);
    p1.h2[1] = __floats2half2_rn(vw0.z * inv, vw0.w * inv);
    p2.h2[0] = __floats2half2_rn(vw1.x * inv, vw1.y * inv);
    p2.h2[1] = __floats2half2_rn(vw1.z * inv, vw1.w * inv);
    reinterpret_cast<uint2*>(aHh)[(size_t)row * 32 + lane] = p0.u;
    uint2* pwh = reinterpret_cast<uint2*>(aWh) + (size_t)row * 64;
    pwh[lane] = p1.u;
    pwh[lane + 32] = p2.u;
}

// ---------------- oH: per (b,w): O[d,h] = sum_g v[g,d]*aHh[h,g]; out [b][h][w][d] ----------------
__global__ void oH_kernel(const float* __restrict__ vt, const __half* __restrict__ aHh,
                          float* __restrict__ oht) {
    const int hh = blockIdx.x * 64;
    const int w = blockIdx.y, b = blockIdx.z;
    const int tid = threadIdx.x;
    const int dg = tid & 15, hg = tid >> 4;
    __shared__ float Vs[64][64];
    __shared__ float As[64][68];
    float acc[4][4];
#pragma unroll
    for (int i = 0; i < 4; ++i)
#pragma unroll
        for (int j = 0; j < 4; ++j) acc[i][j] = 0.f;
    for (int gc = 0; gc < 128; gc += 64) {
        for (int i = tid; i < 4096; i += 256) {
            const int g = i >> 6, d = i & 63;
            Vs[g][d] = vt[(((size_t)b * HH + gc + g) * WW + w) * 64 + d];
        }
        for (int i = tid; i < 2048; i += 256) {
            const int h = i >> 5, g2 = i & 31;
            const __half2 v2 = *reinterpret_cast<const __half2*>(
                aHh + (((size_t)b * HH + hh + h) * WW + w) * 128 + gc + g2 * 2);
            const float2 f = __half22float2(v2);
            As[g2 * 2][h] = f.x;
            As[g2 * 2 + 1][h] = f.y;
        }
        __syncthreads();
#pragma unroll 8
        for (int g = 0; g < 64; ++g) {
            float4 vv = *reinterpret_cast<float4*>(&Vs[g][dg * 4]);
            float4 aa = *reinterpret_cast<float4*>(&As[g][hg * 4]);
            float vd[4] = {vv.x, vv.y, vv.z, vv.w};
            float ah[4] = {aa.x, aa.y, aa.z, aa.w};
#pragma unroll
            for (int di = 0; di < 4; ++di)
#pragma unroll
                for (int hj = 0; hj < 4; ++hj) acc[di][hj] += vd[di] * ah[hj];
        }
        __syncthreads();
    }
#pragma unroll
    for (int j = 0; j < 4; ++j) {
        const int h = hh + hg * 4 + j;
        *reinterpret_cast<float4*>(&oht[(((size_t)b * HH + h) * WW + w) * 64 + dg * 4]) =
            make_float4(acc[0][j], acc[1][j], acc[2][j], acc[3][j]);
    }
}

// ---------------- oW + combine: out = gamma*(oH+oW) + x ----------------
__global__ void oW_combine_kernel(const float* __restrict__ vt, const __half* __restrict__ aWh,
                                  const float* __restrict__ oht, const float* __restrict__ x,
                                  const float* __restrict__ gamma, float* __restrict__ xout) {
    const int wt = blockIdx.x * 64;
    const int h = blockIdx.y, b = blockIdx.z;
    const int tid = threadIdx.x;
    const int dg = tid & 15, wg = tid >> 4;
    __shared__ float Vs[64][64];
    __shared__ float As[64][68];
    float acc[4][4];
#pragma unroll
    for (int i = 0; i < 4; ++i)
#pragma unroll
        for (int j = 0; j < 4; ++j) acc[i][j] = 0.f;
    for (int gc = 0; gc < 256; gc += 64) {
        const float* vbase = vt + (((size_t)b * HH + h) * WW + gc) * 64;
        for (int i = tid; i < 4096; i += 256) Vs[i >> 6][i & 63] = vbase[i];
        for (int i = tid; i < 2048; i += 256) {
            const int ww = i >> 5, g2 = i & 31;
            const __half2 v2 = *reinterpret_cast<const __half2*>(
                aWh + (((size_t)b * HH + h) * WW + wt + ww) * 256 + gc + g2 * 2);
            const float2 f = __half22float2(v2);
            As[g2 * 2][ww] = f.x;
            As[g2 * 2 + 1][ww] = f.y;
        }
        __syncthreads();
#pragma unroll 8
        for (int g = 0; g < 64; ++g) {
            float4 vv = *reinterpret_cast<float4*>(&Vs[g][dg * 4]);
            float4 aa = *reinterpret_cast<float4*>(&As[g][wg * 4]);
            float vd[4] = {vv.x, vv.y, vv.z, vv.w};
            float aw4[4] = {aa.x, aa.y, aa.z, aa.w};
#pragma unroll
            for (int di = 0; di < 4; ++di)
#pragma unroll
                for (int wj = 0; wj < 4; ++wj) acc[di][wj] += vd[di] * aw4[wj];
        }
        __syncthreads();
    }
    const float gam = *gamma;
#pragma unroll
    for (int di = 0; di < 4; ++di) {
        const int d = dg * 4 + di;
        const size_t xoff = ((size_t)(b * 64 + d)) * HW_ + (size_t)h * WW + wt + wg * 4;
        float4 xr = *reinterpret_cast<const float4*>(x + xoff);
        float o[4];
#pragma unroll
        for (int wj = 0; wj < 4; ++wj)
            o[wj] = oht[(((size_t)b * HH + h) * WW + wt + wg * 4 + wj) * 64 + d];
        float4 r;
        r.x = gam * (acc[di][0] + o[0]) + xr.x;
        r.y = gam * (acc[di][1] + o[1]) + xr.y;
        r.z = gam * (acc[di][2] + o[2]) + xr.z;
        r.w = gam * (acc[di][3] + o[3]) + xr.w;
        *reinterpret_cast<float4*>(xout + xoff) = r;
    }
}

// ---------------- host ----------------
extern "C" void kernel_launch(void* const* d_in, const int* in_sizes, int n_in,
                              void* d_out, int out_size) {
    const float* cost  = (const float*)d_in[0];
    const float* lf0   = (const float*)d_in[1];
    const float* lf1   = (const float*)d_in[2];
    const float* Wa    = (const float*)d_in[3];
    const float* bn_ag = (const float*)d_in[4];
    const float* bn_ab = (const float*)d_in[5];
    const float* Wq    = (const float*)d_in[6];
    const float* bq    = (const float*)d_in[7];
    const float* Wk    = (const float*)d_in[8];
    const float* bk    = (const float*)d_in[9];
    const float* Wv    = (const float*)d_in[10];
    const float* bv    = (const float*)d_in[11];
    const float* gamma = (const float*)d_in[12];
    const float* Wb    = (const float*)d_in[13];
    const float* bn_bg = (const float*)d_in[14];
    const float* bn_bb = (const float*)d_in[15];
    float* out = (float*)d_out;

    float *conv, *xA, *xB, *vt, *oht, *qt, *kt, *wtb;
    __half *aHs, *aWs, *aHh, *aWh;
    float2 *part, *stats;
    cudaGetSymbolAddress((void**)&conv, g_conv);
    cudaGetSymbolAddress((void**)&xA, g_xA);
    cudaGetSymbolAddress((void**)&xB, g_xB);
    cudaGetSymbolAddress((void**)&vt, g_vt);
    cudaGetSymbolAddress((void**)&oht, g_oht);
    cudaGetSymbolAddress((void**)&qt, g_qt);
    cudaGetSymbolAddress((void**)&kt, g_kt);
    cudaGetSymbolAddress((void**)&aHs, g_aHs);
    cudaGetSymbolAddress((void**)&aWs, g_aWs);
    cudaGetSymbolAddress((void**)&aHh, g_aHh);
    cudaGetSymbolAddress((void**)&aWh, g_aWh);
    cudaGetSymbolAddress((void**)&wtb, g_wt);
    cudaGetSymbolAddress((void**)&part, g_part);
    cudaGetSymbolAddress((void**)&stats, g_stats);

    // Idempotent, called unconditionally (no static guards — harness rule).
    cudaFuncSetAttribute(conv3x3_mma_kernel,
                         cudaFuncAttributeMaxDynamicSharedMemorySize, CONV_SMEM);

    // Launch order puts conv3x3 at capture index 3 (ncu -s5 -c1 lands there).
    conv1x1_c32_kernel<<<512, 256>>>(lf0, Wq, bq, qt);           // 0
    conv1x1_c32_kernel<<<512, 256>>>(lf1, Wk, bk, kt);           // 1
    wtrans_kernel<<<144, 256>>>(Wa, wtb);                        // 2
    conv3x3_mma_kernel<<<dim3(4, 64, 4), 256, CONV_SMEM>>>(cost, wtb, conv);  // 3 <- profiled

    // attention maps (invariant across recurrence)
    eH_kernel<<<dim3(256, 4), 256>>>(qt, kt, aHs);
    eW_kernel<<<dim3(4, 128, 4), 256>>>(qt, kt, aWs);
    softmax_kernel<<<16384, 256>>>(aHs, aWs, aHh, aWh);

    // BN for stage A
    bn_reduce_kernel<<<dim3(64, 8), 256>>>(conv, part);
    bn_finalize_kernel<<<1, 64>>>(part, stats);
    bn_apply_kernel<<<8192, 256>>>(conv, stats, bn_ag, bn_ab, xA);

    // Stage C: 2 recurrence iterations
    float* cur = xA;
    float* nxt = xB;
    for (int it = 0; it < 2; ++it) {
        conv1x1_d64_kernel<<<512, 256>>>(cur, Wv, bv, vt);
        oH_kernel<<<dim3(2, 256, 4), 256>>>(vt, aHh, oht);
        oW_combine_kernel<<<dim3(4, 128, 4), 256>>>(vt, aWh, oht, cur, gamma, nxt);
        float* t = cur; cur = nxt; nxt = t;
    }

    // Stage D: conv3x3(cur, Wb) + BN -> out
    wtrans_kernel<<<144, 256>>>(Wb, wtb);
    conv3x3_mma_kernel<<<dim3(4, 64, 4), 256, CONV_SMEM>>>(cur, wtb, conv);
    bn_reduce_kernel<<<dim3(64, 8), 256>>>(conv, part);
    bn_finalize_kernel<<<1, 64>>>(part, stats);
    bn_apply_kernel<<<8192, 256>>>(conv, stats, bn_bg, bn_bb, out);
}

// round 8
// speedup vs baseline: 2.2624x; 1.2993x over previous
#include <cuda_runtime.h>
#include <cuda_fp16.h>
#include <cstdint>
#include <cstddef>

#define BB 4
#define CC 32
#define DD 64
#define HH 128
#define WW 256
#define HW_ (HH*WW)          // 32768
#define BDHW_ (BB*DD*HW_)    // 8388608
#define BCHW_ (BB*CC*HW_)    // 4194304

// ---------------- scratch (static device globals; no allocation) ----------------
__device__ float g_conv[BDHW_];
__device__ float g_xA[BDHW_];
__device__ float g_xB[BDHW_];
__device__ __half g_vth[BDHW_];      // v fp16, [b][h][w][d]
__device__ __half g_ohth[BDHW_];     // oH fp16, [b][h][w][d]
__device__ float g_qt[BCHW_];        // q in [b][h][w][c]
__device__ float g_kt[BCHW_];        // k in [b][h][w][c]
__device__ __half g_aHs[BB*HH*WW*HH];  // fp16 scores (H part)
__device__ __half g_aWs[BB*HH*WW*WW];  // fp16 scores (W part)
__device__ __half g_aHh[BB*HH*WW*HH];  // fp16 normalized weights
__device__ __half g_aWh[BB*HH*WW*WW];
__device__ float g_wt[9*64*64];      // transposed tf32 conv weights [t][c][d]
__device__ float2 g_part[64*8];
__device__ float2 g_stats[64];

// ---------------- weight transform: W[d][c][3][3] -> wt[t][c][d], tf32-rounded ----------------
__global__ void wtrans_kernel(const float* __restrict__ W, float* __restrict__ wt) {
    const int i = blockIdx.x * 256 + threadIdx.x;
    if (i >= 9 * 64 * 64) return;
    const int t = i >> 12;
    const int rem = i & 4095;
    const int c = rem >> 6;
    const int d = rem & 63;
    float v = W[(((d << 6) + c) * 9) + t];
    uint32_t uv;
    asm("cvt.rna.tf32.f32 %0, %1;" : "=r"(uv) : "f"(v));
    wt[i] = __uint_as_float(uv);
}

// ---------------- conv3x3 via tf32 mma.sync, 2 h-rows per block ----------------
#define XS_RSTRIDE 68
#define XS_CSTRIDE 280
#define XS_FLOATS (64*280)      // 17920
#define WS_STRIDE 72
#define WS_FLOATS (64*72)       // 4608
#define CONV_SMEM ((XS_FLOATS + WS_FLOATS) * 4)   // 90112 bytes

__device__ __forceinline__ void mma_tf32(float* c, uint32_t a0, uint32_t a1, uint32_t a2, uint32_t a3,
                                         uint32_t b0, uint32_t b1) {
    asm volatile("mma.sync.aligned.m16n8k8.row.col.f32.tf32.tf32.f32 "
                 "{%0,%1,%2,%3}, {%4,%5,%6,%7}, {%8,%9}, {%0,%1,%2,%3};"
                 : "+f"(c[0]), "+f"(c[1]), "+f"(c[2]), "+f"(c[3])
                 : "r"(a0), "r"(a1), "r"(a2), "r"(a3), "r"(b0), "r"(b1));
}

__device__ __forceinline__ void mma_f16(float* c, uint32_t a0, uint32_t a1, uint32_t a2, uint32_t a3,
                                        uint32_t b0, uint32_t b1) {
    asm volatile("mma.sync.aligned.m16n8k16.row.col.f32.f16.f16.f32 "
                 "{%0,%1,%2,%3}, {%4,%5,%6,%7}, {%8,%9}, {%0,%1,%2,%3};"
                 : "+f"(c[0]), "+f"(c[1]), "+f"(c[2]), "+f"(c[3])
                 : "r"(a0), "r"(a1), "r"(a2), "r"(a3), "r"(b0), "r"(b1));
}

__global__ void conv3x3_mma_kernel(const float* __restrict__ x, const float* __restrict__ wt,
                                   float* __restrict__ y) {
    extern __shared__ float smem[];
    float* xs = smem;
    float* ws = smem + XS_FLOATS;

    const int w0 = blockIdx.x * 64;
    const int h0 = blockIdx.y * 2;
    const int b  = blockIdx.z;
    const int tid = threadIdx.x;
    const int lane = tid & 31;
    const int warp = tid >> 5;
    const int hsel = warp >> 2;
    const int d0 = (warp & 3) * 16;
    const int q4 = lane & 3;
    const int g8 = lane >> 2;

    for (int i = tid; i < 64 * 4 * 66; i += 256) {
        const int c = i / 264;
        const int rem = i - c * 264;
        const int r = rem / 66;
        const int col = rem - r * 66;
        const int gh = h0 + r - 1;
        const int gw = w0 + col - 1;
        float v = 0.f;
        if (gh >= 0 && gh < HH && gw >= 0 && gw < WW)
            v = x[((size_t)(b * 64 + c)) * HW_ + gh * WW + gw];
        uint32_t uv;
        asm("cvt.rna.tf32.f32 %0, %1;" : "=r"(uv) : "f"(v));
        xs[c * XS_CSTRIDE + r * XS_RSTRIDE + col] = __uint_as_float(uv);
    }

    float acc[8][4];
#pragma unroll
    for (int j = 0; j < 8; ++j)
#pragma unroll
        for (int k = 0; k < 4; ++k) acc[j][k] = 0.f;

    for (int t = 0; t < 9; ++t) {
        __syncthreads();
        const float* wp = wt + t * 4096;
        for (int i = tid; i < 4096; i += 256)
            ws[(i >> 6) * WS_STRIDE + (i & 63)] = wp[i];
        __syncthreads();

        const int dh = t / 3;
        const int dw = t - dh * 3;
#pragma unroll
        for (int ck = 0; ck < 8; ++ck) {
            const int c0 = ck * 8;
            const float* wr0 = ws + (c0 + q4) * WS_STRIDE + d0 + g8;
            const float* wr1 = wr0 + 4 * WS_STRIDE;
            const uint32_t a0 = __float_as_uint(wr0[0]);
            const uint32_t a1 = __float_as_uint(wr0[8]);
            const uint32_t a2 = __float_as_uint(wr1[0]);
            const uint32_t a3 = __float_as_uint(wr1[8]);
            const float* xb0 = xs + (c0 + q4) * XS_CSTRIDE + (hsel + dh) * XS_RSTRIDE + dw + g8;
            const float* xb1 = xb0 + 4 * XS_CSTRIDE;
#pragma unroll
            for (int j = 0; j < 8; ++j) {
                const uint32_t b0 = __float_as_uint(xb0[j * 8]);
                const uint32_t b1 = __float_as_uint(xb1[j * 8]);
                mma_tf32(acc[j], a0, a1, a2, a3, b0, b1);
            }
        }
    }

    const int h = h0 + hsel;
#pragma unroll
    for (int j = 0; j < 8; ++j) {
        const int w = w0 + j * 8 + 2 * q4;
        const size_t base = ((size_t)(b * 64 + d0 + g8)) * HW_ + (size_t)h * WW + w;
        *reinterpret_cast<float2*>(y + base) = make_float2(acc[j][0], acc[j][1]);
        *reinterpret_cast<float2*>(y + base + (size_t)8 * HW_) = make_float2(acc[j][2], acc[j][3]);
    }
}

// ---------------- batchnorm ----------------
__global__ void bn_reduce_kernel(const float* __restrict__ x, float2* __restrict__ part) {
    const int c = blockIdx.x, p = blockIdx.y;
    float s = 0.f, s2 = 0.f;
    const int base = p * 16384;
    for (int j = threadIdx.x; j < 16384; j += 256) {
        const int f = base + j;
        const int b = f >> 15;
        const int i = f & 32767;
        const float v = x[((size_t)(b * 64 + c)) * HW_ + i];
        s += v; s2 += v * v;
    }
    __shared__ float rs[8], rs2[8];
#pragma unroll
    for (int o = 16; o; o >>= 1) {
        s  += __shfl_xor_sync(0xffffffffu, s, o);
        s2 += __shfl_xor_sync(0xffffffffu, s2, o);
    }
    if ((threadIdx.x & 31) == 0) { rs[threadIdx.x >> 5] = s; rs2[threadIdx.x >> 5] = s2; }
    __syncthreads();
    if (threadIdx.x == 0) {
        float a = 0.f, b2 = 0.f;
        for (int k = 0; k < 8; ++k) { a += rs[k]; b2 += rs2[k]; }
        part[c * 8 + p] = make_float2(a, b2);
    }
}

__global__ void bn_finalize_kernel(const float2* __restrict__ part, float2* __restrict__ stats) {
    const int c = threadIdx.x;
    float s = 0.f, s2 = 0.f;
    for (int p = 0; p < 8; ++p) { s += part[c * 8 + p].x; s2 += part[c * 8 + p].y; }
    const float inv_n = 1.f / 131072.f;
    const float mean = s * inv_n;
    const float var  = s2 * inv_n - mean * mean;
    stats[c] = make_float2(mean, rsqrtf(var + 1e-5f));
}

__global__ void bn_apply_kernel(const float* __restrict__ x, const float2* __restrict__ stats,
                                const float* __restrict__ gam, const float* __restrict__ bet,
                                float* __restrict__ y) {
    const int idx = blockIdx.x * 256 + threadIdx.x;
    const int e = idx * 4;
    const int c = (e / HW_) & 63;
    const float2 st = stats[c];
    const float g = gam[c], be = bet[c];
    float4 v = reinterpret_cast<const float4*>(x)[idx];
    v.x = (v.x - st.x) * st.y * g + be;
    v.y = (v.y - st.x) * st.y * g + be;
    v.z = (v.z - st.x) * st.y * g + be;
    v.w = (v.w - st.x) * st.y * g + be;
    reinterpret_cast<float4*>(y)[idx] = v;
}

// ---------------- 1x1 convs ----------------
__global__ void conv1x1_c32_kernel(const float* __restrict__ x, const float* __restrict__ wgt,
                                   const float* __restrict__ bias, float* __restrict__ yt) {
    __shared__ float sw[32][33];
    __shared__ float sb[32];
    const int tid = threadIdx.x;
    for (int i = tid; i < 1024; i += 256) sw[i >> 5][i & 31] = wgt[i];
    if (tid < 32) sb[tid] = bias[tid];
    __syncthreads();
    const int pos = blockIdx.x * 256 + tid;
    const int b = pos >> 15, i = pos & 32767;
    float xin[32];
#pragma unroll
    for (int ci = 0; ci < 32; ++ci) xin[ci] = x[((size_t)(b * 32 + ci)) * HW_ + i];
    float* out = yt + (size_t)pos * 32;
#pragma unroll
    for (int co = 0; co < 32; co += 4) {
        float4 a = make_float4(sb[co], sb[co + 1], sb[co + 2], sb[co + 3]);
#pragma unroll
        for (int ci = 0; ci < 32; ++ci) {
            const float xv = xin[ci];
            a.x += sw[co][ci] * xv; a.y += sw[co + 1][ci] * xv;
            a.z += sw[co + 2][ci] * xv; a.w += sw[co + 3][ci] * xv;
        }
        *reinterpret_cast<float4*>(out + co) = a;
    }
}

// v: 64->64, fp16 output [b][h][w][d]
__global__ void conv1x1_d64_kernel(const float* __restrict__ x, const float* __restrict__ wgt,
                                   const float* __restrict__ bias, __half* __restrict__ vth) {
    __shared__ float sw[64][65];
    __shared__ float sb[64];
    const int tid = threadIdx.x;
    for (int i = tid; i < 4096; i += 256) sw[i >> 6][i & 63] = wgt[i];
    if (tid < 64) sb[tid] = bias[tid];
    __syncthreads();
    const int pos = blockIdx.x * 256 + tid;
    const int b = pos >> 15, i = pos & 32767;
    float xin[64];
#pragma unroll
    for (int ci = 0; ci < 64; ++ci) xin[ci] = x[((size_t)(b * 64 + ci)) * HW_ + i];
    __half* out = vth + (size_t)pos * 64;
#pragma unroll
    for (int co = 0; co < 64; co += 4) {
        float4 a = make_float4(sb[co], sb[co + 1], sb[co + 2], sb[co + 3]);
#pragma unroll
        for (int ci = 0; ci < 64; ++ci) {
            const float xv = xin[ci];
            a.x += sw[co][ci] * xv; a.y += sw[co + 1][ci] * xv;
            a.z += sw[co + 2][ci] * xv; a.w += sw[co + 3][ci] * xv;
        }
        *reinterpret_cast<__half2*>(out + co)     = __floats2half2_rn(a.x, a.y);
        *reinterpret_cast<__half2*>(out + co + 2) = __floats2half2_rn(a.z, a.w);
    }
}

// ---------------- half-pack helpers ----------------
union H8pack { __half2 h2[4]; uint4 u; };
union H4pack { __half2 h2[2]; uint2 u; };

// ---------------- eH: scores -> fp16, diag=-inf ----------------
__global__ void eH_kernel(const float* __restrict__ qt, const float* __restrict__ kt,
                          __half* __restrict__ aHs) {
    const int w = blockIdx.x, b = blockIdx.y;
    const int tid = threadIdx.x;
    __shared__ float Qs[32][132];
    __shared__ float Ks[32][132];
    for (int i = tid; i < 4096; i += 256) {
        const int h = i >> 5, c = i & 31;
        const size_t gidx = (((size_t)b * HH + h) * WW + w) * 32 + c;
        Qs[c][h] = qt[gidx];
        Ks[c][h] = kt[gidx];
    }
    __syncthreads();
    const int hg = tid >> 4, gg = tid & 15;
    float acc[8][8];
#pragma unroll
    for (int i = 0; i < 8; ++i)
#pragma unroll
        for (int j = 0; j < 8; ++j) acc[i][j] = 0.f;
    for (int c = 0; c < 32; ++c) {
        float4 qa = *reinterpret_cast<float4*>(&Qs[c][hg * 8]);
        float4 qb = *reinterpret_cast<float4*>(&Qs[c][hg * 8 + 4]);
        float4 ka = *reinterpret_cast<float4*>(&Ks[c][gg * 8]);
        float4 kb = *reinterpret_cast<float4*>(&Ks[c][gg * 8 + 4]);
        float qv[8] = {qa.x, qa.y, qa.z, qa.w, qb.x, qb.y, qb.z, qb.w};
        float kv[8] = {ka.x, ka.y, ka.z, ka.w, kb.x, kb.y, kb.z, kb.w};
#pragma unroll
        for (int i = 0; i < 8; ++i)
#pragma unroll
            for (int j = 0; j < 8; ++j) acc[i][j] += qv[i] * kv[j];
    }
    const float ninf = __int_as_float(0xff800000);
#pragma unroll
    for (int i = 0; i < 8; ++i) {
        const int h = hg * 8 + i;
#pragma unroll
        for (int j = 0; j < 8; ++j) {
            const int g = gg * 8 + j;
            if (h == g) acc[i][j] = ninf;
        }
        H8pack p;
#pragma unroll
        for (int j = 0; j < 4; ++j)
            p.h2[j] = __floats2half2_rn(acc[i][2 * j], acc[i][2 * j + 1]);
        *reinterpret_cast<uint4*>(aHs + (((size_t)b * HH + h) * WW + w) * 128 + gg * 8) = p.u;
    }
}

// ---------------- eW: scores -> fp16 ----------------
__global__ void eW_kernel(const float* __restrict__ qt, const float* __restrict__ kt,
                          __half* __restrict__ aWs) {
    const int gc = blockIdx.x * 64;
    const int h = blockIdx.y, b = blockIdx.z;
    const int tid = threadIdx.x;
    __shared__ float Qs[32][260];
    __shared__ float Ks[32][68];
    const float* qbase = qt + (((size_t)b * HH + h) * WW) * 32;
    for (int i = tid; i < 8192; i += 256) { Qs[i & 31][i >> 5] = qbase[i]; }
    const float* kbase = kt + (((size_t)b * HH + h) * WW + gc) * 32;
    for (int i = tid; i < 2048; i += 256) { Ks[i & 31][i >> 5] = kbase[i]; }
    __syncthreads();
    const int wg = tid >> 3, gg = tid & 7;
    float acc[8][8];
#pragma unroll
    for (int i = 0; i < 8; ++i)
#pragma unroll
        for (int j = 0; j < 8; ++j) acc[i][j] = 0.f;
    for (int c = 0; c < 32; ++c) {
        float4 qa = *reinterpret_cast<float4*>(&Qs[c][wg * 8]);
        float4 qb = *reinterpret_cast<float4*>(&Qs[c][wg * 8 + 4]);
        float4 ka = *reinterpret_cast<float4*>(&Ks[c][gg * 8]);
        float4 kb = *reinterpret_cast<float4*>(&Ks[c][gg * 8 + 4]);
        float qv[8] = {qa.x, qa.y, qa.z, qa.w, qb.x, qb.y, qb.z, qb.w};
        float kv[8] = {ka.x, ka.y, ka.z, ka.w, kb.x, kb.y, kb.z, kb.w};
#pragma unroll
        for (int i = 0; i < 8; ++i)
#pragma unroll
            for (int j = 0; j < 8; ++j) acc[i][j] += qv[i] * kv[j];
    }
#pragma unroll
    for (int i = 0; i < 8; ++i) {
        const int w = wg * 8 + i;
        H8pack p;
#pragma unroll
        for (int j = 0; j < 4; ++j)
            p.h2[j] = __floats2half2_rn(acc[i][2 * j], acc[i][2 * j + 1]);
        *reinterpret_cast<uint4*>(aWs + (((size_t)b * HH + h) * WW + w) * 256 + gc + gg * 8) = p.u;
    }
}

// ---------------- fast exp ----------------
__device__ __forceinline__ float fexp(float x) {
    x = fmaxf(x, -80.f);
    const float y = x * 1.44269504f;
    const int e = __float2int_rn(y);
    const float f = y - (float)e;
    float p = 0.00133335581f;
    p = fmaf(p, f, 0.00961812910f);
    p = fmaf(p, f, 0.0555041086f);
    p = fmaf(p, f, 0.240226507f);
    p = fmaf(p, f, 0.693147182f);
    p = fmaf(p, f, 1.0f);
    return p * __int_as_float((e + 127) << 23);
}

// ---------------- softmax: fp16 scores in, fp16 weights out ----------------
__global__ void softmax_kernel(const __half* __restrict__ aHs, const __half* __restrict__ aWs,
                               __half* __restrict__ aHh, __half* __restrict__ aWh) {
    const int row = blockIdx.x * 8 + (threadIdx.x >> 5);
    const int lane = threadIdx.x & 31;
    const uint2* ph = reinterpret_cast<const uint2*>(aHs) + (size_t)row * 32;
    const uint2* pw = reinterpret_cast<const uint2*>(aWs) + (size_t)row * 64;
    H4pack ih, iw0, iw1;
    ih.u = ph[lane];
    iw0.u = pw[lane];
    iw1.u = pw[lane + 32];
    float2 h01 = __half22float2(ih.h2[0]);
    float2 h23 = __half22float2(ih.h2[1]);
    float2 w01 = __half22float2(iw0.h2[0]);
    float2 w23 = __half22float2(iw0.h2[1]);
    float2 w45 = __half22float2(iw1.h2[0]);
    float2 w67 = __half22float2(iw1.h2[1]);
    float4 vh  = make_float4(h01.x, h01.y, h23.x, h23.y);
    float4 vw0 = make_float4(w01.x, w01.y, w23.x, w23.y);
    float4 vw1 = make_float4(w45.x, w45.y, w67.x, w67.y);
    float m = fmaxf(fmaxf(fmaxf(vh.x, vh.y), fmaxf(vh.z, vh.w)),
              fmaxf(fmaxf(fmaxf(vw0.x, vw0.y), fmaxf(vw0.z, vw0.w)),
                    fmaxf(fmaxf(fmaxf(vw1.x, vw1.y), fmaxf(vw1.z, vw1.w)), -1e30f)));
#pragma unroll
    for (int o = 16; o; o >>= 1) m = fmaxf(m, __shfl_xor_sync(0xffffffffu, m, o));
    vh.x = fexp(vh.x - m); vh.y = fexp(vh.y - m); vh.z = fexp(vh.z - m); vh.w = fexp(vh.w - m);
    vw0.x = fexp(vw0.x - m); vw0.y = fexp(vw0.y - m); vw0.z = fexp(vw0.z - m); vw0.w = fexp(vw0.w - m);
    vw1.x = fexp(vw1.x - m); vw1.y = fexp(vw1.y - m); vw1.z = fexp(vw1.z - m); vw1.w = fexp(vw1.w - m);
    float s = vh.x + vh.y + vh.z + vh.w + vw0.x + vw0.y + vw0.z + vw0.w + vw1.x + vw1.y + vw1.z + vw1.w;
#pragma unroll
    for (int o = 16; o; o >>= 1) s += __shfl_xor_sync(0xffffffffu, s, o);
    const float inv = 1.f / s;
    H4pack p0, p1, p2;
    p0.h2[0] = __floats2half2_rn(vh.x * inv, vh.y * inv);
    p0.h2[1] = __floats2half2_rn(vh.z * inv, vh.w * inv);
    p1.h2[0] = __floats2half2_rn(vw0.x * inv, vw0.y * inv);
    p1.h2[1] = __floats2half2_rn(vw0.z * inv, vw0.w * inv);
    p2.h2[0] = __floats2half2_rn(vw1.x * inv, vw1.y * inv);
    p2.h2[1] = __floats2half2_rn(vw1.z * inv, vw1.w * inv);
    reinterpret_cast<uint2*>(aHh)[(size_t)row * 32 + lane] = p0.u;
    uint2* pwh = reinterpret_cast<uint2*>(aWh) + (size_t)row * 64;
    pwh[lane] = p1.u;
    pwh[lane + 32] = p2.u;
}

// ---------------- oH via HMMA: per (b,w): O[h,d] = sum_g aH[h,g]*v[g,d] ----------------
// grid (256 w, 4 b), 128 threads (4 warps, each 32 h x 64 d). Output fp16 [b][h][w][d].
#define ATT_SSTRIDE 136
#define ATT_SMEM ((128*ATT_SSTRIDE + 64*ATT_SSTRIDE) * 2)   // 52224 bytes

__global__ void oH_kernel(const __half* __restrict__ vth, const __half* __restrict__ aHh,
                          __half* __restrict__ ohth) {
    extern __shared__ __half sh[];
    __half* As = sh;                       // [128 h][136] g-contiguous
    __half* Vs = sh + 128 * ATT_SSTRIDE;   // [64 d][136] g-contiguous (B col-major)
    const int w = blockIdx.x, b = blockIdx.y;
    const int tid = threadIdx.x;
    const int lane = tid & 31, warp = tid >> 5;
    const int g8 = lane >> 2, t2 = (lane & 3) * 2;

    for (int i = tid; i < 2048; i += 128) {
        const int row = i >> 4, ch = (i & 15) * 8;
        *reinterpret_cast<uint4*>(As + row * ATT_SSTRIDE + ch) =
            *reinterpret_cast<const uint4*>(aHh + (((size_t)b * HH + row) * WW + w) * 128 + ch);
    }
    for (int i = tid; i < 1024; i += 128) {
        const int g = i >> 3, dc = (i & 7) * 8;
        uint4 v = *reinterpret_cast<const uint4*>(vth + (((size_t)b * HH + g) * WW + w) * 64 + dc);
        __half tmp[8];
        *reinterpret_cast<uint4*>(tmp) = v;
#pragma unroll
        for (int j = 0; j < 8; ++j) Vs[(dc + j) * ATT_SSTRIDE + g] = tmp[j];
    }
    __syncthreads();

    float acc[2][8][4];
#pragma unroll
    for (int mi = 0; mi < 2; ++mi)
#pragma unroll
        for (int ni = 0; ni < 8; ++ni)
#pragma unroll
            for (int k = 0; k < 4; ++k) acc[mi][ni][k] = 0.f;

    const int h0 = warp * 32;
#pragma unroll
    for (int kb = 0; kb < 128; kb += 16) {
        uint32_t a[2][4];
#pragma unroll
        for (int mi = 0; mi < 2; ++mi) {
            const __half* ap = As + (h0 + mi * 16 + g8) * ATT_SSTRIDE + kb + t2;
            a[mi][0] = *reinterpret_cast<const uint32_t*>(ap);
            a[mi][1] = *reinterpret_cast<const uint32_t*>(ap + 8 * ATT_SSTRIDE);
            a[mi][2] = *reinterpret_cast<const uint32_t*>(ap + 8);
            a[mi][3] = *reinterpret_cast<const uint32_t*>(ap + 8 * ATT_SSTRIDE + 8);
        }
#pragma unroll
        for (int ni = 0; ni < 8; ++ni) {
            const __half* bp = Vs + (ni * 8 + g8) * ATT_SSTRIDE + kb + t2;
            const uint32_t b0 = *reinterpret_cast<const uint32_t*>(bp);
            const uint32_t b1 = *reinterpret_cast<const uint32_t*>(bp + 8);
            mma_f16(acc[0][ni], a[0][0], a[0][1], a[0][2], a[0][3], b0, b1);
            mma_f16(acc[1][ni], a[1][0], a[1][1], a[1][2], a[1][3], b0, b1);
        }
    }

#pragma unroll
    for (int mi = 0; mi < 2; ++mi)
#pragma unroll
        for (int ni = 0; ni < 8; ++ni) {
            const int h = h0 + mi * 16 + g8;
            const int d = ni * 8 + t2;
            *reinterpret_cast<__half2*>(ohth + (((size_t)b * HH + h) * WW + w) * 64 + d) =
                __floats2half2_rn(acc[mi][ni][0], acc[mi][ni][1]);
            *reinterpret_cast<__half2*>(ohth + (((size_t)b * HH + h + 8) * WW + w) * 64 + d) =
                __floats2half2_rn(acc[mi][ni][2], acc[mi][ni][3]);
        }
}

// ---------------- oW via HMMA + combine: per (b,h): out = gamma*(oH + A_w @ v) + x ----------------
// grid (2, 128 h, 4 b), 128 threads; block covers 128 w x 64 d, K=256 in 2 chunks.
__global__ void oW_combine_kernel(const __half* __restrict__ vth, const __half* __restrict__ aWh,
                                  const __half* __restrict__ ohth, const float* __restrict__ x,
                                  const float* __restrict__ gamma, float* __restrict__ xout) {
    extern __shared__ __half sh[];
    __half* As = sh;                       // [128 w][136]
    __half* Vs = sh + 128 * ATT_SSTRIDE;   // [64 d][136]
    const int wb = blockIdx.x * 128;
    const int h = blockIdx.y, b = blockIdx.z;
    const int tid = threadIdx.x;
    const int lane = tid & 31, warp = tid >> 5;
    const int g8 = lane >> 2, t2 = (lane & 3) * 2;

    float acc[2][8][4];
#pragma unroll
    for (int mi = 0; mi < 2; ++mi)
#pragma unroll
        for (int ni = 0; ni < 8; ++ni)
#pragma unroll
            for (int k = 0; k < 4; ++k) acc[mi][ni][k] = 0.f;

    const int w0 = warp * 32;
    for (int gc = 0; gc < 256; gc += 128) {
        __syncthreads();
        for (int i = tid; i < 2048; i += 128) {
            const int row = i >> 4, ch = (i & 15) * 8;
            *reinterpret_cast<uint4*>(As + row * ATT_SSTRIDE + ch) =
                *reinterpret_cast<const uint4*>(
                    aWh + (((size_t)b * HH + h) * WW + wb + row) * 256 + gc + ch);
        }
        for (int i = tid; i < 1024; i += 128) {
            const int g = i >> 3, dc = (i & 7) * 8;
            uint4 v = *reinterpret_cast<const uint4*>(
                vth + (((size_t)b * HH + h) * WW + gc + g) * 64 + dc);
            __half tmp[8];
            *reinterpret_cast<uint4*>(tmp) = v;
#pragma unroll
            for (int j = 0; j < 8; ++j) Vs[(dc + j) * ATT_SSTRIDE + g] = tmp[j];
        }
        __syncthreads();

#pragma unroll
        for (int kb = 0; kb < 128; kb += 16) {
            uint32_t a[2][4];
#pragma unroll
            for (int mi = 0; mi < 2; ++mi) {
                const __half* ap = As + (w0 + mi * 16 + g8) * ATT_SSTRIDE + kb + t2;
                a[mi][0] = *reinterpret_cast<const uint32_t*>(ap);
                a[mi][1] = *reinterpret_cast<const uint32_t*>(ap + 8 * ATT_SSTRIDE);
                a[mi][2] = *reinterpret_cast<const uint32_t*>(ap + 8);
                a[mi][3] = *reinterpret_cast<const uint32_t*>(ap + 8 * ATT_SSTRIDE + 8);
            }
#pragma unroll
            for (int ni = 0; ni < 8; ++ni) {
                const __half* bp = Vs + (ni * 8 + g8) * ATT_SSTRIDE + kb + t2;
                const uint32_t b0 = *reinterpret_cast<const uint32_t*>(bp);
                const uint32_t b1 = *reinterpret_cast<const uint32_t*>(bp + 8);
                mma_f16(acc[0][ni], a[0][0], a[0][1], a[0][2], a[0][3], b0, b1);
                mma_f16(acc[1][ni], a[1][0], a[1][1], a[1][2], a[1][3], b0, b1);
            }
        }
    }

    const float gam = *gamma;
#pragma unroll
    for (int mi = 0; mi < 2; ++mi)
#pragma unroll
        for (int ni = 0; ni < 8; ++ni) {
            const int d = ni * 8 + t2;
#pragma unroll
            for (int half = 0; half < 2; ++half) {
                const int w = wb + w0 + mi * 16 + g8 + half * 8;
                const float cA = acc[mi][ni][half * 2];
                const float cB = acc[mi][ni][half * 2 + 1];
                const float2 ohf = __half22float2(*reinterpret_cast<const __half2*>(
                    ohth + (((size_t)b * HH + h) * WW + w) * 64 + d));
                const size_t x0 = ((size_t)(b * 64 + d)) * HW_ + (size_t)h * WW + w;
                const size_t x1 = ((size_t)(b * 64 + d + 1)) * HW_ + (size_t)h * WW + w;
                xout[x0] = gam * (cA + ohf.x) + x[x0];
                xout[x1] = gam * (cB + ohf.y) + x[x1];
            }
        }
}

// ---------------- host ----------------
extern "C" void kernel_launch(void* const* d_in, const int* in_sizes, int n_in,
                              void* d_out, int out_size) {
    const float* cost  = (const float*)d_in[0];
    const float* lf0   = (const float*)d_in[1];
    const float* lf1   = (const float*)d_in[2];
    const float* Wa    = (const float*)d_in[3];
    const float* bn_ag = (const float*)d_in[4];
    const float* bn_ab = (const float*)d_in[5];
    const float* Wq    = (const float*)d_in[6];
    const float* bq    = (const float*)d_in[7];
    const float* Wk    = (const float*)d_in[8];
    const float* bk    = (const float*)d_in[9];
    const float* Wv    = (const float*)d_in[10];
    const float* bv    = (const float*)d_in[11];
    const float* gamma = (const float*)d_in[12];
    const float* Wb    = (const float*)d_in[13];
    const float* bn_bg = (const float*)d_in[14];
    const float* bn_bb = (const float*)d_in[15];
    float* out = (float*)d_out;

    float *conv, *xA, *xB, *qt, *kt, *wtb;
    __half *vth, *ohth, *aHs, *aWs, *aHh, *aWh;
    float2 *part, *stats;
    cudaGetSymbolAddress((void**)&conv, g_conv);
    cudaGetSymbolAddress((void**)&xA, g_xA);
    cudaGetSymbolAddress((void**)&xB, g_xB);
    cudaGetSymbolAddress((void**)&vth, g_vth);
    cudaGetSymbolAddress((void**)&ohth, g_ohth);
    cudaGetSymbolAddress((void**)&qt, g_qt);
    cudaGetSymbolAddress((void**)&kt, g_kt);
    cudaGetSymbolAddress((void**)&aHs, g_aHs);
    cudaGetSymbolAddress((void**)&aWs, g_aWs);
    cudaGetSymbolAddress((void**)&aHh, g_aHh);
    cudaGetSymbolAddress((void**)&aWh, g_aWh);
    cudaGetSymbolAddress((void**)&wtb, g_wt);
    cudaGetSymbolAddress((void**)&part, g_part);
    cudaGetSymbolAddress((void**)&stats, g_stats);

    // Idempotent, called unconditionally (no static guards — harness rule).
    cudaFuncSetAttribute(conv3x3_mma_kernel,
                         cudaFuncAttributeMaxDynamicSharedMemorySize, CONV_SMEM);
    cudaFuncSetAttribute(oH_kernel,
                         cudaFuncAttributeMaxDynamicSharedMemorySize, ATT_SMEM);
    cudaFuncSetAttribute(oW_combine_kernel,
                         cudaFuncAttributeMaxDynamicSharedMemorySize, ATT_SMEM);

    // Launch order keeps conv3x3 at capture index 3 (ncu -s5 -c1 lands there).
    conv1x1_c32_kernel<<<512, 256>>>(lf0, Wq, bq, qt);           // 0
    conv1x1_c32_kernel<<<512, 256>>>(lf1, Wk, bk, kt);           // 1
    wtrans_kernel<<<144, 256>>>(Wa, wtb);                        // 2
    conv3x3_mma_kernel<<<dim3(4, 64, 4), 256, CONV_SMEM>>>(cost, wtb, conv);  // 3 <- profiled

    // attention maps (invariant across recurrence)
    eH_kernel<<<dim3(256, 4), 256>>>(qt, kt, aHs);
    eW_kernel<<<dim3(4, 128, 4), 256>>>(qt, kt, aWs);
    softmax_kernel<<<16384, 256>>>(aHs, aWs, aHh, aWh);

    // BN for stage A
    bn_reduce_kernel<<<dim3(64, 8), 256>>>(conv, part);
    bn_finalize_kernel<<<1, 64>>>(part, stats);
    bn_apply_kernel<<<8192, 256>>>(conv, stats, bn_ag, bn_ab, xA);

    // Stage C: 2 recurrence iterations (attention aggregation on tensor cores)
    float* cur = xA;
    float* nxt = xB;
    for (int it = 0; it < 2; ++it) {
        conv1x1_d64_kernel<<<512, 256>>>(cur, Wv, bv, vth);
        oH_kernel<<<dim3(256, 4), 128, ATT_SMEM>>>(vth, aHh, ohth);
        oW_combine_kernel<<<dim3(2, 128, 4), 128, ATT_SMEM>>>(vth, aWh, ohth, cur, gamma, nxt);
        float* t = cur; cur = nxt; nxt = t;
    }

    // Stage D: conv3x3(cur, Wb) + BN -> out
    wtrans_kernel<<<144, 256>>>(Wb, wtb);
    conv3x3_mma_kernel<<<dim3(4, 64, 4), 256, CONV_SMEM>>>(cur, wtb, conv);
    bn_reduce_kernel<<<dim3(64, 8), 256>>>(conv, part);
    bn_finalize_kernel<<<1, 64>>>(part, stats);
    bn_apply_kernel<<<8192, 256>>>(conv, stats, bn_bg, bn_bb, out);
}

// round 9
// speedup vs baseline: 2.5102x; 1.1095x over previous
#include <cuda_runtime.h>
#include <cuda_fp16.h>
#include <cstdint>
#include <cstddef>

#define BB 4
#define CC 32
#define DD 64
#define HH 128
#define WW 256
#define HW_ (HH*WW)          // 32768
#define BDHW_ (BB*DD*HW_)    // 8388608
#define BCHW_ (BB*CC*HW_)    // 4194304

// ---------------- scratch (static device globals; no allocation) ----------------
__device__ float g_conv[BDHW_];
__device__ float g_xA[BDHW_];
__device__ float g_xB[BDHW_];
__device__ __half g_vth[BDHW_];      // v fp16, [b][h][w][d]
__device__ __half g_ohth[BDHW_];     // oH fp16, [b][h][w][d]
__device__ float g_qt[BCHW_];        // q in [b][h][w][c]
__device__ float g_kt[BCHW_];        // k in [b][h][w][c]
__device__ __half g_aHs[BB*HH*WW*HH];  // fp16 scores (H part)
__device__ __half g_aWs[BB*HH*WW*WW];  // fp16 scores (W part)
__device__ __half g_aHh[BB*HH*WW*HH];  // fp16 normalized weights
__device__ __half g_aWh[BB*HH*WW*WW];
__device__ __half g_wth[9*64*64];    // fp16 conv weights [t][d][c]
__device__ float2 g_part[64*8];
__device__ float2 g_stats[64];

// ---------------- weight transform: W[d][c][3][3] -> wth[t][d][c], fp16 ----------------
__global__ void wtrans_kernel(const float* __restrict__ W, __half* __restrict__ wth) {
    const int i = blockIdx.x * 256 + threadIdx.x;
    if (i >= 9 * 64 * 64) return;
    const int t = i >> 12;
    const int d = (i >> 6) & 63;
    const int c = i & 63;
    wth[i] = __float2half(W[((d * 64 + c) * 9) + t]);
}

// ---------------- conv3x3 via fp16 mma.sync m16n8k16, 2 h-rows per block ----------------
// grid (W/64, H/2, B), 256 threads (8 warps: hsel(2) x 4 d-groups of 16).
// smem: xs[(4 rows * 66 cols)][72 c-halves] + ws[64 d][72 c-halves]
#define CXS_STRIDE 72
#define CXS_HALVES (4*66*72)    // 19008
#define CWS_HALVES (64*72)      // 4608
#define CONV_SMEM ((CXS_HALVES + CWS_HALVES) * 2)   // 47232 bytes

__device__ __forceinline__ void mma_f16(float* c, uint32_t a0, uint32_t a1, uint32_t a2, uint32_t a3,
                                        uint32_t b0, uint32_t b1) {
    asm volatile("mma.sync.aligned.m16n8k16.row.col.f32.f16.f16.f32 "
                 "{%0,%1,%2,%3}, {%4,%5,%6,%7}, {%8,%9}, {%0,%1,%2,%3};"
                 : "+f"(c[0]), "+f"(c[1]), "+f"(c[2]), "+f"(c[3])
                 : "r"(a0), "r"(a1), "r"(a2), "r"(a3), "r"(b0), "r"(b1));
}

__global__ __launch_bounds__(256)
void conv3x3_mma_kernel(const float* __restrict__ x, const __half* __restrict__ wth,
                        float* __restrict__ y) {
    extern __shared__ __half shc[];
    __half* xs = shc;                  // [(r*66+col)][72]
    __half* ws = shc + CXS_HALVES;     // [d][72]

    const int w0 = blockIdx.x * 64;
    const int h0 = blockIdx.y * 2;
    const int b  = blockIdx.z;
    const int tid = threadIdx.x;
    const int lane = tid & 31;
    const int warp = tid >> 5;
    const int hsel = warp >> 2;        // 0/1 -> output row h0+hsel
    const int d0 = (warp & 3) * 16;
    const int g8 = lane >> 2;
    const int t2 = (lane & 3) * 2;

    // input tile: c in [0,64), rows h0-1..h0+2, cols w0-1..w0+64, fp16
    for (int i = tid; i < 64 * 4 * 66; i += 256) {
        const int c = i / 264;
        const int rem = i - c * 264;
        const int r = rem / 66;
        const int col = rem - r * 66;
        const int gh = h0 + r - 1;
        const int gw = w0 + col - 1;
        float v = 0.f;
        if (gh >= 0 && gh < HH && gw >= 0 && gw < WW)
            v = x[((size_t)(b * 64 + c)) * HW_ + gh * WW + gw];
        xs[(r * 66 + col) * CXS_STRIDE + c] = __float2half(v);
    }

    float acc[8][4];
#pragma unroll
    for (int j = 0; j < 8; ++j)
#pragma unroll
        for (int k = 0; k < 4; ++k) acc[j][k] = 0.f;

    for (int t = 0; t < 9; ++t) {
        __syncthreads();
        const __half* wp = wth + t * 4096;
        for (int i = tid; i < 4096; i += 256)
            ws[(i >> 6) * CXS_STRIDE + (i & 63)] = wp[i];
        __syncthreads();

        const int dh = t / 3;
        const int dw = t - dh * 3;
        const int colrow = (hsel + dh) * 66 + dw;
#pragma unroll
        for (int kb = 0; kb < 64; kb += 16) {
            const __half* ap = ws + (d0 + g8) * CXS_STRIDE + kb + t2;
            const uint32_t a0 = *reinterpret_cast<const uint32_t*>(ap);
            const uint32_t a1 = *reinterpret_cast<const uint32_t*>(ap + 8 * CXS_STRIDE);
            const uint32_t a2 = *reinterpret_cast<const uint32_t*>(ap + 8);
            const uint32_t a3 = *reinterpret_cast<const uint32_t*>(ap + 8 * CXS_STRIDE + 8);
#pragma unroll
            for (int j = 0; j < 8; ++j) {
                const __half* bp = xs + (colrow + j * 8 + g8) * CXS_STRIDE + kb + t2;
                const uint32_t b0 = *reinterpret_cast<const uint32_t*>(bp);
                const uint32_t b1 = *reinterpret_cast<const uint32_t*>(bp + 8);
                mma_f16(acc[j], a0, a1, a2, a3, b0, b1);
            }
        }
    }

    // epilogue: C rows = d (g8, g8+8), cols = w (t2, t2+1)
    const int h = h0 + hsel;
#pragma unroll
    for (int j = 0; j < 8; ++j) {
        const int w = w0 + j * 8 + t2;
        const size_t base = ((size_t)(b * 64 + d0 + g8)) * HW_ + (size_t)h * WW + w;
        *reinterpret_cast<float2*>(y + base) = make_float2(acc[j][0], acc[j][1]);
        *reinterpret_cast<float2*>(y + base + (size_t)8 * HW_) = make_float2(acc[j][2], acc[j][3]);
    }
}

// ---------------- batchnorm ----------------
__global__ void bn_reduce_kernel(const float* __restrict__ x, float2* __restrict__ part) {
    const int c = blockIdx.x, p = blockIdx.y;
    float s = 0.f, s2 = 0.f;
    const int base = p * 16384;
    for (int j = threadIdx.x; j < 16384; j += 256) {
        const int f = base + j;
        const int b = f >> 15;
        const int i = f & 32767;
        const float v = x[((size_t)(b * 64 + c)) * HW_ + i];
        s += v; s2 += v * v;
    }
    __shared__ float rs[8], rs2[8];
#pragma unroll
    for (int o = 16; o; o >>= 1) {
        s  += __shfl_xor_sync(0xffffffffu, s, o);
        s2 += __shfl_xor_sync(0xffffffffu, s2, o);
    }
    if ((threadIdx.x & 31) == 0) { rs[threadIdx.x >> 5] = s; rs2[threadIdx.x >> 5] = s2; }
    __syncthreads();
    if (threadIdx.x == 0) {
        float a = 0.f, b2 = 0.f;
        for (int k = 0; k < 8; ++k) { a += rs[k]; b2 += rs2[k]; }
        part[c * 8 + p] = make_float2(a, b2);
    }
}

__global__ void bn_finalize_kernel(const float2* __restrict__ part, float2* __restrict__ stats) {
    const int c = threadIdx.x;
    float s = 0.f, s2 = 0.f;
    for (int p = 0; p < 8; ++p) { s += part[c * 8 + p].x; s2 += part[c * 8 + p].y; }
    const float inv_n = 1.f / 131072.f;
    const float mean = s * inv_n;
    const float var  = s2 * inv_n - mean * mean;
    stats[c] = make_float2(mean, rsqrtf(var + 1e-5f));
}

__global__ void bn_apply_kernel(const float* __restrict__ x, const float2* __restrict__ stats,
                                const float* __restrict__ gam, const float* __restrict__ bet,
                                float* __restrict__ y) {
    const int idx = blockIdx.x * 256 + threadIdx.x;
    const int e = idx * 4;
    const int c = (e / HW_) & 63;
    const float2 st = stats[c];
    const float g = gam[c], be = bet[c];
    float4 v = reinterpret_cast<const float4*>(x)[idx];
    v.x = (v.x - st.x) * st.y * g + be;
    v.y = (v.y - st.x) * st.y * g + be;
    v.z = (v.z - st.x) * st.y * g + be;
    v.w = (v.w - st.x) * st.y * g + be;
    reinterpret_cast<float4*>(y)[idx] = v;
}

// ---------------- 1x1 convs ----------------
__global__ void conv1x1_c32_kernel(const float* __restrict__ x, const float* __restrict__ wgt,
                                   const float* __restrict__ bias, float* __restrict__ yt) {
    __shared__ float sw[32][33];
    __shared__ float sb[32];
    const int tid = threadIdx.x;
    for (int i = tid; i < 1024; i += 256) sw[i >> 5][i & 31] = wgt[i];
    if (tid < 32) sb[tid] = bias[tid];
    __syncthreads();
    const int pos = blockIdx.x * 256 + tid;
    const int b = pos >> 15, i = pos & 32767;
    float xin[32];
#pragma unroll
    for (int ci = 0; ci < 32; ++ci) xin[ci] = x[((size_t)(b * 32 + ci)) * HW_ + i];
    float* out = yt + (size_t)pos * 32;
#pragma unroll
    for (int co = 0; co < 32; co += 4) {
        float4 a = make_float4(sb[co], sb[co + 1], sb[co + 2], sb[co + 3]);
#pragma unroll
        for (int ci = 0; ci < 32; ++ci) {
            const float xv = xin[ci];
            a.x += sw[co][ci] * xv; a.y += sw[co + 1][ci] * xv;
            a.z += sw[co + 2][ci] * xv; a.w += sw[co + 3][ci] * xv;
        }
        *reinterpret_cast<float4*>(out + co) = a;
    }
}

// v: 64->64, fp16 output [b][h][w][d]
__global__ void conv1x1_d64_kernel(const float* __restrict__ x, const float* __restrict__ wgt,
                                   const float* __restrict__ bias, __half* __restrict__ vth) {
    __shared__ float sw[64][65];
    __shared__ float sb[64];
    const int tid = threadIdx.x;
    for (int i = tid; i < 4096; i += 256) sw[i >> 6][i & 63] = wgt[i];
    if (tid < 64) sb[tid] = bias[tid];
    __syncthreads();
    const int pos = blockIdx.x * 256 + tid;
    const int b = pos >> 15, i = pos & 32767;
    float xin[64];
#pragma unroll
    for (int ci = 0; ci < 64; ++ci) xin[ci] = x[((size_t)(b * 64 + ci)) * HW_ + i];
    __half* out = vth + (size_t)pos * 64;
#pragma unroll
    for (int co = 0; co < 64; co += 4) {
        float4 a = make_float4(sb[co], sb[co + 1], sb[co + 2], sb[co + 3]);
#pragma unroll
        for (int ci = 0; ci < 64; ++ci) {
            const float xv = xin[ci];
            a.x += sw[co][ci] * xv; a.y += sw[co + 1][ci] * xv;
            a.z += sw[co + 2][ci] * xv; a.w += sw[co + 3][ci] * xv;
        }
        *reinterpret_cast<__half2*>(out + co)     = __floats2half2_rn(a.x, a.y);
        *reinterpret_cast<__half2*>(out + co + 2) = __floats2half2_rn(a.z, a.w);
    }
}

// ---------------- half-pack helpers ----------------
union H8pack { __half2 h2[4]; uint4 u; };
union H4pack { __half2 h2[2]; uint2 u; };

// ---------------- eH: scores -> fp16, diag=-inf ----------------
__global__ void eH_kernel(const float* __restrict__ qt, const float* __restrict__ kt,
                          __half* __restrict__ aHs) {
    const int w = blockIdx.x, b = blockIdx.y;
    const int tid = threadIdx.x;
    __shared__ float Qs[32][132];
    __shared__ float Ks[32][132];
    for (int i = tid; i < 4096; i += 256) {
        const int h = i >> 5, c = i & 31;
        const size_t gidx = (((size_t)b * HH + h) * WW + w) * 32 + c;
        Qs[c][h] = qt[gidx];
        Ks[c][h] = kt[gidx];
    }
    __syncthreads();
    const int hg = tid >> 4, gg = tid & 15;
    float acc[8][8];
#pragma unroll
    for (int i = 0; i < 8; ++i)
#pragma unroll
        for (int j = 0; j < 8; ++j) acc[i][j] = 0.f;
    for (int c = 0; c < 32; ++c) {
        float4 qa = *reinterpret_cast<float4*>(&Qs[c][hg * 8]);
        float4 qb = *reinterpret_cast<float4*>(&Qs[c][hg * 8 + 4]);
        float4 ka = *reinterpret_cast<float4*>(&Ks[c][gg * 8]);
        float4 kb = *reinterpret_cast<float4*>(&Ks[c][gg * 8 + 4]);
        float qv[8] = {qa.x, qa.y, qa.z, qa.w, qb.x, qb.y, qb.z, qb.w};
        float kv[8] = {ka.x, ka.y, ka.z, ka.w, kb.x, kb.y, kb.z, kb.w};
#pragma unroll
        for (int i = 0; i < 8; ++i)
#pragma unroll
            for (int j = 0; j < 8; ++j) acc[i][j] += qv[i] * kv[j];
    }
    const float ninf = __int_as_float(0xff800000);
#pragma unroll
    for (int i = 0; i < 8; ++i) {
        const int h = hg * 8 + i;
#pragma unroll
        for (int j = 0; j < 8; ++j) {
            const int g = gg * 8 + j;
            if (h == g) acc[i][j] = ninf;
        }
        H8pack p;
#pragma unroll
        for (int j = 0; j < 4; ++j)
            p.h2[j] = __floats2half2_rn(acc[i][2 * j], acc[i][2 * j + 1]);
        *reinterpret_cast<uint4*>(aHs + (((size_t)b * HH + h) * WW + w) * 128 + gg * 8) = p.u;
    }
}

// ---------------- eW: scores -> fp16 ----------------
__global__ void eW_kernel(const float* __restrict__ qt, const float* __restrict__ kt,
                          __half* __restrict__ aWs) {
    const int gc = blockIdx.x * 64;
    const int h = blockIdx.y, b = blockIdx.z;
    const int tid = threadIdx.x;
    __shared__ float Qs[32][260];
    __shared__ float Ks[32][68];
    const float* qbase = qt + (((size_t)b * HH + h) * WW) * 32;
    for (int i = tid; i < 8192; i += 256) { Qs[i & 31][i >> 5] = qbase[i]; }
    const float* kbase = kt + (((size_t)b * HH + h) * WW + gc) * 32;
    for (int i = tid; i < 2048; i += 256) { Ks[i & 31][i >> 5] = kbase[i]; }
    __syncthreads();
    const int wg = tid >> 3, gg = tid & 7;
    float acc[8][8];
#pragma unroll
    for (int i = 0; i < 8; ++i)
#pragma unroll
        for (int j = 0; j < 8; ++j) acc[i][j] = 0.f;
    for (int c = 0; c < 32; ++c) {
        float4 qa = *reinterpret_cast<float4*>(&Qs[c][wg * 8]);
        float4 qb = *reinterpret_cast<float4*>(&Qs[c][wg * 8 + 4]);
        float4 ka = *reinterpret_cast<float4*>(&Ks[c][gg * 8]);
        float4 kb = *reinterpret_cast<float4*>(&Ks[c][gg * 8 + 4]);
        float qv[8] = {qa.x, qa.y, qa.z, qa.w, qb.x, qb.y, qb.z, qb.w};
        float kv[8] = {ka.x, ka.y, ka.z, ka.w, kb.x, kb.y, kb.z, kb.w};
#pragma unroll
        for (int i = 0; i < 8; ++i)
#pragma unroll
            for (int j = 0; j < 8; ++j) acc[i][j] += qv[i] * kv[j];
    }
#pragma unroll
    for (int i = 0; i < 8; ++i) {
        const int w = wg * 8 + i;
        H8pack p;
#pragma unroll
        for (int j = 0; j < 4; ++j)
            p.h2[j] = __floats2half2_rn(acc[i][2 * j], acc[i][2 * j + 1]);
        *reinterpret_cast<uint4*>(aWs + (((size_t)b * HH + h) * WW + w) * 256 + gc + gg * 8) = p.u;
    }
}

// ---------------- fast exp ----------------
__device__ __forceinline__ float fexp(float x) {
    x = fmaxf(x, -80.f);
    const float y = x * 1.44269504f;
    const int e = __float2int_rn(y);
    const float f = y - (float)e;
    float p = 0.00133335581f;
    p = fmaf(p, f, 0.00961812910f);
    p = fmaf(p, f, 0.0555041086f);
    p = fmaf(p, f, 0.240226507f);
    p = fmaf(p, f, 0.693147182f);
    p = fmaf(p, f, 1.0f);
    return p * __int_as_float((e + 127) << 23);
}

// ---------------- softmax: fp16 scores in, fp16 weights out ----------------
__global__ void softmax_kernel(const __half* __restrict__ aHs, const __half* __restrict__ aWs,
                               __half* __restrict__ aHh, __half* __restrict__ aWh) {
    const int row = blockIdx.x * 8 + (threadIdx.x >> 5);
    const int lane = threadIdx.x & 31;
    const uint2* ph = reinterpret_cast<const uint2*>(aHs) + (size_t)row * 32;
    const uint2* pw = reinterpret_cast<const uint2*>(aWs) + (size_t)row * 64;
    H4pack ih, iw0, iw1;
    ih.u = ph[lane];
    iw0.u = pw[lane];
    iw1.u = pw[lane + 32];
    float2 h01 = __half22float2(ih.h2[0]);
    float2 h23 = __half22float2(ih.h2[1]);
    float2 w01 = __half22float2(iw0.h2[0]);
    float2 w23 = __half22float2(iw0.h2[1]);
    float2 w45 = __half22float2(iw1.h2[0]);
    float2 w67 = __half22float2(iw1.h2[1]);
    float4 vh  = make_float4(h01.x, h01.y, h23.x, h23.y);
    float4 vw0 = make_float4(w01.x, w01.y, w23.x, w23.y);
    float4 vw1 = make_float4(w45.x, w45.y, w67.x, w67.y);
    float m = fmaxf(fmaxf(fmaxf(vh.x, vh.y), fmaxf(vh.z, vh.w)),
              fmaxf(fmaxf(fmaxf(vw0.x, vw0.y), fmaxf(vw0.z, vw0.w)),
                    fmaxf(fmaxf(fmaxf(vw1.x, vw1.y), fmaxf(vw1.z, vw1.w)), -1e30f)));
#pragma unroll
    for (int o = 16; o; o >>= 1) m = fmaxf(m, __shfl_xor_sync(0xffffffffu, m, o));
    vh.x = fexp(vh.x - m); vh.y = fexp(vh.y - m); vh.z = fexp(vh.z - m); vh.w = fexp(vh.w - m);
    vw0.x = fexp(vw0.x - m); vw0.y = fexp(vw0.y - m); vw0.z = fexp(vw0.z - m); vw0.w = fexp(vw0.w - m);
    vw1.x = fexp(vw1.x - m); vw1.y = fexp(vw1.y - m); vw1.z = fexp(vw1.z - m); vw1.w = fexp(vw1.w - m);
    float s = vh.x + vh.y + vh.z + vh.w + vw0.x + vw0.y + vw0.z + vw0.w + vw1.x + vw1.y + vw1.z + vw1.w;
#pragma unroll
    for (int o = 16; o; o >>= 1) s += __shfl_xor_sync(0xffffffffu, s, o);
    const float inv = 1.f / s;
    H4pack p0, p1, p2;
    p0.h2[0] = __floats2half2_rn(vh.x * inv, vh.y * inv);
    p0.h2[1] = __floats2half2_rn(vh.z * inv, vh.w * inv);
    p1.h2[0] = __floats2half2_rn(vw0.x * inv, vw0.y * inv);
    p1.h2[1] = __floats2half2_rn(vw0.z * inv, vw0.w * inv);
    p2.h2[0] = __floats2half2_rn(vw1.x * inv, vw1.y * inv);
    p2.h2[1] = __floats2half2_rn(vw1.z * inv, vw1.w * inv);
    reinterpret_cast<uint2*>(aHh)[(size_t)row * 32 + lane] = p0.u;
    uint2* pwh = reinterpret_cast<uint2*>(aWh) + (size_t)row * 64;
    pwh[lane] = p1.u;
    pwh[lane + 32] = p2.u;
}

// ---------------- oH via HMMA: per (b,w): O[h,d] = sum_g aH[h,g]*v[g,d] ----------------
#define ATT_SSTRIDE 136
#define ATT_SMEM ((128*ATT_SSTRIDE + 64*ATT_SSTRIDE) * 2)   // 52224 bytes

__global__ void oH_kernel(const __half* __restrict__ vth, const __half* __restrict__ aHh,
                          __half* __restrict__ ohth) {
    extern __shared__ __half sh[];
    __half* As = sh;                       // [128 h][136] g-contiguous
    __half* Vs = sh + 128 * ATT_SSTRIDE;   // [64 d][136] g-contiguous (B col-major)
    const int w = blockIdx.x, b = blockIdx.y;
    const int tid = threadIdx.x;
    const int lane = tid & 31, warp = tid >> 5;
    const int g8 = lane >> 2, t2 = (lane & 3) * 2;

    for (int i = tid; i < 2048; i += 128) {
        const int row = i >> 4, ch = (i & 15) * 8;
        *reinterpret_cast<uint4*>(As + row * ATT_SSTRIDE + ch) =
            *reinterpret_cast<const uint4*>(aHh + (((size_t)b * HH + row) * WW + w) * 128 + ch);
    }
    for (int i = tid; i < 1024; i += 128) {
        const int g = i >> 3, dc = (i & 7) * 8;
        uint4 v = *reinterpret_cast<const uint4*>(vth + (((size_t)b * HH + g) * WW + w) * 64 + dc);
        __half tmp[8];
        *reinterpret_cast<uint4*>(tmp) = v;
#pragma unroll
        for (int j = 0; j < 8; ++j) Vs[(dc + j) * ATT_SSTRIDE + g] = tmp[j];
    }
    __syncthreads();

    float acc[2][8][4];
#pragma unroll
    for (int mi = 0; mi < 2; ++mi)
#pragma unroll
        for (int ni = 0; ni < 8; ++ni)
#pragma unroll
            for (int k = 0; k < 4; ++k) acc[mi][ni][k] = 0.f;

    const int h0 = warp * 32;
#pragma unroll
    for (int kb = 0; kb < 128; kb += 16) {
        uint32_t a[2][4];
#pragma unroll
        for (int mi = 0; mi < 2; ++mi) {
            const __half* ap = As + (h0 + mi * 16 + g8) * ATT_SSTRIDE + kb + t2;
            a[mi][0] = *reinterpret_cast<const uint32_t*>(ap);
            a[mi][1] = *reinterpret_cast<const uint32_t*>(ap + 8 * ATT_SSTRIDE);
            a[mi][2] = *reinterpret_cast<const uint32_t*>(ap + 8);
            a[mi][3] = *reinterpret_cast<const uint32_t*>(ap + 8 * ATT_SSTRIDE + 8);
        }
#pragma unroll
        for (int ni = 0; ni < 8; ++ni) {
            const __half* bp = Vs + (ni * 8 + g8) * ATT_SSTRIDE + kb + t2;
            const uint32_t b0 = *reinterpret_cast<const uint32_t*>(bp);
            const uint32_t b1 = *reinterpret_cast<const uint32_t*>(bp + 8);
            mma_f16(acc[0][ni], a[0][0], a[0][1], a[0][2], a[0][3], b0, b1);
            mma_f16(acc[1][ni], a[1][0], a[1][1], a[1][2], a[1][3], b0, b1);
        }
    }

#pragma unroll
    for (int mi = 0; mi < 2; ++mi)
#pragma unroll
        for (int ni = 0; ni < 8; ++ni) {
            const int h = h0 + mi * 16 + g8;
            const int d = ni * 8 + t2;
            *reinterpret_cast<__half2*>(ohth + (((size_t)b * HH + h) * WW + w) * 64 + d) =
                __floats2half2_rn(acc[mi][ni][0], acc[mi][ni][1]);
            *reinterpret_cast<__half2*>(ohth + (((size_t)b * HH + h + 8) * WW + w) * 64 + d) =
                __floats2half2_rn(acc[mi][ni][2], acc[mi][ni][3]);
        }
}

// ---------------- oW via HMMA + combine ----------------
__global__ void oW_combine_kernel(const __half* __restrict__ vth, const __half* __restrict__ aWh,
                                  const __half* __restrict__ ohth, const float* __restrict__ x,
                                  const float* __restrict__ gamma, float* __restrict__ xout) {
    extern __shared__ __half sh[];
    __half* As = sh;                       // [128 w][136]
    __half* Vs = sh + 128 * ATT_SSTRIDE;   // [64 d][136]
    const int wb = blockIdx.x * 128;
    const int h = blockIdx.y, b = blockIdx.z;
    const int tid = threadIdx.x;
    const int lane = tid & 31, warp = tid >> 5;
    const int g8 = lane >> 2, t2 = (lane & 3) * 2;

    float acc[2][8][4];
#pragma unroll
    for (int mi = 0; mi < 2; ++mi)
#pragma unroll
        for (int ni = 0; ni < 8; ++ni)
#pragma unroll
            for (int k = 0; k < 4; ++k) acc[mi][ni][k] = 0.f;

    const int w0 = warp * 32;
    for (int gc = 0; gc < 256; gc += 128) {
        __syncthreads();
        for (int i = tid; i < 2048; i += 128) {
            const int row = i >> 4, ch = (i & 15) * 8;
            *reinterpret_cast<uint4*>(As + row * ATT_SSTRIDE + ch) =
                *reinterpret_cast<const uint4*>(
                    aWh + (((size_t)b * HH + h) * WW + wb + row) * 256 + gc + ch);
        }
        for (int i = tid; i < 1024; i += 128) {
            const int g = i >> 3, dc = (i & 7) * 8;
            uint4 v = *reinterpret_cast<const uint4*>(
                vth + (((size_t)b * HH + h) * WW + gc + g) * 64 + dc);
            __half tmp[8];
            *reinterpret_cast<uint4*>(tmp) = v;
#pragma unroll
            for (int j = 0; j < 8; ++j) Vs[(dc + j) * ATT_SSTRIDE + g] = tmp[j];
        }
        __syncthreads();

#pragma unroll
        for (int kb = 0; kb < 128; kb += 16) {
            uint32_t a[2][4];
#pragma unroll
            for (int mi = 0; mi < 2; ++mi) {
                const __half* ap = As + (w0 + mi * 16 + g8) * ATT_SSTRIDE + kb + t2;
                a[mi][0] = *reinterpret_cast<const uint32_t*>(ap);
                a[mi][1] = *reinterpret_cast<const uint32_t*>(ap + 8 * ATT_SSTRIDE);
                a[mi][2] = *reinterpret_cast<const uint32_t*>(ap + 8);
                a[mi][3] = *reinterpret_cast<const uint32_t*>(ap + 8 * ATT_SSTRIDE + 8);
            }
#pragma unroll
            for (int ni = 0; ni < 8; ++ni) {
                const __half* bp = Vs + (ni * 8 + g8) * ATT_SSTRIDE + kb + t2;
                const uint32_t b0 = *reinterpret_cast<const uint32_t*>(bp);
                const uint32_t b1 = *reinterpret_cast<const uint32_t*>(bp + 8);
                mma_f16(acc[0][ni], a[0][0], a[0][1], a[0][2], a[0][3], b0, b1);
                mma_f16(acc[1][ni], a[1][0], a[1][1], a[1][2], a[1][3], b0, b1);
            }
        }
    }

    const float gam = *gamma;
#pragma unroll
    for (int mi = 0; mi < 2; ++mi)
#pragma unroll
        for (int ni = 0; ni < 8; ++ni) {
            const int d = ni * 8 + t2;
#pragma unroll
            for (int half = 0; half < 2; ++half) {
                const int w = wb + w0 + mi * 16 + g8 + half * 8;
                const float cA = acc[mi][ni][half * 2];
                const float cB = acc[mi][ni][half * 2 + 1];
                const float2 ohf = __half22float2(*reinterpret_cast<const __half2*>(
                    ohth + (((size_t)b * HH + h) * WW + w) * 64 + d));
                const size_t x0 = ((size_t)(b * 64 + d)) * HW_ + (size_t)h * WW + w;
                const size_t x1 = ((size_t)(b * 64 + d + 1)) * HW_ + (size_t)h * WW + w;
                xout[x0] = gam * (cA + ohf.x) + x[x0];
                xout[x1] = gam * (cB + ohf.y) + x[x1];
            }
        }
}

// ---------------- host ----------------
extern "C" void kernel_launch(void* const* d_in, const int* in_sizes, int n_in,
                              void* d_out, int out_size) {
    const float* cost  = (const float*)d_in[0];
    const float* lf0   = (const float*)d_in[1];
    const float* lf1   = (const float*)d_in[2];
    const float* Wa    = (const float*)d_in[3];
    const float* bn_ag = (const float*)d_in[4];
    const float* bn_ab = (const float*)d_in[5];
    const float* Wq    = (const float*)d_in[6];
    const float* bq    = (const float*)d_in[7];
    const float* Wk    = (const float*)d_in[8];
    const float* bk    = (const float*)d_in[9];
    const float* Wv    = (const float*)d_in[10];
    const float* bv    = (const float*)d_in[11];
    const float* gamma = (const float*)d_in[12];
    const float* Wb    = (const float*)d_in[13];
    const float* bn_bg = (const float*)d_in[14];
    const float* bn_bb = (const float*)d_in[15];
    float* out = (float*)d_out;

    float *conv, *xA, *xB, *qt, *kt;
    __half *vth, *ohth, *aHs, *aWs, *aHh, *aWh, *wth;
    float2 *part, *stats;
    cudaGetSymbolAddress((void**)&conv, g_conv);
    cudaGetSymbolAddress((void**)&xA, g_xA);
    cudaGetSymbolAddress((void**)&xB, g_xB);
    cudaGetSymbolAddress((void**)&vth, g_vth);
    cudaGetSymbolAddress((void**)&ohth, g_ohth);
    cudaGetSymbolAddress((void**)&qt, g_qt);
    cudaGetSymbolAddress((void**)&kt, g_kt);
    cudaGetSymbolAddress((void**)&aHs, g_aHs);
    cudaGetSymbolAddress((void**)&aWs, g_aWs);
    cudaGetSymbolAddress((void**)&aHh, g_aHh);
    cudaGetSymbolAddress((void**)&aWh, g_aWh);
    cudaGetSymbolAddress((void**)&wth, g_wth);
    cudaGetSymbolAddress((void**)&part, g_part);
    cudaGetSymbolAddress((void**)&stats, g_stats);

    // Idempotent, called unconditionally (no static guards — harness rule).
    cudaFuncSetAttribute(conv3x3_mma_kernel,
                         cudaFuncAttributeMaxDynamicSharedMemorySize, CONV_SMEM);
    cudaFuncSetAttribute(oH_kernel,
                         cudaFuncAttributeMaxDynamicSharedMemorySize, ATT_SMEM);
    cudaFuncSetAttribute(oW_combine_kernel,
                         cudaFuncAttributeMaxDynamicSharedMemorySize, ATT_SMEM);

    // Launch order keeps conv3x3 at capture index 3 (ncu -s5 -c1 lands there).
    conv1x1_c32_kernel<<<512, 256>>>(lf0, Wq, bq, qt);           // 0
    conv1x1_c32_kernel<<<512, 256>>>(lf1, Wk, bk, kt);           // 1
    wtrans_kernel<<<144, 256>>>(Wa, wth);                        // 2
    conv3x3_mma_kernel<<<dim3(4, 64, 4), 256, CONV_SMEM>>>(cost, wth, conv);  // 3 <- profiled

    // attention maps (invariant across recurrence)
    eH_kernel<<<dim3(256, 4), 256>>>(qt, kt, aHs);
    eW_kernel<<<dim3(4, 128, 4), 256>>>(qt, kt, aWs);
    softmax_kernel<<<16384, 256>>>(aHs, aWs, aHh, aWh);

    // BN for stage A
    bn_reduce_kernel<<<dim3(64, 8), 256>>>(conv, part);
    bn_finalize_kernel<<<1, 64>>>(part, stats);
    bn_apply_kernel<<<8192, 256>>>(conv, stats, bn_ag, bn_ab, xA);

    // Stage C: 2 recurrence iterations (attention aggregation on tensor cores)
    float* cur = xA;
    float* nxt = xB;
    for (int it = 0; it < 2; ++it) {
        conv1x1_d64_kernel<<<512, 256>>>(cur, Wv, bv, vth);
        oH_kernel<<<dim3(256, 4), 128, ATT_SMEM>>>(vth, aHh, ohth);
        oW_combine_kernel<<<dim3(2, 128, 4), 128, ATT_SMEM>>>(vth, aWh, ohth, cur, gamma, nxt);
        float* t = cur; cur = nxt; nxt = t;
    }

    // Stage D: conv3x3(cur, Wb) + BN -> out
    wtrans_kernel<<<144, 256>>>(Wb, wth);
    conv3x3_mma_kernel<<<dim3(4, 64, 4), 256, CONV_SMEM>>>(cur, wth, conv);
    bn_reduce_kernel<<<dim3(64, 8), 256>>>(conv, part);
    bn_finalize_kernel<<<1, 64>>>(part, stats);
    bn_apply_kernel<<<8192, 256>>>(conv, stats, bn_bg, bn_bb, out);
}

// round 10
// speedup vs baseline: 2.9253x; 1.1654x over previous
#include <cuda_runtime.h>
#include <cuda_fp16.h>
#include <cstdint>
#include <cstddef>

#define BB 4
#define CC 32
#define DD 64
#define HH 128
#define WW 256
#define HW_ (HH*WW)          // 32768
#define BDHW_ (BB*DD*HW_)    // 8388608
#define BCHW_ (BB*CC*HW_)    // 4194304

// ---------------- scratch (static device globals; no allocation) ----------------
__device__ float g_conv[BDHW_];
__device__ float g_xA[BDHW_];
__device__ float g_xB[BDHW_];
__device__ __half g_vth[BDHW_];      // v fp16, [b][h][w][d]
__device__ __half g_ohth[BDHW_];     // oH fp16, [b][h][w][d]
__device__ __half g_qth[BCHW_];      // q fp16, [b][h][w][c]
__device__ __half g_kth[BCHW_];      // k fp16, [b][h][w][c]
__device__ __half g_aHs[BB*HH*WW*HH];  // fp16 scores (H part)
__device__ __half g_aWs[BB*HH*WW*WW];  // fp16 scores (W part)
__device__ __half g_aHh[BB*HH*WW*HH];  // fp16 normalized weights
__device__ __half g_aWh[BB*HH*WW*WW];
__device__ __half g_wth[9*64*64];    // fp16 conv weights [t][d][c]
__device__ float2 g_part[64*8];
__device__ float2 g_stats[64];

// ---------------- weight transform: W[d][c][3][3] -> wth[t][d][c], fp16 ----------------
__global__ void wtrans_kernel(const float* __restrict__ W, __half* __restrict__ wth) {
    const int i = blockIdx.x * 256 + threadIdx.x;
    if (i >= 9 * 64 * 64) return;
    const int t = i >> 12;
    const int d = (i >> 6) & 63;
    const int c = i & 63;
    wth[i] = __float2half(W[((d * 64 + c) * 9) + t]);
}

// ---------------- common mma.f16 ----------------
__device__ __forceinline__ void mma_f16(float* c, uint32_t a0, uint32_t a1, uint32_t a2, uint32_t a3,
                                        uint32_t b0, uint32_t b1) {
    asm volatile("mma.sync.aligned.m16n8k16.row.col.f32.f16.f16.f32 "
                 "{%0,%1,%2,%3}, {%4,%5,%6,%7}, {%8,%9}, {%0,%1,%2,%3};"
                 : "+f"(c[0]), "+f"(c[1]), "+f"(c[2]), "+f"(c[3])
                 : "r"(a0), "r"(a1), "r"(a2), "r"(a3), "r"(b0), "r"(b1));
}

// ---------------- conv3x3 via fp16 mma.sync m16n8k16, 2 h-rows per block ----------------
#define CXS_STRIDE 72
#define CXS_HALVES (4*66*72)    // 19008
#define CWS_HALVES (64*72)      // 4608
#define CONV_SMEM ((CXS_HALVES + CWS_HALVES) * 2)   // 47232 bytes

__global__ __launch_bounds__(256)
void conv3x3_mma_kernel(const float* __restrict__ x, const __half* __restrict__ wth,
                        float* __restrict__ y) {
    extern __shared__ __half shc[];
    __half* xs = shc;                  // [(r*66+col)][72]
    __half* ws = shc + CXS_HALVES;     // [d][72]

    const int w0 = blockIdx.x * 64;
    const int h0 = blockIdx.y * 2;
    const int b  = blockIdx.z;
    const int tid = threadIdx.x;
    const int lane = tid & 31;
    const int warp = tid >> 5;
    const int hsel = warp >> 2;
    const int d0 = (warp & 3) * 16;
    const int g8 = lane >> 2;
    const int t2 = (lane & 3) * 2;

    for (int i = tid; i < 64 * 4 * 66; i += 256) {
        const int c = i / 264;
        const int rem = i - c * 264;
        const int r = rem / 66;
        const int col = rem - r * 66;
        const int gh = h0 + r - 1;
        const int gw = w0 + col - 1;
        float v = 0.f;
        if (gh >= 0 && gh < HH && gw >= 0 && gw < WW)
            v = x[((size_t)(b * 64 + c)) * HW_ + gh * WW + gw];
        xs[(r * 66 + col) * CXS_STRIDE + c] = __float2half(v);
    }

    float acc[8][4];
#pragma unroll
    for (int j = 0; j < 8; ++j)
#pragma unroll
        for (int k = 0; k < 4; ++k) acc[j][k] = 0.f;

    for (int t = 0; t < 9; ++t) {
        __syncthreads();
        const __half* wp = wth + t * 4096;
        for (int i = tid; i < 4096; i += 256)
            ws[(i >> 6) * CXS_STRIDE + (i & 63)] = wp[i];
        __syncthreads();

        const int dh = t / 3;
        const int dw = t - dh * 3;
        const int colrow = (hsel + dh) * 66 + dw;
#pragma unroll
        for (int kb = 0; kb < 64; kb += 16) {
            const __half* ap = ws + (d0 + g8) * CXS_STRIDE + kb + t2;
            const uint32_t a0 = *reinterpret_cast<const uint32_t*>(ap);
            const uint32_t a1 = *reinterpret_cast<const uint32_t*>(ap + 8 * CXS_STRIDE);
            const uint32_t a2 = *reinterpret_cast<const uint32_t*>(ap + 8);
            const uint32_t a3 = *reinterpret_cast<const uint32_t*>(ap + 8 * CXS_STRIDE + 8);
#pragma unroll
            for (int j = 0; j < 8; ++j) {
                const __half* bp = xs + (colrow + j * 8 + g8) * CXS_STRIDE + kb + t2;
                const uint32_t b0 = *reinterpret_cast<const uint32_t*>(bp);
                const uint32_t b1 = *reinterpret_cast<const uint32_t*>(bp + 8);
                mma_f16(acc[j], a0, a1, a2, a3, b0, b1);
            }
        }
    }

    const int h = h0 + hsel;
#pragma unroll
    for (int j = 0; j < 8; ++j) {
        const int w = w0 + j * 8 + t2;
        const size_t base = ((size_t)(b * 64 + d0 + g8)) * HW_ + (size_t)h * WW + w;
        *reinterpret_cast<float2*>(y + base) = make_float2(acc[j][0], acc[j][1]);
        *reinterpret_cast<float2*>(y + base + (size_t)8 * HW_) = make_float2(acc[j][2], acc[j][3]);
    }
}

// ---------------- batchnorm ----------------
__global__ void bn_reduce_kernel(const float* __restrict__ x, float2* __restrict__ part) {
    const int c = blockIdx.x, p = blockIdx.y;
    float s = 0.f, s2 = 0.f;
    const int base = p * 16384;
    for (int j = threadIdx.x; j < 16384; j += 256) {
        const int f = base + j;
        const int b = f >> 15;
        const int i = f & 32767;
        const float v = x[((size_t)(b * 64 + c)) * HW_ + i];
        s += v; s2 += v * v;
    }
    __shared__ float rs[8], rs2[8];
#pragma unroll
    for (int o = 16; o; o >>= 1) {
        s  += __shfl_xor_sync(0xffffffffu, s, o);
        s2 += __shfl_xor_sync(0xffffffffu, s2, o);
    }
    if ((threadIdx.x & 31) == 0) { rs[threadIdx.x >> 5] = s; rs2[threadIdx.x >> 5] = s2; }
    __syncthreads();
    if (threadIdx.x == 0) {
        float a = 0.f, b2 = 0.f;
        for (int k = 0; k < 8; ++k) { a += rs[k]; b2 += rs2[k]; }
        part[c * 8 + p] = make_float2(a, b2);
    }
}

__global__ void bn_finalize_kernel(const float2* __restrict__ part, float2* __restrict__ stats) {
    const int c = threadIdx.x;
    float s = 0.f, s2 = 0.f;
    for (int p = 0; p < 8; ++p) { s += part[c * 8 + p].x; s2 += part[c * 8 + p].y; }
    const float inv_n = 1.f / 131072.f;
    const float mean = s * inv_n;
    const float var  = s2 * inv_n - mean * mean;
    stats[c] = make_float2(mean, rsqrtf(var + 1e-5f));
}

__global__ void bn_apply_kernel(const float* __restrict__ x, const float2* __restrict__ stats,
                                const float* __restrict__ gam, const float* __restrict__ bet,
                                float* __restrict__ y) {
    const int idx = blockIdx.x * 256 + threadIdx.x;
    const int e = idx * 4;
    const int c = (e / HW_) & 63;
    const float2 st = stats[c];
    const float g = gam[c], be = bet[c];
    float4 v = reinterpret_cast<const float4*>(x)[idx];
    v.x = (v.x - st.x) * st.y * g + be;
    v.y = (v.y - st.x) * st.y * g + be;
    v.z = (v.z - st.x) * st.y * g + be;
    v.w = (v.w - st.x) * st.y * g + be;
    reinterpret_cast<float4*>(y)[idx] = v;
}

// ---------------- 1x1 convs ----------------
// q/k: 32->32, fp16 output [b][h][w][c]
__global__ void conv1x1_c32_kernel(const float* __restrict__ x, const float* __restrict__ wgt,
                                   const float* __restrict__ bias, __half* __restrict__ yt) {
    __shared__ float sw[32][33];
    __shared__ float sb[32];
    const int tid = threadIdx.x;
    for (int i = tid; i < 1024; i += 256) sw[i >> 5][i & 31] = wgt[i];
    if (tid < 32) sb[tid] = bias[tid];
    __syncthreads();
    const int pos = blockIdx.x * 256 + tid;
    const int b = pos >> 15, i = pos & 32767;
    float xin[32];
#pragma unroll
    for (int ci = 0; ci < 32; ++ci) xin[ci] = x[((size_t)(b * 32 + ci)) * HW_ + i];
    __half* out = yt + (size_t)pos * 32;
#pragma unroll
    for (int co = 0; co < 32; co += 4) {
        float4 a = make_float4(sb[co], sb[co + 1], sb[co + 2], sb[co + 3]);
#pragma unroll
        for (int ci = 0; ci < 32; ++ci) {
            const float xv = xin[ci];
            a.x += sw[co][ci] * xv; a.y += sw[co + 1][ci] * xv;
            a.z += sw[co + 2][ci] * xv; a.w += sw[co + 3][ci] * xv;
        }
        *reinterpret_cast<__half2*>(out + co)     = __floats2half2_rn(a.x, a.y);
        *reinterpret_cast<__half2*>(out + co + 2) = __floats2half2_rn(a.z, a.w);
    }
}

// v: 64->64, fp16 output [b][h][w][d]
__global__ void conv1x1_d64_kernel(const float* __restrict__ x, const float* __restrict__ wgt,
                                   const float* __restrict__ bias, __half* __restrict__ vth) {
    __shared__ float sw[64][65];
    __shared__ float sb[64];
    const int tid = threadIdx.x;
    for (int i = tid; i < 4096; i += 256) sw[i >> 6][i & 63] = wgt[i];
    if (tid < 64) sb[tid] = bias[tid];
    __syncthreads();
    const int pos = blockIdx.x * 256 + tid;
    const int b = pos >> 15, i = pos & 32767;
    float xin[64];
#pragma unroll
    for (int ci = 0; ci < 64; ++ci) xin[ci] = x[((size_t)(b * 64 + ci)) * HW_ + i];
    __half* out = vth + (size_t)pos * 64;
#pragma unroll
    for (int co = 0; co < 64; co += 4) {
        float4 a = make_float4(sb[co], sb[co + 1], sb[co + 2], sb[co + 3]);
#pragma unroll
        for (int ci = 0; ci < 64; ++ci) {
            const float xv = xin[ci];
            a.x += sw[co][ci] * xv; a.y += sw[co + 1][ci] * xv;
            a.z += sw[co + 2][ci] * xv; a.w += sw[co + 3][ci] * xv;
        }
        *reinterpret_cast<__half2*>(out + co)     = __floats2half2_rn(a.x, a.y);
        *reinterpret_cast<__half2*>(out + co + 2) = __floats2half2_rn(a.z, a.w);
    }
}

// ---------------- half-pack helpers ----------------
union H4pack { __half2 h2[2]; uint2 u; };

// ---------------- eH via HMMA: per (b,w): E[h,g] = q[h,:]·k[g,:], diag=-inf ----------------
// grid (256 w, 4 b), 256 threads (8 warps, each 16 h x 128 g). K=32.
#define ES_STRIDE 40

__global__ __launch_bounds__(256)
void eH_kernel(const __half* __restrict__ qth, const __half* __restrict__ kth,
               __half* __restrict__ aHs) {
    __shared__ __half Qs[128 * ES_STRIDE];
    __shared__ __half Ks[128 * ES_STRIDE];
    const int w = blockIdx.x, b = blockIdx.y;
    const int tid = threadIdx.x;
    const int lane = tid & 31, warp = tid >> 5;
    const int g8 = lane >> 2, t2 = (lane & 3) * 2;

    for (int i = tid; i < 512; i += 256) {
        const int row = i >> 2, seg = (i & 3) * 8;
        const size_t gidx = (((size_t)b * HH + row) * WW + w) * 32 + seg;
        *reinterpret_cast<uint4*>(Qs + row * ES_STRIDE + seg) =
            *reinterpret_cast<const uint4*>(qth + gidx);
        *reinterpret_cast<uint4*>(Ks + row * ES_STRIDE + seg) =
            *reinterpret_cast<const uint4*>(kth + gidx);
    }
    __syncthreads();

    float acc[16][4];
#pragma unroll
    for (int ni = 0; ni < 16; ++ni)
#pragma unroll
        for (int k = 0; k < 4; ++k) acc[ni][k] = 0.f;

    const int h0 = warp * 16;
#pragma unroll
    for (int kb = 0; kb < 32; kb += 16) {
        const __half* ap = Qs + (h0 + g8) * ES_STRIDE + kb + t2;
        const uint32_t a0 = *reinterpret_cast<const uint32_t*>(ap);
        const uint32_t a1 = *reinterpret_cast<const uint32_t*>(ap + 8 * ES_STRIDE);
        const uint32_t a2 = *reinterpret_cast<const uint32_t*>(ap + 8);
        const uint32_t a3 = *reinterpret_cast<const uint32_t*>(ap + 8 * ES_STRIDE + 8);
#pragma unroll
        for (int ni = 0; ni < 16; ++ni) {
            const __half* bp = Ks + (ni * 8 + g8) * ES_STRIDE + kb + t2;
            const uint32_t b0 = *reinterpret_cast<const uint32_t*>(bp);
            const uint32_t b1 = *reinterpret_cast<const uint32_t*>(bp + 8);
            mma_f16(acc[ni], a0, a1, a2, a3, b0, b1);
        }
    }

    const float ninf = __int_as_float(0xff800000);
    const int h1 = h0 + g8, h2 = h1 + 8;
#pragma unroll
    for (int ni = 0; ni < 16; ++ni) {
        const int g = ni * 8 + t2;
        const float c0 = (h1 == g)     ? ninf : acc[ni][0];
        const float c1 = (h1 == g + 1) ? ninf : acc[ni][1];
        const float c2 = (h2 == g)     ? ninf : acc[ni][2];
        const float c3 = (h2 == g + 1) ? ninf : acc[ni][3];
        *reinterpret_cast<__half2*>(aHs + (((size_t)b * HH + h1) * WW + w) * 128 + g) =
            __floats2half2_rn(c0, c1);
        *reinterpret_cast<__half2*>(aHs + (((size_t)b * HH + h2) * WW + w) * 128 + g) =
            __floats2half2_rn(c2, c3);
    }
}

// ---------------- eW via HMMA: per (b,h,gc): E[w,g] = q[w,:]·k[g,:] ----------------
// grid (4 gc, 128 h, 4 b), 256 threads (8 warps, each 32 w x 64 g). K=32.
__global__ __launch_bounds__(256)
void eW_kernel(const __half* __restrict__ qth, const __half* __restrict__ kth,
               __half* __restrict__ aWs) {
    __shared__ __half Qs[256 * ES_STRIDE];
    __shared__ __half Ks[64 * ES_STRIDE];
    const int gc = blockIdx.x * 64;
    const int h = blockIdx.y, b = blockIdx.z;
    const int tid = threadIdx.x;
    const int lane = tid & 31, warp = tid >> 5;
    const int g8 = lane >> 2, t2 = (lane & 3) * 2;

    const __half* qbase = qth + (((size_t)b * HH + h) * WW) * 32;
    for (int i = tid; i < 1024; i += 256) {
        const int row = i >> 2, seg = (i & 3) * 8;
        *reinterpret_cast<uint4*>(Qs + row * ES_STRIDE + seg) =
            *reinterpret_cast<const uint4*>(qbase + row * 32 + seg);
    }
    const __half* kbase = kth + (((size_t)b * HH + h) * WW + gc) * 32;
    {
        const int i = tid;  // 64 rows x 4 segs = 256 = blockDim
        const int row = i >> 2, seg = (i & 3) * 8;
        *reinterpret_cast<uint4*>(Ks + row * ES_STRIDE + seg) =
            *reinterpret_cast<const uint4*>(kbase + row * 32 + seg);
    }
    __syncthreads();

    float acc[2][8][4];
#pragma unroll
    for (int mi = 0; mi < 2; ++mi)
#pragma unroll
        for (int ni = 0; ni < 8; ++ni)
#pragma unroll
            for (int k = 0; k < 4; ++k) acc[mi][ni][k] = 0.f;

    const int w0 = warp * 32;
#pragma unroll
    for (int kb = 0; kb < 32; kb += 16) {
        uint32_t a[2][4];
#pragma unroll
        for (int mi = 0; mi < 2; ++mi) {
            const __half* ap = Qs + (w0 + mi * 16 + g8) * ES_STRIDE + kb + t2;
            a[mi][0] = *reinterpret_cast<const uint32_t*>(ap);
            a[mi][1] = *reinterpret_cast<const uint32_t*>(ap + 8 * ES_STRIDE);
            a[mi][2] = *reinterpret_cast<const uint32_t*>(ap + 8);
            a[mi][3] = *reinterpret_cast<const uint32_t*>(ap + 8 * ES_STRIDE + 8);
        }
#pragma unroll
        for (int ni = 0; ni < 8; ++ni) {
            const __half* bp = Ks + (ni * 8 + g8) * ES_STRIDE + kb + t2;
            const uint32_t b0 = *reinterpret_cast<const uint32_t*>(bp);
            const uint32_t b1 = *reinterpret_cast<const uint32_t*>(bp + 8);
            mma_f16(acc[0][ni], a[0][0], a[0][1], a[0][2], a[0][3], b0, b1);
            mma_f16(acc[1][ni], a[1][0], a[1][1], a[1][2], a[1][3], b0, b1);
        }
    }

#pragma unroll
    for (int mi = 0; mi < 2; ++mi) {
        const int w1 = w0 + mi * 16 + g8, w2 = w1 + 8;
#pragma unroll
        for (int ni = 0; ni < 8; ++ni) {
            const int g = gc + ni * 8 + t2;
            *reinterpret_cast<__half2*>(aWs + (((size_t)b * HH + h) * WW + w1) * 256 + g) =
                __floats2half2_rn(acc[mi][ni][0], acc[mi][ni][1]);
            *reinterpret_cast<__half2*>(aWs + (((size_t)b * HH + h) * WW + w2) * 256 + g) =
                __floats2half2_rn(acc[mi][ni][2], acc[mi][ni][3]);
        }
    }
}

// ---------------- fast exp ----------------
__device__ __forceinline__ float fexp(float x) {
    x = fmaxf(x, -80.f);
    const float y = x * 1.44269504f;
    const int e = __float2int_rn(y);
    const float f = y - (float)e;
    float p = 0.00133335581f;
    p = fmaf(p, f, 0.00961812910f);
    p = fmaf(p, f, 0.0555041086f);
    p = fmaf(p, f, 0.240226507f);
    p = fmaf(p, f, 0.693147182f);
    p = fmaf(p, f, 1.0f);
    return p * __int_as_float((e + 127) << 23);
}

// ---------------- softmax: fp16 scores in, fp16 weights out ----------------
__global__ void softmax_kernel(const __half* __restrict__ aHs, const __half* __restrict__ aWs,
                               __half* __restrict__ aHh, __half* __restrict__ aWh) {
    const int row = blockIdx.x * 8 + (threadIdx.x >> 5);
    const int lane = threadIdx.x & 31;
    const uint2* ph = reinterpret_cast<const uint2*>(aHs) + (size_t)row * 32;
    const uint2* pw = reinterpret_cast<const uint2*>(aWs) + (size_t)row * 64;
    H4pack ih, iw0, iw1;
    ih.u = ph[lane];
    iw0.u = pw[lane];
    iw1.u = pw[lane + 32];
    float2 h01 = __half22float2(ih.h2[0]);
    float2 h23 = __half22float2(ih.h2[1]);
    float2 w01 = __half22float2(iw0.h2[0]);
    float2 w23 = __half22float2(iw0.h2[1]);
    float2 w45 = __half22float2(iw1.h2[0]);
    float2 w67 = __half22float2(iw1.h2[1]);
    float4 vh  = make_float4(h01.x, h01.y, h23.x, h23.y);
    float4 vw0 = make_float4(w01.x, w01.y, w23.x, w23.y);
    float4 vw1 = make_float4(w45.x, w45.y, w67.x, w67.y);
    float m = fmaxf(fmaxf(fmaxf(vh.x, vh.y), fmaxf(vh.z, vh.w)),
              fmaxf(fmaxf(fmaxf(vw0.x, vw0.y), fmaxf(vw0.z, vw0.w)),
                    fmaxf(fmaxf(fmaxf(vw1.x, vw1.y), fmaxf(vw1.z, vw1.w)), -1e30f)));
#pragma unroll
    for (int o = 16; o; o >>= 1) m = fmaxf(m, __shfl_xor_sync(0xffffffffu, m, o));
    vh.x = fexp(vh.x - m); vh.y = fexp(vh.y - m); vh.z = fexp(vh.z - m); vh.w = fexp(vh.w - m);
    vw0.x = fexp(vw0.x - m); vw0.y = fexp(vw0.y - m); vw0.z = fexp(vw0.z - m); vw0.w = fexp(vw0.w - m);
    vw1.x = fexp(vw1.x - m); vw1.y = fexp(vw1.y - m); vw1.z = fexp(vw1.z - m); vw1.w = fexp(vw1.w - m);
    float s = vh.x + vh.y + vh.z + vh.w + vw0.x + vw0.y + vw0.z + vw0.w + vw1.x + vw1.y + vw1.z + vw1.w;
#pragma unroll
    for (int o = 16; o; o >>= 1) s += __shfl_xor_sync(0xffffffffu, s, o);
    const float inv = 1.f / s;
    H4pack p0, p1, p2;
    p0.h2[0] = __floats2half2_rn(vh.x * inv, vh.y * inv);
    p0.h2[1] = __floats2half2_rn(vh.z * inv, vh.w * inv);
    p1.h2[0] = __floats2half2_rn(vw0.x * inv, vw0.y * inv);
    p1.h2[1] = __floats2half2_rn(vw0.z * inv, vw0.w * inv);
    p2.h2[0] = __floats2half2_rn(vw1.x * inv, vw1.y * inv);
    p2.h2[1] = __floats2half2_rn(vw1.z * inv, vw1.w * inv);
    reinterpret_cast<uint2*>(aHh)[(size_t)row * 32 + lane] = p0.u;
    uint2* pwh = reinterpret_cast<uint2*>(aWh) + (size_t)row * 64;
    pwh[lane] = p1.u;
    pwh[lane + 32] = p2.u;
}

// ---------------- oH via HMMA: per (b,w): O[h,d] = sum_g aH[h,g]*v[g,d] ----------------
#define ATT_SSTRIDE 136
#define ATT_SMEM ((128*ATT_SSTRIDE + 64*ATT_SSTRIDE) * 2)   // 52224 bytes

__global__ void oH_kernel(const __half* __restrict__ vth, const __half* __restrict__ aHh,
                          __half* __restrict__ ohth) {
    extern __shared__ __half sh[];
    __half* As = sh;                       // [128 h][136] g-contiguous
    __half* Vs = sh + 128 * ATT_SSTRIDE;   // [64 d][136] g-contiguous (B col-major)
    const int w = blockIdx.x, b = blockIdx.y;
    const int tid = threadIdx.x;
    const int lane = tid & 31, warp = tid >> 5;
    const int g8 = lane >> 2, t2 = (lane & 3) * 2;

    for (int i = tid; i < 2048; i += 128) {
        const int row = i >> 4, ch = (i & 15) * 8;
        *reinterpret_cast<uint4*>(As + row * ATT_SSTRIDE + ch) =
            *reinterpret_cast<const uint4*>(aHh + (((size_t)b * HH + row) * WW + w) * 128 + ch);
    }
    for (int i = tid; i < 1024; i += 128) {
        const int g = i >> 3, dc = (i & 7) * 8;
        uint4 v = *reinterpret_cast<const uint4*>(vth + (((size_t)b * HH + g) * WW + w) * 64 + dc);
        __half tmp[8];
        *reinterpret_cast<uint4*>(tmp) = v;
#pragma unroll
        for (int j = 0; j < 8; ++j) Vs[(dc + j) * ATT_SSTRIDE + g] = tmp[j];
    }
    __syncthreads();

    float acc[2][8][4];
#pragma unroll
    for (int mi = 0; mi < 2; ++mi)
#pragma unroll
        for (int ni = 0; ni < 8; ++ni)
#pragma unroll
            for (int k = 0; k < 4; ++k) acc[mi][ni][k] = 0.f;

    const int h0 = warp * 32;
#pragma unroll
    for (int kb = 0; kb < 128; kb += 16) {
        uint32_t a[2][4];
#pragma unroll
        for (int mi = 0; mi < 2; ++mi) {
            const __half* ap = As + (h0 + mi * 16 + g8) * ATT_SSTRIDE + kb + t2;
            a[mi][0] = *reinterpret_cast<const uint32_t*>(ap);
            a[mi][1] = *reinterpret_cast<const uint32_t*>(ap + 8 * ATT_SSTRIDE);
            a[mi][2] = *reinterpret_cast<const uint32_t*>(ap + 8);
            a[mi][3] = *reinterpret_cast<const uint32_t*>(ap + 8 * ATT_SSTRIDE + 8);
        }
#pragma unroll
        for (int ni = 0; ni < 8; ++ni) {
            const __half* bp = Vs + (ni * 8 + g8) * ATT_SSTRIDE + kb + t2;
            const uint32_t b0 = *reinterpret_cast<const uint32_t*>(bp);
            const uint32_t b1 = *reinterpret_cast<const uint32_t*>(bp + 8);
            mma_f16(acc[0][ni], a[0][0], a[0][1], a[0][2], a[0][3], b0, b1);
            mma_f16(acc[1][ni], a[1][0], a[1][1], a[1][2], a[1][3], b0, b1);
        }
    }

#pragma unroll
    for (int mi = 0; mi < 2; ++mi)
#pragma unroll
        for (int ni = 0; ni < 8; ++ni) {
            const int h = h0 + mi * 16 + g8;
            const int d = ni * 8 + t2;
            *reinterpret_cast<__half2*>(ohth + (((size_t)b * HH + h) * WW + w) * 64 + d) =
                __floats2half2_rn(acc[mi][ni][0], acc[mi][ni][1]);
            *reinterpret_cast<__half2*>(ohth + (((size_t)b * HH + h + 8) * WW + w) * 64 + d) =
                __floats2half2_rn(acc[mi][ni][2], acc[mi][ni][3]);
        }
}

// ---------------- oW via HMMA + combine ----------------
__global__ void oW_combine_kernel(const __half* __restrict__ vth, const __half* __restrict__ aWh,
                                  const __half* __restrict__ ohth, const float* __restrict__ x,
                                  const float* __restrict__ gamma, float* __restrict__ xout) {
    extern __shared__ __half sh[];
    __half* As = sh;                       // [128 w][136]
    __half* Vs = sh + 128 * ATT_SSTRIDE;   // [64 d][136]
    const int wb = blockIdx.x * 128;
    const int h = blockIdx.y, b = blockIdx.z;
    const int tid = threadIdx.x;
    const int lane = tid & 31, warp = tid >> 5;
    const int g8 = lane >> 2, t2 = (lane & 3) * 2;

    float acc[2][8][4];
#pragma unroll
    for (int mi = 0; mi < 2; ++mi)
#pragma unroll
        for (int ni = 0; ni < 8; ++ni)
#pragma unroll
            for (int k = 0; k < 4; ++k) acc[mi][ni][k] = 0.f;

    const int w0 = warp * 32;
    for (int gc = 0; gc < 256; gc += 128) {
        __syncthreads();
        for (int i = tid; i < 2048; i += 128) {
            const int row = i >> 4, ch = (i & 15) * 8;
            *reinterpret_cast<uint4*>(As + row * ATT_SSTRIDE + ch) =
                *reinterpret_cast<const uint4*>(
                    aWh + (((size_t)b * HH + h) * WW + wb + row) * 256 + gc + ch);
        }
        for (int i = tid; i < 1024; i += 128) {
            const int g = i >> 3, dc = (i & 7) * 8;
            uint4 v = *reinterpret_cast<const uint4*>(
                vth + (((size_t)b * HH + h) * WW + gc + g) * 64 + dc);
            __half tmp[8];
            *reinterpret_cast<uint4*>(tmp) = v;
#pragma unroll
            for (int j = 0; j < 8; ++j) Vs[(dc + j) * ATT_SSTRIDE + g] = tmp[j];
        }
        __syncthreads();

#pragma unroll
        for (int kb = 0; kb < 128; kb += 16) {
            uint32_t a[2][4];
#pragma unroll
            for (int mi = 0; mi < 2; ++mi) {
                const __half* ap = As + (w0 + mi * 16 + g8) * ATT_SSTRIDE + kb + t2;
                a[mi][0] = *reinterpret_cast<const uint32_t*>(ap);
                a[mi][1] = *reinterpret_cast<const uint32_t*>(ap + 8 * ATT_SSTRIDE);
                a[mi][2] = *reinterpret_cast<const uint32_t*>(ap + 8);
                a[mi][3] = *reinterpret_cast<const uint32_t*>(ap + 8 * ATT_SSTRIDE + 8);
            }
#pragma unroll
            for (int ni = 0; ni < 8; ++ni) {
                const __half* bp = Vs + (ni * 8 + g8) * ATT_SSTRIDE + kb + t2;
                const uint32_t b0 = *reinterpret_cast<const uint32_t*>(bp);
                const uint32_t b1 = *reinterpret_cast<const uint32_t*>(bp + 8);
                mma_f16(acc[0][ni], a[0][0], a[0][1], a[0][2], a[0][3], b0, b1);
                mma_f16(acc[1][ni], a[1][0], a[1][1], a[1][2], a[1][3], b0, b1);
            }
        }
    }

    const float gam = *gamma;
#pragma unroll
    for (int mi = 0; mi < 2; ++mi)
#pragma unroll
        for (int ni = 0; ni < 8; ++ni) {
            const int d = ni * 8 + t2;
#pragma unroll
            for (int half = 0; half < 2; ++half) {
                const int w = wb + w0 + mi * 16 + g8 + half * 8;
                const float cA = acc[mi][ni][half * 2];
                const float cB = acc[mi][ni][half * 2 + 1];
                const float2 ohf = __half22float2(*reinterpret_cast<const __half2*>(
                    ohth + (((size_t)b * HH + h) * WW + w) * 64 + d));
                const size_t x0 = ((size_t)(b * 64 + d)) * HW_ + (size_t)h * WW + w;
                const size_t x1 = ((size_t)(b * 64 + d + 1)) * HW_ + (size_t)h * WW + w;
                xout[x0] = gam * (cA + ohf.x) + x[x0];
                xout[x1] = gam * (cB + ohf.y) + x[x1];
            }
        }
}

// ---------------- host ----------------
extern "C" void kernel_launch(void* const* d_in, const int* in_sizes, int n_in,
                              void* d_out, int out_size) {
    const float* cost  = (const float*)d_in[0];
    const float* lf0   = (const float*)d_in[1];
    const float* lf1   = (const float*)d_in[2];
    const float* Wa    = (const float*)d_in[3];
    const float* bn_ag = (const float*)d_in[4];
    const float* bn_ab = (const float*)d_in[5];
    const float* Wq    = (const float*)d_in[6];
    const float* bq    = (const float*)d_in[7];
    const float* Wk    = (const float*)d_in[8];
    const float* bk    = (const float*)d_in[9];
    const float* Wv    = (const float*)d_in[10];
    const float* bv    = (const float*)d_in[11];
    const float* gamma = (const float*)d_in[12];
    const float* Wb    = (const float*)d_in[13];
    const float* bn_bg = (const float*)d_in[14];
    const float* bn_bb = (const float*)d_in[15];
    float* out = (float*)d_out;

    float *conv, *xA, *xB;
    __half *vth, *ohth, *qth, *kth, *aHs, *aWs, *aHh, *aWh, *wth;
    float2 *part, *stats;
    cudaGetSymbolAddress((void**)&conv, g_conv);
    cudaGetSymbolAddress((void**)&xA, g_xA);
    cudaGetSymbolAddress((void**)&xB, g_xB);
    cudaGetSymbolAddress((void**)&vth, g_vth);
    cudaGetSymbolAddress((void**)&ohth, g_ohth);
    cudaGetSymbolAddress((void**)&qth, g_qth);
    cudaGetSymbolAddress((void**)&kth, g_kth);
    cudaGetSymbolAddress((void**)&aHs, g_aHs);
    cudaGetSymbolAddress((void**)&aWs, g_aWs);
    cudaGetSymbolAddress((void**)&aHh, g_aHh);
    cudaGetSymbolAddress((void**)&aWh, g_aWh);
    cudaGetSymbolAddress((void**)&wth, g_wth);
    cudaGetSymbolAddress((void**)&part, g_part);
    cudaGetSymbolAddress((void**)&stats, g_stats);

    // Idempotent, called unconditionally (no static guards — harness rule).
    cudaFuncSetAttribute(conv3x3_mma_kernel,
                         cudaFuncAttributeMaxDynamicSharedMemorySize, CONV_SMEM);
    cudaFuncSetAttribute(oH_kernel,
                         cudaFuncAttributeMaxDynamicSharedMemorySize, ATT_SMEM);
    cudaFuncSetAttribute(oW_combine_kernel,
                         cudaFuncAttributeMaxDynamicSharedMemorySize, ATT_SMEM);

    // Launch order keeps conv3x3 at capture index 3 (ncu -s5 -c1 lands there).
    conv1x1_c32_kernel<<<512, 256>>>(lf0, Wq, bq, qth);          // 0
    conv1x1_c32_kernel<<<512, 256>>>(lf1, Wk, bk, kth);          // 1
    wtrans_kernel<<<144, 256>>>(Wa, wth);                        // 2
    conv3x3_mma_kernel<<<dim3(4, 64, 4), 256, CONV_SMEM>>>(cost, wth, conv);  // 3 <- profiled

    // attention maps (invariant across recurrence), now HMMA
    eH_kernel<<<dim3(256, 4), 256>>>(qth, kth, aHs);
    eW_kernel<<<dim3(4, 128, 4), 256>>>(qth, kth, aWs);
    softmax_kernel<<<16384, 256>>>(aHs, aWs, aHh, aWh);

    // BN for stage A
    bn_reduce_kernel<<<dim3(64, 8), 256>>>(conv, part);
    bn_finalize_kernel<<<1, 64>>>(part, stats);
    bn_apply_kernel<<<8192, 256>>>(conv, stats, bn_ag, bn_ab, xA);

    // Stage C: 2 recurrence iterations (attention aggregation on tensor cores)
    float* cur = xA;
    float* nxt = xB;
    for (int it = 0; it < 2; ++it) {
        conv1x1_d64_kernel<<<512, 256>>>(cur, Wv, bv, vth);
        oH_kernel<<<dim3(256, 4), 128, ATT_SMEM>>>(vth, aHh, ohth);
        oW_combine_kernel<<<dim3(2, 128, 4), 128, ATT_SMEM>>>(vth, aWh, ohth, cur, gamma, nxt);
        float* t = cur; cur = nxt; nxt = t;
    }

    // Stage D: conv3x3(cur, Wb) + BN -> out
    wtrans_kernel<<<144, 256>>>(Wb, wth);
    conv3x3_mma_kernel<<<dim3(4, 64, 4), 256, CONV_SMEM>>>(cur, wth, conv);
    bn_reduce_kernel<<<dim3(64, 8), 256>>>(conv, part);
    bn_finalize_kernel<<<1, 64>>>(part, stats);
    bn_apply_kernel<<<8192, 256>>>(conv, stats, bn_bg, bn_bb, out);
}

// round 12
// speedup vs baseline: 3.0667x; 1.0483x over previous
#include <cuda_runtime.h>
#include <cuda_fp16.h>
#include <cstdint>
#include <cstddef>

#define BB 4
#define CC 32
#define DD 64
#define HH 128
#define WW 256
#define HW_ (HH*WW)          // 32768
#define BDHW_ (BB*DD*HW_)    // 8388608
#define BCHW_ (BB*CC*HW_)    // 4194304
#define NROWS (BB*HH*WW)     // 131072

// ---------------- scratch (static device globals; no allocation) ----------------
__device__ float g_conv[BDHW_];
__device__ float g_xA[BDHW_];
__device__ float g_xB[BDHW_];
__device__ __half g_vth[BDHW_];      // v fp16, [b][h][w][d]
__device__ __half g_ohth[BDHW_];     // oH fp16 (normalized), [b][h][w][d]
__device__ __half g_qth[BCHW_];      // q fp16, [b][h][w][c]
__device__ __half g_kth[BCHW_];      // k fp16, [b][h][w][c]
__device__ __half g_aHh[BB*HH*WW*HH];  // fp16 exp(scores) (H part)
__device__ __half g_aWh[BB*HH*WW*WW];  // fp16 exp(scores) (W part)
__device__ float g_rsum[NROWS];      // per-row softmax denominators
__device__ __half g_wth[9*64*64];    // fp16 conv weights [t][d][c]
__device__ float2 g_part[64*8];
__device__ float2 g_stats[64];

// ---------------- weight transform: W[d][c][3][3] -> wth[t][d][c], fp16 ----------------
__global__ void wtrans_kernel(const float* __restrict__ W, __half* __restrict__ wth) {
    const int i = blockIdx.x * 256 + threadIdx.x;
    if (i >= 9 * 64 * 64) return;
    const int t = i >> 12;
    const int d = (i >> 6) & 63;
    const int c = i & 63;
    wth[i] = __float2half(W[((d * 64 + c) * 9) + t]);
}

// ---------------- common mma.f16 ----------------
__device__ __forceinline__ void mma_f16(float* c, uint32_t a0, uint32_t a1, uint32_t a2, uint32_t a3,
                                        uint32_t b0, uint32_t b1) {
    asm volatile("mma.sync.aligned.m16n8k16.row.col.f32.f16.f16.f32 "
                 "{%0,%1,%2,%3}, {%4,%5,%6,%7}, {%8,%9}, {%0,%1,%2,%3};"
                 : "+f"(c[0]), "+f"(c[1]), "+f"(c[2]), "+f"(c[3])
                 : "r"(a0), "r"(a1), "r"(a2), "r"(a3), "r"(b0), "r"(b1));
}

// ---------------- fast exp (FMA/ALU pipes only) ----------------
__device__ __forceinline__ float fexp(float x) {
    x = fmaxf(x, -80.f);
    const float y = x * 1.44269504f;
    const int e = __float2int_rn(y);
    const float f = y - (float)e;
    float p = 0.00133335581f;
    p = fmaf(p, f, 0.00961812910f);
    p = fmaf(p, f, 0.0555041086f);
    p = fmaf(p, f, 0.240226507f);
    p = fmaf(p, f, 0.693147182f);
    p = fmaf(p, f, 1.0f);
    return p * __int_as_float((e + 127) << 23);
}

// ---------------- conv3x3 via fp16 mma.sync m16n8k16, 2 h-rows per block ----------------
#define CXS_STRIDE 72
#define CXS_HALVES (4*66*72)    // 19008
#define CWS_HALVES (64*72)      // 4608
#define CONV_SMEM ((CXS_HALVES + CWS_HALVES) * 2)   // 47232 bytes

__global__ __launch_bounds__(256)
void conv3x3_mma_kernel(const float* __restrict__ x, const __half* __restrict__ wth,
                        float* __restrict__ y) {
    extern __shared__ __half shc[];
    __half* xs = shc;                  // [(r*66+col)][72]
    __half* ws = shc + CXS_HALVES;     // [d][72]

    const int w0 = blockIdx.x * 64;
    const int h0 = blockIdx.y * 2;
    const int b  = blockIdx.z;
    const int tid = threadIdx.x;
    const int lane = tid & 31;
    const int warp = tid >> 5;
    const int hsel = warp >> 2;
    const int d0 = (warp & 3) * 16;
    const int g8 = lane >> 2;
    const int t2 = (lane & 3) * 2;

    for (int i = tid; i < 64 * 4 * 66; i += 256) {
        const int c = i / 264;
        const int rem = i - c * 264;
        const int r = rem / 66;
        const int col = rem - r * 66;
        const int gh = h0 + r - 1;
        const int gw = w0 + col - 1;
        float v = 0.f;
        if (gh >= 0 && gh < HH && gw >= 0 && gw < WW)
            v = x[((size_t)(b * 64 + c)) * HW_ + gh * WW + gw];
        xs[(r * 66 + col) * CXS_STRIDE + c] = __float2half(v);
    }

    float acc[8][4];
#pragma unroll
    for (int j = 0; j < 8; ++j)
#pragma unroll
        for (int k = 0; k < 4; ++k) acc[j][k] = 0.f;

    for (int t = 0; t < 9; ++t) {
        __syncthreads();
        const __half* wp = wth + t * 4096;
        for (int i = tid; i < 4096; i += 256)
            ws[(i >> 6) * CXS_STRIDE + (i & 63)] = wp[i];
        __syncthreads();

        const int dh = t / 3;
        const int dw = t - dh * 3;
        const int colrow = (hsel + dh) * 66 + dw;
#pragma unroll
        for (int kb = 0; kb < 64; kb += 16) {
            const __half* ap = ws + (d0 + g8) * CXS_STRIDE + kb + t2;
            const uint32_t a0 = *reinterpret_cast<const uint32_t*>(ap);
            const uint32_t a1 = *reinterpret_cast<const uint32_t*>(ap + 8 * CXS_STRIDE);
            const uint32_t a2 = *reinterpret_cast<const uint32_t*>(ap + 8);
            const uint32_t a3 = *reinterpret_cast<const uint32_t*>(ap + 8 * CXS_STRIDE + 8);
#pragma unroll
            for (int j = 0; j < 8; ++j) {
                const __half* bp = xs + (colrow + j * 8 + g8) * CXS_STRIDE + kb + t2;
                const uint32_t b0 = *reinterpret_cast<const uint32_t*>(bp);
                const uint32_t b1 = *reinterpret_cast<const uint32_t*>(bp + 8);
                mma_f16(acc[j], a0, a1, a2, a3, b0, b1);
            }
        }
    }

    const int h = h0 + hsel;
#pragma unroll
    for (int j = 0; j < 8; ++j) {
        const int w = w0 + j * 8 + t2;
        const size_t base = ((size_t)(b * 64 + d0 + g8)) * HW_ + (size_t)h * WW + w;
        *reinterpret_cast<float2*>(y + base) = make_float2(acc[j][0], acc[j][1]);
        *reinterpret_cast<float2*>(y + base + (size_t)8 * HW_) = make_float2(acc[j][2], acc[j][3]);
    }
}

// ---------------- batchnorm ----------------
__global__ void bn_reduce_kernel(const float* __restrict__ x, float2* __restrict__ part) {
    const int c = blockIdx.x, p = blockIdx.y;
    float s = 0.f, s2 = 0.f;
    const int base = p * 16384;
    for (int j = threadIdx.x; j < 16384; j += 256) {
        const int f = base + j;
        const int b = f >> 15;
        const int i = f & 32767;
        const float v = x[((size_t)(b * 64 + c)) * HW_ + i];
        s += v; s2 += v * v;
    }
    __shared__ float rs[8], rs2[8];
#pragma unroll
    for (int o = 16; o; o >>= 1) {
        s  += __shfl_xor_sync(0xffffffffu, s, o);
        s2 += __shfl_xor_sync(0xffffffffu, s2, o);
    }
    if ((threadIdx.x & 31) == 0) { rs[threadIdx.x >> 5] = s; rs2[threadIdx.x >> 5] = s2; }
    __syncthreads();
    if (threadIdx.x == 0) {
        float a = 0.f, b2 = 0.f;
        for (int k = 0; k < 8; ++k) { a += rs[k]; b2 += rs2[k]; }
        part[c * 8 + p] = make_float2(a, b2);
    }
}

__global__ void bn_finalize_kernel(const float2* __restrict__ part, float2* __restrict__ stats) {
    const int c = threadIdx.x;
    float s = 0.f, s2 = 0.f;
    for (int p = 0; p < 8; ++p) { s += part[c * 8 + p].x; s2 += part[c * 8 + p].y; }
    const float inv_n = 1.f / 131072.f;
    const float mean = s * inv_n;
    const float var  = s2 * inv_n - mean * mean;
    stats[c] = make_float2(mean, rsqrtf(var + 1e-5f));
}

__global__ void bn_apply_kernel(const float* __restrict__ x, const float2* __restrict__ stats,
                                const float* __restrict__ gam, const float* __restrict__ bet,
                                float* __restrict__ y) {
    const int idx = blockIdx.x * 256 + threadIdx.x;
    const int e = idx * 4;
    const int c = (e / HW_) & 63;
    const float2 st = stats[c];
    const float g = gam[c], be = bet[c];
    float4 v = reinterpret_cast<const float4*>(x)[idx];
    v.x = (v.x - st.x) * st.y * g + be;
    v.y = (v.y - st.x) * st.y * g + be;
    v.z = (v.z - st.x) * st.y * g + be;
    v.w = (v.w - st.x) * st.y * g + be;
    reinterpret_cast<float4*>(y)[idx] = v;
}

// ---------------- 1x1 convs ----------------
__global__ void conv1x1_c32_kernel(const float* __restrict__ x, const float* __restrict__ wgt,
                                   const float* __restrict__ bias, __half* __restrict__ yt) {
    __shared__ float sw[32][33];
    __shared__ float sb[32];
    const int tid = threadIdx.x;
    for (int i = tid; i < 1024; i += 256) sw[i >> 5][i & 31] = wgt[i];
    if (tid < 32) sb[tid] = bias[tid];
    __syncthreads();
    const int pos = blockIdx.x * 256 + tid;
    const int b = pos >> 15, i = pos & 32767;
    float xin[32];
#pragma unroll
    for (int ci = 0; ci < 32; ++ci) xin[ci] = x[((size_t)(b * 32 + ci)) * HW_ + i];
    __half* out = yt + (size_t)pos * 32;
#pragma unroll
    for (int co = 0; co < 32; co += 4) {
        float4 a = make_float4(sb[co], sb[co + 1], sb[co + 2], sb[co + 3]);
#pragma unroll
        for (int ci = 0; ci < 32; ++ci) {
            const float xv = xin[ci];
            a.x += sw[co][ci] * xv; a.y += sw[co + 1][ci] * xv;
            a.z += sw[co + 2][ci] * xv; a.w += sw[co + 3][ci] * xv;
        }
        *reinterpret_cast<__half2*>(out + co)     = __floats2half2_rn(a.x, a.y);
        *reinterpret_cast<__half2*>(out + co + 2) = __floats2half2_rn(a.z, a.w);
    }
}

__global__ void conv1x1_d64_kernel(const float* __restrict__ x, const float* __restrict__ wgt,
                                   const float* __restrict__ bias, __half* __restrict__ vth) {
    __shared__ float sw[64][65];
    __shared__ float sb[64];
    const int tid = threadIdx.x;
    for (int i = tid; i < 4096; i += 256) sw[i >> 6][i & 63] = wgt[i];
    if (tid < 64) sb[tid] = bias[tid];
    __syncthreads();
    const int pos = blockIdx.x * 256 + tid;
    const int b = pos >> 15, i = pos & 32767;
    float xin[64];
#pragma unroll
    for (int ci = 0; ci < 64; ++ci) xin[ci] = x[((size_t)(b * 64 + ci)) * HW_ + i];
    __half* out = vth + (size_t)pos * 64;
#pragma unroll
    for (int co = 0; co < 64; co += 4) {
        float4 a = make_float4(sb[co], sb[co + 1], sb[co + 2], sb[co + 3]);
#pragma unroll
        for (int ci = 0; ci < 64; ++ci) {
            const float xv = xin[ci];
            a.x += sw[co][ci] * xv; a.y += sw[co + 1][ci] * xv;
            a.z += sw[co + 2][ci] * xv; a.w += sw[co + 3][ci] * xv;
        }
        *reinterpret_cast<__half2*>(out + co)     = __floats2half2_rn(a.x, a.y);
        *reinterpret_cast<__half2*>(out + co + 2) = __floats2half2_rn(a.z, a.w);
    }
}

// ---------------- eH via HMMA + fused exp + row-sum: per (b,w) ----------------
// grid (256 w, 4 b), 256 threads (8 warps, each 16 h x 128 g). K=32. diag -> 0.
#define ES_STRIDE 40

__global__ __launch_bounds__(256)
void eH_kernel(const __half* __restrict__ qth, const __half* __restrict__ kth,
               __half* __restrict__ aHh, float* __restrict__ rsum) {
    __shared__ __half Qs[128 * ES_STRIDE];
    __shared__ __half Ks[128 * ES_STRIDE];
    const int w = blockIdx.x, b = blockIdx.y;
    const int tid = threadIdx.x;
    const int lane = tid & 31, warp = tid >> 5;
    const int g8 = lane >> 2, t2 = (lane & 3) * 2;

    for (int i = tid; i < 512; i += 256) {
        const int row = i >> 2, seg = (i & 3) * 8;
        const size_t gidx = (((size_t)b * HH + row) * WW + w) * 32 + seg;
        *reinterpret_cast<uint4*>(Qs + row * ES_STRIDE + seg) =
            *reinterpret_cast<const uint4*>(qth + gidx);
        *reinterpret_cast<uint4*>(Ks + row * ES_STRIDE + seg) =
            *reinterpret_cast<const uint4*>(kth + gidx);
    }
    __syncthreads();

    float acc[16][4];
#pragma unroll
    for (int ni = 0; ni < 16; ++ni)
#pragma unroll
        for (int k = 0; k < 4; ++k) acc[ni][k] = 0.f;

    const int h0 = warp * 16;
#pragma unroll
    for (int kb = 0; kb < 32; kb += 16) {
        const __half* ap = Qs + (h0 + g8) * ES_STRIDE + kb + t2;
        const uint32_t a0 = *reinterpret_cast<const uint32_t*>(ap);
        const uint32_t a1 = *reinterpret_cast<const uint32_t*>(ap + 8 * ES_STRIDE);
        const uint32_t a2 = *reinterpret_cast<const uint32_t*>(ap + 8);
        const uint32_t a3 = *reinterpret_cast<const uint32_t*>(ap + 8 * ES_STRIDE + 8);
#pragma unroll
        for (int ni = 0; ni < 16; ++ni) {
            const __half* bp = Ks + (ni * 8 + g8) * ES_STRIDE + kb + t2;
            const uint32_t b0 = *reinterpret_cast<const uint32_t*>(bp);
            const uint32_t b1 = *reinterpret_cast<const uint32_t*>(bp + 8);
            mma_f16(acc[ni], a0, a1, a2, a3, b0, b1);
        }
    }

    const int h1 = h0 + g8, h2 = h1 + 8;
    float s1 = 0.f, s2 = 0.f;
#pragma unroll
    for (int ni = 0; ni < 16; ++ni) {
        const int g = ni * 8 + t2;
        const float e0 = (h1 == g)     ? 0.f : fexp(acc[ni][0]);
        const float e1 = (h1 == g + 1) ? 0.f : fexp(acc[ni][1]);
        const float e2 = (h2 == g)     ? 0.f : fexp(acc[ni][2]);
        const float e3 = (h2 == g + 1) ? 0.f : fexp(acc[ni][3]);
        s1 += e0 + e1;
        s2 += e2 + e3;
        *reinterpret_cast<__half2*>(aHh + (((size_t)b * HH + h1) * WW + w) * 128 + g) =
            __floats2half2_rn(e0, e1);
        *reinterpret_cast<__half2*>(aHh + (((size_t)b * HH + h2) * WW + w) * 128 + g) =
            __floats2half2_rn(e2, e3);
    }
    s1 += __shfl_xor_sync(0xffffffffu, s1, 1);
    s1 += __shfl_xor_sync(0xffffffffu, s1, 2);
    s2 += __shfl_xor_sync(0xffffffffu, s2, 1);
    s2 += __shfl_xor_sync(0xffffffffu, s2, 2);
    if ((lane & 3) == 0) {
        atomicAdd(rsum + ((size_t)b * HH + h1) * WW + w, s1);
        atomicAdd(rsum + ((size_t)b * HH + h2) * WW + w, s2);
    }
}

// ---------------- eW via HMMA + fused exp + row-sum: per (b,h,gc) ----------------
// grid (4 gc, 128 h, 4 b), 256 threads (8 warps, each 32 w x 64 g). K=32.
__global__ __launch_bounds__(256)
void eW_kernel(const __half* __restrict__ qth, const __half* __restrict__ kth,
               __half* __restrict__ aWh, float* __restrict__ rsum) {
    __shared__ __half Qs[256 * ES_STRIDE];
    __shared__ __half Ks[64 * ES_STRIDE];
    const int gc = blockIdx.x * 64;
    const int h = blockIdx.y, b = blockIdx.z;
    const int tid = threadIdx.x;
    const int lane = tid & 31, warp = tid >> 5;
    const int g8 = lane >> 2, t2 = (lane & 3) * 2;

    const __half* qbase = qth + (((size_t)b * HH + h) * WW) * 32;
    for (int i = tid; i < 1024; i += 256) {
        const int row = i >> 2, seg = (i & 3) * 8;
        *reinterpret_cast<uint4*>(Qs + row * ES_STRIDE + seg) =
            *reinterpret_cast<const uint4*>(qbase + row * 32 + seg);
    }
    const __half* kbase = kth + (((size_t)b * HH + h) * WW + gc) * 32;
    {
        const int i = tid;
        const int row = i >> 2, seg = (i & 3) * 8;
        *reinterpret_cast<uint4*>(Ks + row * ES_STRIDE + seg) =
            *reinterpret_cast<const uint4*>(kbase + row * 32 + seg);
    }
    __syncthreads();

    float acc[2][8][4];
#pragma unroll
    for (int mi = 0; mi < 2; ++mi)
#pragma unroll
        for (int ni = 0; ni < 8; ++ni)
#pragma unroll
            for (int k = 0; k < 4; ++k) acc[mi][ni][k] = 0.f;

    const int w0 = warp * 32;
#pragma unroll
    for (int kb = 0; kb < 32; kb += 16) {
        uint32_t a[2][4];
#pragma unroll
        for (int mi = 0; mi < 2; ++mi) {
            const __half* ap = Qs + (w0 + mi * 16 + g8) * ES_STRIDE + kb + t2;
            a[mi][0] = *reinterpret_cast<const uint32_t*>(ap);
            a[mi][1] = *reinterpret_cast<const uint32_t*>(ap + 8 * ES_STRIDE);
            a[mi][2] = *reinterpret_cast<const uint32_t*>(ap + 8);
            a[mi][3] = *reinterpret_cast<const uint32_t*>(ap + 8 * ES_STRIDE + 8);
        }
#pragma unroll
        for (int ni = 0; ni < 8; ++ni) {
            const __half* bp = Ks + (ni * 8 + g8) * ES_STRIDE + kb + t2;
            const uint32_t b0 = *reinterpret_cast<const uint32_t*>(bp);
            const uint32_t b1 = *reinterpret_cast<const uint32_t*>(bp + 8);
            mma_f16(acc[0][ni], a[0][0], a[0][1], a[0][2], a[0][3], b0, b1);
            mma_f16(acc[1][ni], a[1][0], a[1][1], a[1][2], a[1][3], b0, b1);
        }
    }

#pragma unroll
    for (int mi = 0; mi < 2; ++mi) {
        const int w1 = w0 + mi * 16 + g8, w2 = w1 + 8;
        float s1 = 0.f, s2 = 0.f;
#pragma unroll
        for (int ni = 0; ni < 8; ++ni) {
            const int g = gc + ni * 8 + t2;
            const float e0 = fexp(acc[mi][ni][0]);
            const float e1 = fexp(acc[mi][ni][1]);
            const float e2 = fexp(acc[mi][ni][2]);
            const float e3 = fexp(acc[mi][ni][3]);
            s1 += e0 + e1;
            s2 += e2 + e3;
            *reinterpret_cast<__half2*>(aWh + (((size_t)b * HH + h) * WW + w1) * 256 + g) =
                __floats2half2_rn(e0, e1);
            *reinterpret_cast<__half2*>(aWh + (((size_t)b * HH + h) * WW + w2) * 256 + g) =
                __floats2half2_rn(e2, e3);
        }
        s1 += __shfl_xor_sync(0xffffffffu, s1, 1);
        s1 += __shfl_xor_sync(0xffffffffu, s1, 2);
        s2 += __shfl_xor_sync(0xffffffffu, s2, 1);
        s2 += __shfl_xor_sync(0xffffffffu, s2, 2);
        if ((lane & 3) == 0) {
            atomicAdd(rsum + ((size_t)b * HH + h) * WW + w1, s1);
            atomicAdd(rsum + ((size_t)b * HH + h) * WW + w2, s2);
        }
    }
}

// ---------------- oH via HMMA + normalization: per (b,w) ----------------
#define ATT_SSTRIDE 136
#define ATT_SMEM ((128*ATT_SSTRIDE + 64*ATT_SSTRIDE) * 2)   // 52224 bytes

__global__ void oH_kernel(const __half* __restrict__ vth, const __half* __restrict__ aHh,
                          const float* __restrict__ rsum, __half* __restrict__ ohth) {
    extern __shared__ __half sh[];
    __half* As = sh;                       // [128 h][136] g-contiguous
    __half* Vs = sh + 128 * ATT_SSTRIDE;   // [64 d][136] g-contiguous (B col-major)
    const int w = blockIdx.x, b = blockIdx.y;
    const int tid = threadIdx.x;
    const int lane = tid & 31, warp = tid >> 5;
    const int g8 = lane >> 2, t2 = (lane & 3) * 2;

    for (int i = tid; i < 2048; i += 128) {
        const int row = i >> 4, ch = (i & 15) * 8;
        *reinterpret_cast<uint4*>(As + row * ATT_SSTRIDE + ch) =
            *reinterpret_cast<const uint4*>(aHh + (((size_t)b * HH + row) * WW + w) * 128 + ch);
    }
    for (int i = tid; i < 1024; i += 128) {
        const int g = i >> 3, dc = (i & 7) * 8;
        uint4 v = *reinterpret_cast<const uint4*>(vth + (((size_t)b * HH + g) * WW + w) * 64 + dc);
        __half tmp[8];
        *reinterpret_cast<uint4*>(tmp) = v;
#pragma unroll
        for (int j = 0; j < 8; ++j) Vs[(dc + j) * ATT_SSTRIDE + g] = tmp[j];
    }
    __syncthreads();

    float acc[2][8][4];
#pragma unroll
    for (int mi = 0; mi < 2; ++mi)
#pragma unroll
        for (int ni = 0; ni < 8; ++ni)
#pragma unroll
            for (int k = 0; k < 4; ++k) acc[mi][ni][k] = 0.f;

    const int h0 = warp * 32;
#pragma unroll
    for (int kb = 0; kb < 128; kb += 16) {
        uint32_t a[2][4];
#pragma unroll
        for (int mi = 0; mi < 2; ++mi) {
            const __half* ap = As + (h0 + mi * 16 + g8) * ATT_SSTRIDE + kb + t2;
            a[mi][0] = *reinterpret_cast<const uint32_t*>(ap);
            a[mi][1] = *reinterpret_cast<const uint32_t*>(ap + 8 * ATT_SSTRIDE);
            a[mi][2] = *reinterpret_cast<const uint32_t*>(ap + 8);
            a[mi][3] = *reinterpret_cast<const uint32_t*>(ap + 8 * ATT_SSTRIDE + 8);
        }
#pragma unroll
        for (int ni = 0; ni < 8; ++ni) {
            const __half* bp = Vs + (ni * 8 + g8) * ATT_SSTRIDE + kb + t2;
            const uint32_t b0 = *reinterpret_cast<const uint32_t*>(bp);
            const uint32_t b1 = *reinterpret_cast<const uint32_t*>(bp + 8);
            mma_f16(acc[0][ni], a[0][0], a[0][1], a[0][2], a[0][3], b0, b1);
            mma_f16(acc[1][ni], a[1][0], a[1][1], a[1][2], a[1][3], b0, b1);
        }
    }

#pragma unroll
    for (int mi = 0; mi < 2; ++mi) {
        const int h = h0 + mi * 16 + g8;
        const float inv1 = 1.f / rsum[((size_t)b * HH + h) * WW + w];
        const float inv2 = 1.f / rsum[((size_t)b * HH + h + 8) * WW + w];
#pragma unroll
        for (int ni = 0; ni < 8; ++ni) {
            const int d = ni * 8 + t2;
            *reinterpret_cast<__half2*>(ohth + (((size_t)b * HH + h) * WW + w) * 64 + d) =
                __floats2half2_rn(acc[mi][ni][0] * inv1, acc[mi][ni][1] * inv1);
            *reinterpret_cast<__half2*>(ohth + (((size_t)b * HH + h + 8) * WW + w) * 64 + d) =
                __floats2half2_rn(acc[mi][ni][2] * inv2, acc[mi][ni][3] * inv2);
        }
    }
}

// ---------------- oW via HMMA + normalization + combine ----------------
__global__ void oW_combine_kernel(const __half* __restrict__ vth, const __half* __restrict__ aWh,
                                  const __half* __restrict__ ohth, const float* __restrict__ x,
                                  const float* __restrict__ rsum,
                                  const float* __restrict__ gamma, float* __restrict__ xout) {
    extern __shared__ __half sh[];
    __half* As = sh;                       // [128 w][136]
    __half* Vs = sh + 128 * ATT_SSTRIDE;   // [64 d][136]
    const int wb = blockIdx.x * 128;
    const int h = blockIdx.y, b = blockIdx.z;
    const int tid = threadIdx.x;
    const int lane = tid & 31, warp = tid >> 5;
    const int g8 = lane >> 2, t2 = (lane & 3) * 2;

    float acc[2][8][4];
#pragma unroll
    for (int mi = 0; mi < 2; ++mi)
#pragma unroll
        for (int ni = 0; ni < 8; ++ni)
#pragma unroll
            for (int k = 0; k < 4; ++k) acc[mi][ni][k] = 0.f;

    const int w0 = warp * 32;
    for (int gc = 0; gc < 256; gc += 128) {
        __syncthreads();
        for (int i = tid; i < 2048; i += 128) {
            const int row = i >> 4, ch = (i & 15) * 8;
            *reinterpret_cast<uint4*>(As + row * ATT_SSTRIDE + ch) =
                *reinterpret_cast<const uint4*>(
                    aWh + (((size_t)b * HH + h) * WW + wb + row) * 256 + gc + ch);
        }
        for (int i = tid; i < 1024; i += 128) {
            const int g = i >> 3, dc = (i & 7) * 8;
            uint4 v = *reinterpret_cast<const uint4*>(
                vth + (((size_t)b * HH + h) * WW + gc + g) * 64 + dc);
            __half tmp[8];
            *reinterpret_cast<uint4*>(tmp) = v;
#pragma unroll
            for (int j = 0; j < 8; ++j) Vs[(dc + j) * ATT_SSTRIDE + g] = tmp[j];
        }
        __syncthreads();

#pragma unroll
        for (int kb = 0; kb < 128; kb += 16) {
            uint32_t a[2][4];
#pragma unroll
            for (int mi = 0; mi < 2; ++mi) {
                const __half* ap = As + (w0 + mi * 16 + g8) * ATT_SSTRIDE + kb + t2;
                a[mi][0] = *reinterpret_cast<const uint32_t*>(ap);
                a[mi][1] = *reinterpret_cast<const uint32_t*>(ap + 8 * ATT_SSTRIDE);
                a[mi][2] = *reinterpret_cast<const uint32_t*>(ap + 8);
                a[mi][3] = *reinterpret_cast<const uint32_t*>(ap + 8 * ATT_SSTRIDE + 8);
            }
#pragma unroll
            for (int ni = 0; ni < 8; ++ni) {
                const __half* bp = Vs + (ni * 8 + g8) * ATT_SSTRIDE + kb + t2;
                const uint32_t b0 = *reinterpret_cast<const uint32_t*>(bp);
                const uint32_t b1 = *reinterpret_cast<const uint32_t*>(bp + 8);
                mma_f16(acc[0][ni], a[0][0], a[0][1], a[0][2], a[0][3], b0, b1);
                mma_f16(acc[1][ni], a[1][0], a[1][1], a[1][2], a[1][3], b0, b1);
            }
        }
    }

    const float gam = *gamma;
#pragma unroll
    for (int mi = 0; mi < 2; ++mi) {
#pragma unroll
        for (int half = 0; half < 2; ++half) {
            const int w = wb + w0 + mi * 16 + g8 + half * 8;
            const float inv = 1.f / rsum[((size_t)b * HH + h) * WW + w];
#pragma unroll
            for (int ni = 0; ni < 8; ++ni) {
                const int d = ni * 8 + t2;
                const float cA = acc[mi][ni][half * 2] * inv;
                const float cB = acc[mi][ni][half * 2 + 1] * inv;
                const float2 ohf = __half22float2(*reinterpret_cast<const __half2*>(
                    ohth + (((size_t)b * HH + h) * WW + w) * 64 + d));
                const size_t x0 = ((size_t)(b * 64 + d)) * HW_ + (size_t)h * WW + w;
                const size_t x1 = ((size_t)(b * 64 + d + 1)) * HW_ + (size_t)h * WW + w;
                xout[x0] = gam * (cA + ohf.x) + x[x0];
                xout[x1] = gam * (cB + ohf.y) + x[x1];
            }
        }
    }
}

// ---------------- host ----------------
extern "C" void kernel_launch(void* const* d_in, const int* in_sizes, int n_in,
                              void* d_out, int out_size) {
    const float* cost  = (const float*)d_in[0];
    const float* lf0   = (const float*)d_in[1];
    const float* lf1   = (const float*)d_in[2];
    const float* Wa    = (const float*)d_in[3];
    const float* bn_ag = (const float*)d_in[4];
    const float* bn_ab = (const float*)d_in[5];
    const float* Wq    = (const float*)d_in[6];
    const float* bq    = (const float*)d_in[7];
    const float* Wk    = (const float*)d_in[8];
    const float* bk    = (const float*)d_in[9];
    const float* Wv    = (const float*)d_in[10];
    const float* bv    = (const float*)d_in[11];
    const float* gamma = (const float*)d_in[12];
    const float* Wb    = (const float*)d_in[13];
    const float* bn_bg = (const float*)d_in[14];
    const float* bn_bb = (const float*)d_in[15];
    float* out = (float*)d_out;

    float *conv, *xA, *xB, *rsum;
    __half *vth, *ohth, *qth, *kth, *aHh, *aWh, *wth;
    float2 *part, *stats;
    cudaGetSymbolAddress((void**)&conv, g_conv);
    cudaGetSymbolAddress((void**)&xA, g_xA);
    cudaGetSymbolAddress((void**)&xB, g_xB);
    cudaGetSymbolAddress((void**)&vth, g_vth);
    cudaGetSymbolAddress((void**)&ohth, g_ohth);
    cudaGetSymbolAddress((void**)&qth, g_qth);
    cudaGetSymbolAddress((void**)&kth, g_kth);
    cudaGetSymbolAddress((void**)&aHh, g_aHh);
    cudaGetSymbolAddress((void**)&aWh, g_aWh);
    cudaGetSymbolAddress((void**)&rsum, g_rsum);
    cudaGetSymbolAddress((void**)&wth, g_wth);
    cudaGetSymbolAddress((void**)&part, g_part);
    cudaGetSymbolAddress((void**)&stats, g_stats);

    // Idempotent, called unconditionally (no static guards — harness rule).
    cudaFuncSetAttribute(conv3x3_mma_kernel,
                         cudaFuncAttributeMaxDynamicSharedMemorySize, CONV_SMEM);
    cudaFuncSetAttribute(oH_kernel,
                         cudaFuncAttributeMaxDynamicSharedMemorySize, ATT_SMEM);
    cudaFuncSetAttribute(oW_combine_kernel,
                         cudaFuncAttributeMaxDynamicSharedMemorySize, ATT_SMEM);

    // Launch order keeps conv3x3 at capture index 3 (ncu -s5 -c1 lands there).
    conv1x1_c32_kernel<<<512, 256>>>(lf0, Wq, bq, qth);          // 0
    conv1x1_c32_kernel<<<512, 256>>>(lf1, Wk, bk, kth);          // 1
    wtrans_kernel<<<144, 256>>>(Wa, wth);                        // 2
    conv3x3_mma_kernel<<<dim3(4, 64, 4), 256, CONV_SMEM>>>(cost, wth, conv);  // 3 <- profiled

    // attention maps: exp(scores) + row sums (softmax fused; invariant across recurrence)
    cudaMemsetAsync(rsum, 0, NROWS * sizeof(float));
    eH_kernel<<<dim3(256, 4), 256>>>(qth, kth, aHh, rsum);
    eW_kernel<<<dim3(4, 128, 4), 256>>>(qth, kth, aWh, rsum);

    // BN for stage A
    bn_reduce_kernel<<<dim3(64, 8), 256>>>(conv, part);
    bn_finalize_kernel<<<1, 64>>>(part, stats);
    bn_apply_kernel<<<8192, 256>>>(conv, stats, bn_ag, bn_ab, xA);

    // Stage C: 2 recurrence iterations (attention aggregation on tensor cores)
    float* cur = xA;
    float* nxt = xB;
    for (int it = 0; it < 2; ++it) {
        conv1x1_d64_kernel<<<512, 256>>>(cur, Wv, bv, vth);
        oH_kernel<<<dim3(256, 4), 128, ATT_SMEM>>>(vth, aHh, rsum, ohth);
        oW_combine_kernel<<<dim3(2, 128, 4), 128, ATT_SMEM>>>(vth, aWh, ohth, cur, rsum, gamma, nxt);
        float* t = cur; cur = nxt; nxt = t;
    }

    // Stage D: conv3x3(cur, Wb) + BN -> out
    wtrans_kernel<<<144, 256>>>(Wb, wth);
    conv3x3_mma_kernel<<<dim3(4, 64, 4), 256, CONV_SMEM>>>(cur, wth, conv);
    bn_reduce_kernel<<<dim3(64, 8), 256>>>(conv, part);
    bn_finalize_kernel<<<1, 64>>>(part, stats);
    bn_apply_kernel<<<8192, 256>>>(conv, stats, bn_bg, bn_bb, out);
}

// round 13
// speedup vs baseline: 3.2610x; 1.0634x over previous
#include <cuda_runtime.h>
#include <cuda_fp16.h>
#include <cstdint>
#include <cstddef>

#define BB 4
#define CC 32
#define DD 64
#define HH 128
#define WW 256
#define HW_ (HH*WW)          // 32768
#define BDHW_ (BB*DD*HW_)    // 8388608
#define BCHW_ (BB*CC*HW_)    // 4194304
#define NROWS (BB*HH*WW)     // 131072

// ---------------- scratch (static device globals; no allocation) ----------------
__device__ float g_conv[BDHW_];
__device__ float g_xA[BDHW_];
__device__ float g_xB[BDHW_];
__device__ __half g_vth[BDHW_];      // v fp16, [b][h][w][d]
__device__ __half g_ohth[BDHW_];     // oH fp16 (normalized), [b][h][w][d]
__device__ __half g_qth[BCHW_];      // q fp16, [b][h][w][c]
__device__ __half g_kth[BCHW_];      // k fp16, [b][h][w][c]
__device__ __half g_aHh[BB*HH*WW*HH];  // fp16 exp(scores) (H part)
__device__ __half g_aWh[BB*HH*WW*WW];  // fp16 exp(scores) (W part)
__device__ float g_rsum[NROWS];      // per-row softmax denominators
__device__ __half g_wth[9*64*64];    // fp16 conv weights [t][d][c]
__device__ float2 g_part[64*8];
__device__ float2 g_stats[64];

// ---------------- weight transform ----------------
__global__ void wtrans_kernel(const float* __restrict__ W, __half* __restrict__ wth) {
    const int i = blockIdx.x * 256 + threadIdx.x;
    if (i >= 9 * 64 * 64) return;
    const int t = i >> 12;
    const int d = (i >> 6) & 63;
    const int c = i & 63;
    wth[i] = __float2half(W[((d * 64 + c) * 9) + t]);
}

// ---------------- mma / ldmatrix helpers ----------------
__device__ __forceinline__ void mma_f16(float* c, uint32_t a0, uint32_t a1, uint32_t a2, uint32_t a3,
                                        uint32_t b0, uint32_t b1) {
    asm volatile("mma.sync.aligned.m16n8k16.row.col.f32.f16.f16.f32 "
                 "{%0,%1,%2,%3}, {%4,%5,%6,%7}, {%8,%9}, {%0,%1,%2,%3};"
                 : "+f"(c[0]), "+f"(c[1]), "+f"(c[2]), "+f"(c[3])
                 : "r"(a0), "r"(a1), "r"(a2), "r"(a3), "r"(b0), "r"(b1));
}

__device__ __forceinline__ uint32_t cvta_smem(const void* p) {
    return (uint32_t)__cvta_generic_to_shared(p);
}

__device__ __forceinline__ void ldsm_x4(uint32_t& r0, uint32_t& r1, uint32_t& r2, uint32_t& r3,
                                        uint32_t addr) {
    asm volatile("ldmatrix.sync.aligned.m8n8.x4.shared.b16 {%0,%1,%2,%3}, [%4];"
                 : "=r"(r0), "=r"(r1), "=r"(r2), "=r"(r3) : "r"(addr));
}

__device__ __forceinline__ void ldsm_x4_trans(uint32_t& r0, uint32_t& r1, uint32_t& r2, uint32_t& r3,
                                              uint32_t addr) {
    asm volatile("ldmatrix.sync.aligned.m8n8.x4.trans.shared.b16 {%0,%1,%2,%3}, [%4];"
                 : "=r"(r0), "=r"(r1), "=r"(r2), "=r"(r3) : "r"(addr));
}

// ---------------- fast exp ----------------
__device__ __forceinline__ float fexp(float x) {
    x = fmaxf(x, -80.f);
    const float y = x * 1.44269504f;
    const int e = __float2int_rn(y);
    const float f = y - (float)e;
    float p = 0.00133335581f;
    p = fmaf(p, f, 0.00961812910f);
    p = fmaf(p, f, 0.0555041086f);
    p = fmaf(p, f, 0.240226507f);
    p = fmaf(p, f, 0.693147182f);
    p = fmaf(p, f, 1.0f);
    return p * __int_as_float((e + 127) << 23);
}

// ---------------- conv3x3 via fp16 mma + ldmatrix, 2 h-rows per block ----------------
#define CXS_STRIDE 72
#define CXS_HALVES (4*66*72)    // 19008
#define CWS_HALVES (64*72)      // 4608
#define CONV_SMEM ((CXS_HALVES + CWS_HALVES) * 2)   // 47232 bytes

__global__ __launch_bounds__(256)
void conv3x3_mma_kernel(const float* __restrict__ x, const __half* __restrict__ wth,
                        float* __restrict__ y) {
    extern __shared__ __half shc[];
    __half* xs = shc;                  // [(r*66+col)][72]
    __half* ws = shc + CXS_HALVES;     // [d][72]

    const int w0 = blockIdx.x * 64;
    const int h0 = blockIdx.y * 2;
    const int b  = blockIdx.z;
    const int tid = threadIdx.x;
    const int lane = tid & 31;
    const int warp = tid >> 5;
    const int hsel = warp >> 2;
    const int d0 = (warp & 3) * 16;
    const int g8 = lane >> 2;
    const int t2 = (lane & 3) * 2;

    for (int i = tid; i < 64 * 4 * 66; i += 256) {
        const int c = i / 264;
        const int rem = i - c * 264;
        const int r = rem / 66;
        const int col = rem - r * 66;
        const int gh = h0 + r - 1;
        const int gw = w0 + col - 1;
        float v = 0.f;
        if (gh >= 0 && gh < HH && gw >= 0 && gw < WW)
            v = x[((size_t)(b * 64 + c)) * HW_ + gh * WW + gw];
        xs[(r * 66 + col) * CXS_STRIDE + c] = __float2half(v);
    }

    float acc[8][4];
#pragma unroll
    for (int j = 0; j < 8; ++j)
#pragma unroll
        for (int k = 0; k < 4; ++k) acc[j][k] = 0.f;

    // ldmatrix per-thread address offsets (bytes)
    const uint32_t ws_base = cvta_smem(ws);
    const uint32_t xs_base = cvta_smem(xs);
    const uint32_t a_off = ((uint32_t)((d0 + (lane & 15)) * CXS_STRIDE + ((lane >> 4) << 3))) * 2;
    const uint32_t b_off = ((uint32_t)((((lane >> 4) << 3) + (lane & 7)) * CXS_STRIDE
                                       + (((lane >> 3) & 1) << 3))) * 2;

    for (int t = 0; t < 9; ++t) {
        __syncthreads();
        const __half* wp = wth + t * 4096;
        for (int i = tid; i < 4096; i += 256)
            ws[(i >> 6) * CXS_STRIDE + (i & 63)] = wp[i];
        __syncthreads();

        const int dh = t / 3;
        const int dw = t - dh * 3;
        const int colrow = (hsel + dh) * 66 + dw;
        const uint32_t b_tap = xs_base + b_off + (uint32_t)(colrow * CXS_STRIDE) * 2;
#pragma unroll
        for (int kb = 0; kb < 64; kb += 16) {
            uint32_t a0, a1, a2, a3;
            ldsm_x4(a0, a1, a2, a3, ws_base + a_off + kb * 2);
#pragma unroll
            for (int jj = 0; jj < 4; ++jj) {
                uint32_t b0, b1, c0, c1;
                ldsm_x4(b0, b1, c0, c1, b_tap + (uint32_t)(jj * 16 * CXS_STRIDE + kb) * 2);
                mma_f16(acc[2 * jj],     a0, a1, a2, a3, b0, b1);
                mma_f16(acc[2 * jj + 1], a0, a1, a2, a3, c0, c1);
            }
        }
    }

    const int h = h0 + hsel;
#pragma unroll
    for (int j = 0; j < 8; ++j) {
        const int w = w0 + j * 8 + t2;
        const size_t base = ((size_t)(b * 64 + d0 + g8)) * HW_ + (size_t)h * WW + w;
        *reinterpret_cast<float2*>(y + base) = make_float2(acc[j][0], acc[j][1]);
        *reinterpret_cast<float2*>(y + base + (size_t)8 * HW_) = make_float2(acc[j][2], acc[j][3]);
    }
}

// ---------------- batchnorm ----------------
__global__ void bn_reduce_kernel(const float* __restrict__ x, float2* __restrict__ part) {
    const int c = blockIdx.x, p = blockIdx.y;
    float s = 0.f, s2 = 0.f;
    const int base = p * 16384;
    for (int j = threadIdx.x; j < 16384; j += 256) {
        const int f = base + j;
        const int b = f >> 15;
        const int i = f & 32767;
        const float v = x[((size_t)(b * 64 + c)) * HW_ + i];
        s += v; s2 += v * v;
    }
    __shared__ float rs[8], rs2[8];
#pragma unroll
    for (int o = 16; o; o >>= 1) {
        s  += __shfl_xor_sync(0xffffffffu, s, o);
        s2 += __shfl_xor_sync(0xffffffffu, s2, o);
    }
    if ((threadIdx.x & 31) == 0) { rs[threadIdx.x >> 5] = s; rs2[threadIdx.x >> 5] = s2; }
    __syncthreads();
    if (threadIdx.x == 0) {
        float a = 0.f, b2 = 0.f;
        for (int k = 0; k < 8; ++k) { a += rs[k]; b2 += rs2[k]; }
        part[c * 8 + p] = make_float2(a, b2);
    }
}

__global__ void bn_finalize_kernel(const float2* __restrict__ part, float2* __restrict__ stats) {
    const int c = threadIdx.x;
    float s = 0.f, s2 = 0.f;
    for (int p = 0; p < 8; ++p) { s += part[c * 8 + p].x; s2 += part[c * 8 + p].y; }
    const float inv_n = 1.f / 131072.f;
    const float mean = s * inv_n;
    const float var  = s2 * inv_n - mean * mean;
    stats[c] = make_float2(mean, rsqrtf(var + 1e-5f));
}

__global__ void bn_apply_kernel(const float* __restrict__ x, const float2* __restrict__ stats,
                                const float* __restrict__ gam, const float* __restrict__ bet,
                                float* __restrict__ y) {
    const int idx = blockIdx.x * 256 + threadIdx.x;
    const int e = idx * 4;
    const int c = (e / HW_) & 63;
    const float2 st = stats[c];
    const float g = gam[c], be = bet[c];
    float4 v = reinterpret_cast<const float4*>(x)[idx];
    v.x = (v.x - st.x) * st.y * g + be;
    v.y = (v.y - st.x) * st.y * g + be;
    v.z = (v.z - st.x) * st.y * g + be;
    v.w = (v.w - st.x) * st.y * g + be;
    reinterpret_cast<float4*>(y)[idx] = v;
}

// ---------------- 1x1 convs ----------------
__global__ void conv1x1_c32_kernel(const float* __restrict__ x, const float* __restrict__ wgt,
                                   const float* __restrict__ bias, __half* __restrict__ yt) {
    __shared__ float sw[32][33];
    __shared__ float sb[32];
    const int tid = threadIdx.x;
    for (int i = tid; i < 1024; i += 256) sw[i >> 5][i & 31] = wgt[i];
    if (tid < 32) sb[tid] = bias[tid];
    __syncthreads();
    const int pos = blockIdx.x * 256 + tid;
    const int b = pos >> 15, i = pos & 32767;
    float xin[32];
#pragma unroll
    for (int ci = 0; ci < 32; ++ci) xin[ci] = x[((size_t)(b * 32 + ci)) * HW_ + i];
    __half* out = yt + (size_t)pos * 32;
#pragma unroll
    for (int co = 0; co < 32; co += 4) {
        float4 a = make_float4(sb[co], sb[co + 1], sb[co + 2], sb[co + 3]);
#pragma unroll
        for (int ci = 0; ci < 32; ++ci) {
            const float xv = xin[ci];
            a.x += sw[co][ci] * xv; a.y += sw[co + 1][ci] * xv;
            a.z += sw[co + 2][ci] * xv; a.w += sw[co + 3][ci] * xv;
        }
        *reinterpret_cast<__half2*>(out + co)     = __floats2half2_rn(a.x, a.y);
        *reinterpret_cast<__half2*>(out + co + 2) = __floats2half2_rn(a.z, a.w);
    }
}

__global__ void conv1x1_d64_kernel(const float* __restrict__ x, const float* __restrict__ wgt,
                                   const float* __restrict__ bias, __half* __restrict__ vth) {
    __shared__ float sw[64][65];
    __shared__ float sb[64];
    const int tid = threadIdx.x;
    for (int i = tid; i < 4096; i += 256) sw[i >> 6][i & 63] = wgt[i];
    if (tid < 64) sb[tid] = bias[tid];
    __syncthreads();
    const int pos = blockIdx.x * 256 + tid;
    const int b = pos >> 15, i = pos & 32767;
    float xin[64];
#pragma unroll
    for (int ci = 0; ci < 64; ++ci) xin[ci] = x[((size_t)(b * 64 + ci)) * HW_ + i];
    __half* out = vth + (size_t)pos * 64;
#pragma unroll
    for (int co = 0; co < 64; co += 4) {
        float4 a = make_float4(sb[co], sb[co + 1], sb[co + 2], sb[co + 3]);
#pragma unroll
        for (int ci = 0; ci < 64; ++ci) {
            const float xv = xin[ci];
            a.x += sw[co][ci] * xv; a.y += sw[co + 1][ci] * xv;
            a.z += sw[co + 2][ci] * xv; a.w += sw[co + 3][ci] * xv;
        }
        *reinterpret_cast<__half2*>(out + co)     = __floats2half2_rn(a.x, a.y);
        *reinterpret_cast<__half2*>(out + co + 2) = __floats2half2_rn(a.z, a.w);
    }
}

// ---------------- eH via HMMA + fused exp + row-sum: per (b,w) ----------------
#define ES_STRIDE 40

__global__ __launch_bounds__(256)
void eH_kernel(const __half* __restrict__ qth, const __half* __restrict__ kth,
               __half* __restrict__ aHh, float* __restrict__ rsum) {
    __shared__ __half Qs[128 * ES_STRIDE];
    __shared__ __half Ks[128 * ES_STRIDE];
    const int w = blockIdx.x, b = blockIdx.y;
    const int tid = threadIdx.x;
    const int lane = tid & 31, warp = tid >> 5;
    const int g8 = lane >> 2, t2 = (lane & 3) * 2;

    for (int i = tid; i < 512; i += 256) {
        const int row = i >> 2, seg = (i & 3) * 8;
        const size_t gidx = (((size_t)b * HH + row) * WW + w) * 32 + seg;
        *reinterpret_cast<uint4*>(Qs + row * ES_STRIDE + seg) =
            *reinterpret_cast<const uint4*>(qth + gidx);
        *reinterpret_cast<uint4*>(Ks + row * ES_STRIDE + seg) =
            *reinterpret_cast<const uint4*>(kth + gidx);
    }
    __syncthreads();

    float acc[16][4];
#pragma unroll
    for (int ni = 0; ni < 16; ++ni)
#pragma unroll
        for (int k = 0; k < 4; ++k) acc[ni][k] = 0.f;

    const int h0 = warp * 16;
#pragma unroll
    for (int kb = 0; kb < 32; kb += 16) {
        const __half* ap = Qs + (h0 + g8) * ES_STRIDE + kb + t2;
        const uint32_t a0 = *reinterpret_cast<const uint32_t*>(ap);
        const uint32_t a1 = *reinterpret_cast<const uint32_t*>(ap + 8 * ES_STRIDE);
        const uint32_t a2 = *reinterpret_cast<const uint32_t*>(ap + 8);
        const uint32_t a3 = *reinterpret_cast<const uint32_t*>(ap + 8 * ES_STRIDE + 8);
#pragma unroll
        for (int ni = 0; ni < 16; ++ni) {
            const __half* bp = Ks + (ni * 8 + g8) * ES_STRIDE + kb + t2;
            const uint32_t b0 = *reinterpret_cast<const uint32_t*>(bp);
            const uint32_t b1 = *reinterpret_cast<const uint32_t*>(bp + 8);
            mma_f16(acc[ni], a0, a1, a2, a3, b0, b1);
        }
    }

    const int h1 = h0 + g8, h2 = h1 + 8;
    float s1 = 0.f, s2 = 0.f;
#pragma unroll
    for (int ni = 0; ni < 16; ++ni) {
        const int g = ni * 8 + t2;
        const float e0 = (h1 == g)     ? 0.f : fexp(acc[ni][0]);
        const float e1 = (h1 == g + 1) ? 0.f : fexp(acc[ni][1]);
        const float e2 = (h2 == g)     ? 0.f : fexp(acc[ni][2]);
        const float e3 = (h2 == g + 1) ? 0.f : fexp(acc[ni][3]);
        s1 += e0 + e1;
        s2 += e2 + e3;
        *reinterpret_cast<__half2*>(aHh + (((size_t)b * HH + h1) * WW + w) * 128 + g) =
            __floats2half2_rn(e0, e1);
        *reinterpret_cast<__half2*>(aHh + (((size_t)b * HH + h2) * WW + w) * 128 + g) =
            __floats2half2_rn(e2, e3);
    }
    s1 += __shfl_xor_sync(0xffffffffu, s1, 1);
    s1 += __shfl_xor_sync(0xffffffffu, s1, 2);
    s2 += __shfl_xor_sync(0xffffffffu, s2, 1);
    s2 += __shfl_xor_sync(0xffffffffu, s2, 2);
    if ((lane & 3) == 0) {
        atomicAdd(rsum + ((size_t)b * HH + h1) * WW + w, s1);
        atomicAdd(rsum + ((size_t)b * HH + h2) * WW + w, s2);
    }
}

// ---------------- eW via HMMA + fused exp + row-sum: per (b,h,gc) ----------------
__global__ __launch_bounds__(256)
void eW_kernel(const __half* __restrict__ qth, const __half* __restrict__ kth,
               __half* __restrict__ aWh, float* __restrict__ rsum) {
    __shared__ __half Qs[256 * ES_STRIDE];
    __shared__ __half Ks[64 * ES_STRIDE];
    const int gc = blockIdx.x * 64;
    const int h = blockIdx.y, b = blockIdx.z;
    const int tid = threadIdx.x;
    const int lane = tid & 31, warp = tid >> 5;
    const int g8 = lane >> 2, t2 = (lane & 3) * 2;

    const __half* qbase = qth + (((size_t)b * HH + h) * WW) * 32;
    for (int i = tid; i < 1024; i += 256) {
        const int row = i >> 2, seg = (i & 3) * 8;
        *reinterpret_cast<uint4*>(Qs + row * ES_STRIDE + seg) =
            *reinterpret_cast<const uint4*>(qbase + row * 32 + seg);
    }
    const __half* kbase = kth + (((size_t)b * HH + h) * WW + gc) * 32;
    {
        const int i = tid;
        const int row = i >> 2, seg = (i & 3) * 8;
        *reinterpret_cast<uint4*>(Ks + row * ES_STRIDE + seg) =
            *reinterpret_cast<const uint4*>(kbase + row * 32 + seg);
    }
    __syncthreads();

    float acc[2][8][4];
#pragma unroll
    for (int mi = 0; mi < 2; ++mi)
#pragma unroll
        for (int ni = 0; ni < 8; ++ni)
#pragma unroll
            for (int k = 0; k < 4; ++k) acc[mi][ni][k] = 0.f;

    const int w0 = warp * 32;
#pragma unroll
    for (int kb = 0; kb < 32; kb += 16) {
        uint32_t a[2][4];
#pragma unroll
        for (int mi = 0; mi < 2; ++mi) {
            const __half* ap = Qs + (w0 + mi * 16 + g8) * ES_STRIDE + kb + t2;
            a[mi][0] = *reinterpret_cast<const uint32_t*>(ap);
            a[mi][1] = *reinterpret_cast<const uint32_t*>(ap + 8 * ES_STRIDE);
            a[mi][2] = *reinterpret_cast<const uint32_t*>(ap + 8);
            a[mi][3] = *reinterpret_cast<const uint32_t*>(ap + 8 * ES_STRIDE + 8);
        }
#pragma unroll
        for (int ni = 0; ni < 8; ++ni) {
            const __half* bp = Ks + (ni * 8 + g8) * ES_STRIDE + kb + t2;
            const uint32_t b0 = *reinterpret_cast<const uint32_t*>(bp);
            const uint32_t b1 = *reinterpret_cast<const uint32_t*>(bp + 8);
            mma_f16(acc[0][ni], a[0][0], a[0][1], a[0][2], a[0][3], b0, b1);
            mma_f16(acc[1][ni], a[1][0], a[1][1], a[1][2], a[1][3], b0, b1);
        }
    }

#pragma unroll
    for (int mi = 0; mi < 2; ++mi) {
        const int w1 = w0 + mi * 16 + g8, w2 = w1 + 8;
        float s1 = 0.f, s2 = 0.f;
#pragma unroll
        for (int ni = 0; ni < 8; ++ni) {
            const int g = gc + ni * 8 + t2;
            const float e0 = fexp(acc[mi][ni][0]);
            const float e1 = fexp(acc[mi][ni][1]);
            const float e2 = fexp(acc[mi][ni][2]);
            const float e3 = fexp(acc[mi][ni][3]);
            s1 += e0 + e1;
            s2 += e2 + e3;
            *reinterpret_cast<__half2*>(aWh + (((size_t)b * HH + h) * WW + w1) * 256 + g) =
                __floats2half2_rn(e0, e1);
            *reinterpret_cast<__half2*>(aWh + (((size_t)b * HH + h) * WW + w2) * 256 + g) =
                __floats2half2_rn(e2, e3);
        }
        s1 += __shfl_xor_sync(0xffffffffu, s1, 1);
        s1 += __shfl_xor_sync(0xffffffffu, s1, 2);
        s2 += __shfl_xor_sync(0xffffffffu, s2, 1);
        s2 += __shfl_xor_sync(0xffffffffu, s2, 2);
        if ((lane & 3) == 0) {
            atomicAdd(rsum + ((size_t)b * HH + h) * WW + w1, s1);
            atomicAdd(rsum + ((size_t)b * HH + h) * WW + w2, s2);
        }
    }
}

// ---------------- oH via HMMA + ldmatrix + normalization: per (b,w) ----------------
#define ATT_SSTRIDE 136
#define VS2_STRIDE 72
#define ATT_SMEM ((128*ATT_SSTRIDE + 128*VS2_STRIDE) * 2)   // 53248 bytes

__global__ void oH_kernel(const __half* __restrict__ vth, const __half* __restrict__ aHh,
                          const float* __restrict__ rsum, __half* __restrict__ ohth) {
    extern __shared__ __half sh[];
    __half* As = sh;                       // [128 h][136] g-contiguous
    __half* Vs = sh + 128 * ATT_SSTRIDE;   // [128 g][72] d-contiguous (natural)
    const int w = blockIdx.x, b = blockIdx.y;
    const int tid = threadIdx.x;
    const int lane = tid & 31, warp = tid >> 5;
    const int g8 = lane >> 2, t2 = (lane & 3) * 2;

    for (int i = tid; i < 2048; i += 128) {
        const int row = i >> 4, ch = (i & 15) * 8;
        *reinterpret_cast<uint4*>(As + row * ATT_SSTRIDE + ch) =
            *reinterpret_cast<const uint4*>(aHh + (((size_t)b * HH + row) * WW + w) * 128 + ch);
    }
    for (int i = tid; i < 1024; i += 128) {
        const int g = i >> 3, dc = (i & 7) * 8;
        *reinterpret_cast<uint4*>(Vs + g * VS2_STRIDE + dc) =
            *reinterpret_cast<const uint4*>(vth + (((size_t)b * HH + g) * WW + w) * 64 + dc);
    }
    __syncthreads();

    float acc[2][8][4];
#pragma unroll
    for (int mi = 0; mi < 2; ++mi)
#pragma unroll
        for (int ni = 0; ni < 8; ++ni)
#pragma unroll
            for (int k = 0; k < 4; ++k) acc[mi][ni][k] = 0.f;

    const uint32_t as_base = cvta_smem(As);
    const uint32_t vs_base = cvta_smem(Vs);
    const uint32_t a_off = ((uint32_t)((lane & 15) * ATT_SSTRIDE + ((lane >> 4) << 3))) * 2;
    const uint32_t b_off = ((uint32_t)((lane & 15) * VS2_STRIDE + ((lane >> 4) << 3))) * 2;

    const int h0 = warp * 32;
#pragma unroll
    for (int kb = 0; kb < 128; kb += 16) {
        uint32_t a[2][4];
#pragma unroll
        for (int mi = 0; mi < 2; ++mi)
            ldsm_x4(a[mi][0], a[mi][1], a[mi][2], a[mi][3],
                    as_base + a_off + (uint32_t)((h0 + mi * 16) * ATT_SSTRIDE + kb) * 2);
#pragma unroll
        for (int np = 0; np < 4; ++np) {
            uint32_t b0, b1, c0, c1;
            ldsm_x4_trans(b0, b1, c0, c1,
                          vs_base + b_off + (uint32_t)(kb * VS2_STRIDE + np * 16) * 2);
            mma_f16(acc[0][2 * np],     a[0][0], a[0][1], a[0][2], a[0][3], b0, b1);
            mma_f16(acc[0][2 * np + 1], a[0][0], a[0][1], a[0][2], a[0][3], c0, c1);
            mma_f16(acc[1][2 * np],     a[1][0], a[1][1], a[1][2], a[1][3], b0, b1);
            mma_f16(acc[1][2 * np + 1], a[1][0], a[1][1], a[1][2], a[1][3], c0, c1);
        }
    }

#pragma unroll
    for (int mi = 0; mi < 2; ++mi) {
        const int h = h0 + mi * 16 + g8;
        const float inv1 = 1.f / rsum[((size_t)b * HH + h) * WW + w];
        const float inv2 = 1.f / rsum[((size_t)b * HH + h + 8) * WW + w];
#pragma unroll
        for (int ni = 0; ni < 8; ++ni) {
            const int d = ni * 8 + t2;
            *reinterpret_cast<__half2*>(ohth + (((size_t)b * HH + h) * WW + w) * 64 + d) =
                __floats2half2_rn(acc[mi][ni][0] * inv1, acc[mi][ni][1] * inv1);
            *reinterpret_cast<__half2*>(ohth + (((size_t)b * HH + h + 8) * WW + w) * 64 + d) =
                __floats2half2_rn(acc[mi][ni][2] * inv2, acc[mi][ni][3] * inv2);
        }
    }
}

// ---------------- oW via HMMA + ldmatrix + normalization + combine ----------------
__global__ void oW_combine_kernel(const __half* __restrict__ vth, const __half* __restrict__ aWh,
                                  const __half* __restrict__ ohth, const float* __restrict__ x,
                                  const float* __restrict__ rsum,
                                  const float* __restrict__ gamma, float* __restrict__ xout) {
    extern __shared__ __half sh[];
    __half* As = sh;                       // [128 w][136]
    __half* Vs = sh + 128 * ATT_SSTRIDE;   // [128 g][72]
    const int wb = blockIdx.x * 128;
    const int h = blockIdx.y, b = blockIdx.z;
    const int tid = threadIdx.x;
    const int lane = tid & 31, warp = tid >> 5;
    const int g8 = lane >> 2, t2 = (lane & 3) * 2;

    float acc[2][8][4];
#pragma unroll
    for (int mi = 0; mi < 2; ++mi)
#pragma unroll
        for (int ni = 0; ni < 8; ++ni)
#pragma unroll
            for (int k = 0; k < 4; ++k) acc[mi][ni][k] = 0.f;

    const uint32_t as_base = cvta_smem(As);
    const uint32_t vs_base = cvta_smem(Vs);
    const uint32_t a_off = ((uint32_t)((lane & 15) * ATT_SSTRIDE + ((lane >> 4) << 3))) * 2;
    const uint32_t b_off = ((uint32_t)((lane & 15) * VS2_STRIDE + ((lane >> 4) << 3))) * 2;

    const int w0 = warp * 32;
    for (int gc = 0; gc < 256; gc += 128) {
        __syncthreads();
        for (int i = tid; i < 2048; i += 128) {
            const int row = i >> 4, ch = (i & 15) * 8;
            *reinterpret_cast<uint4*>(As + row * ATT_SSTRIDE + ch) =
                *reinterpret_cast<const uint4*>(
                    aWh + (((size_t)b * HH + h) * WW + wb + row) * 256 + gc + ch);
        }
        for (int i = tid; i < 1024; i += 128) {
            const int g = i >> 3, dc = (i & 7) * 8;
            *reinterpret_cast<uint4*>(Vs + g * VS2_STRIDE + dc) =
                *reinterpret_cast<const uint4*>(
                    vth + (((size_t)b * HH + h) * WW + gc + g) * 64 + dc);
        }
        __syncthreads();

#pragma unroll
        for (int kb = 0; kb < 128; kb += 16) {
            uint32_t a[2][4];
#pragma unroll
            for (int mi = 0; mi < 2; ++mi)
                ldsm_x4(a[mi][0], a[mi][1], a[mi][2], a[mi][3],
                        as_base + a_off + (uint32_t)((w0 + mi * 16) * ATT_SSTRIDE + kb) * 2);
#pragma unroll
            for (int np = 0; np < 4; ++np) {
                uint32_t b0, b1, c0, c1;
                ldsm_x4_trans(b0, b1, c0, c1,
                              vs_base + b_off + (uint32_t)(kb * VS2_STRIDE + np * 16) * 2);
                mma_f16(acc[0][2 * np],     a[0][0], a[0][1], a[0][2], a[0][3], b0, b1);
                mma_f16(acc[0][2 * np + 1], a[0][0], a[0][1], a[0][2], a[0][3], c0, c1);
                mma_f16(acc[1][2 * np],     a[1][0], a[1][1], a[1][2], a[1][3], b0, b1);
                mma_f16(acc[1][2 * np + 1], a[1][0], a[1][1], a[1][2], a[1][3], c0, c1);
            }
        }
    }

    const float gam = *gamma;
#pragma unroll
    for (int mi = 0; mi < 2; ++mi) {
#pragma unroll
        for (int half = 0; half < 2; ++half) {
            const int w = wb + w0 + mi * 16 + g8 + half * 8;
            const float inv = 1.f / rsum[((size_t)b * HH + h) * WW + w];
#pragma unroll
            for (int ni = 0; ni < 8; ++ni) {
                const int d = ni * 8 + t2;
                const float cA = acc[mi][ni][half * 2] * inv;
                const float cB = acc[mi][ni][half * 2 + 1] * inv;
                const float2 ohf = __half22float2(*reinterpret_cast<const __half2*>(
                    ohth + (((size_t)b * HH + h) * WW + w) * 64 + d));
                const size_t x0 = ((size_t)(b * 64 + d)) * HW_ + (size_t)h * WW + w;
                const size_t x1 = ((size_t)(b * 64 + d + 1)) * HW_ + (size_t)h * WW + w;
                xout[x0] = gam * (cA + ohf.x) + x[x0];
                xout[x1] = gam * (cB + ohf.y) + x[x1];
            }
        }
    }
}

// ---------------- host ----------------
extern "C" void kernel_launch(void* const* d_in, const int* in_sizes, int n_in,
                              void* d_out, int out_size) {
    const float* cost  = (const float*)d_in[0];
    const float* lf0   = (const float*)d_in[1];
    const float* lf1   = (const float*)d_in[2];
    const float* Wa    = (const float*)d_in[3];
    const float* bn_ag = (const float*)d_in[4];
    const float* bn_ab = (const float*)d_in[5];
    const float* Wq    = (const float*)d_in[6];
    const float* bq    = (const float*)d_in[7];
    const float* Wk    = (const float*)d_in[8];
    const float* bk    = (const float*)d_in[9];
    const float* Wv    = (const float*)d_in[10];
    const float* bv    = (const float*)d_in[11];
    const float* gamma = (const float*)d_in[12];
    const float* Wb    = (const float*)d_in[13];
    const float* bn_bg = (const float*)d_in[14];
    const float* bn_bb = (const float*)d_in[15];
    float* out = (float*)d_out;

    float *conv, *xA, *xB, *rsum;
    __half *vth, *ohth, *qth, *kth, *aHh, *aWh, *wth;
    float2 *part, *stats;
    cudaGetSymbolAddress((void**)&conv, g_conv);
    cudaGetSymbolAddress((void**)&xA, g_xA);
    cudaGetSymbolAddress((void**)&xB, g_xB);
    cudaGetSymbolAddress((void**)&vth, g_vth);
    cudaGetSymbolAddress((void**)&ohth, g_ohth);
    cudaGetSymbolAddress((void**)&qth, g_qth);
    cudaGetSymbolAddress((void**)&kth, g_kth);
    cudaGetSymbolAddress((void**)&aHh, g_aHh);
    cudaGetSymbolAddress((void**)&aWh, g_aWh);
    cudaGetSymbolAddress((void**)&rsum, g_rsum);
    cudaGetSymbolAddress((void**)&wth, g_wth);
    cudaGetSymbolAddress((void**)&part, g_part);
    cudaGetSymbolAddress((void**)&stats, g_stats);

    // Idempotent, called unconditionally (no static guards — harness rule).
    cudaFuncSetAttribute(conv3x3_mma_kernel,
                         cudaFuncAttributeMaxDynamicSharedMemorySize, CONV_SMEM);
    cudaFuncSetAttribute(oH_kernel,
                         cudaFuncAttributeMaxDynamicSharedMemorySize, ATT_SMEM);
    cudaFuncSetAttribute(oW_combine_kernel,
                         cudaFuncAttributeMaxDynamicSharedMemorySize, ATT_SMEM);

    // Launch order keeps conv3x3 at capture index 3 (ncu -s5 -c1 lands there).
    conv1x1_c32_kernel<<<512, 256>>>(lf0, Wq, bq, qth);          // 0
    conv1x1_c32_kernel<<<512, 256>>>(lf1, Wk, bk, kth);          // 1
    wtrans_kernel<<<144, 256>>>(Wa, wth);                        // 2
    conv3x3_mma_kernel<<<dim3(4, 64, 4), 256, CONV_SMEM>>>(cost, wth, conv);  // 3 <- profiled

    // attention maps: exp(scores) + row sums (softmax fused; invariant across recurrence)
    cudaMemsetAsync(rsum, 0, NROWS * sizeof(float));
    eH_kernel<<<dim3(256, 4), 256>>>(qth, kth, aHh, rsum);
    eW_kernel<<<dim3(4, 128, 4), 256>>>(qth, kth, aWh, rsum);

    // BN for stage A
    bn_reduce_kernel<<<dim3(64, 8), 256>>>(conv, part);
    bn_finalize_kernel<<<1, 64>>>(part, stats);
    bn_apply_kernel<<<8192, 256>>>(conv, stats, bn_ag, bn_ab, xA);

    // Stage C: 2 recurrence iterations
    float* cur = xA;
    float* nxt = xB;
    for (int it = 0; it < 2; ++it) {
        conv1x1_d64_kernel<<<512, 256>>>(cur, Wv, bv, vth);
        oH_kernel<<<dim3(256, 4), 128, ATT_SMEM>>>(vth, aHh, rsum, ohth);
        oW_combine_kernel<<<dim3(2, 128, 4), 128, ATT_SMEM>>>(vth, aWh, ohth, cur, rsum, gamma, nxt);
        float* t = cur; cur = nxt; nxt = t;
    }

    // Stage D: conv3x3(cur, Wb) + BN -> out
    wtrans_kernel<<<144, 256>>>(Wb, wth);
    conv3x3_mma_kernel<<<dim3(4, 64, 4), 256, CONV_SMEM>>>(cur, wth, conv);
    bn_reduce_kernel<<<dim3(64, 8), 256>>>(conv, part);
    bn_finalize_kernel<<<1, 64>>>(part, stats);
    bn_apply_kernel<<<8192, 256>>>(conv, stats, bn_bg, bn_bb, out);
}